// round 4
// baseline (speedup 1.0000x reference)
#include <cuda_runtime.h>
#include <cstdint>
#include <cstddef>

// Problem constants
#define BB   32
#define NN   256
#define DM   512
#define NH   8
#define DH   64

// Scratch (allocation-free rule: __device__ globals)
__device__ float g_qh[BB*NH*NN*DH];   // [B,H,N,DH]
__device__ float g_kh[BB*NH*NN*DH];
__device__ float g_vh[BB*NH*NN*DH];
__device__ float g_att[BB*NN*DM];     // [B,N,DM] pre-output-proj
__device__ float g_pos[BB*NH*NN*NN];  // pos_scores fallback when d_out lacks room
__device__ int   g_mask_kind;         // 0=int32, 1=float32, 2=byte

// ---------------------------------------------------------------------------
// Mask dtype sniffing: reads first 8192 bytes (valid for u8/i32/f32 variants of
// an 8192-element bool mask). int32 0/1 words => kind 0; float 0/1 => kind 1;
// otherwise bytes => kind 2.
// ---------------------------------------------------------------------------
__global__ void detect_mask_kind(const unsigned int* __restrict__ m) {
    __shared__ int oki, okf;
    if (threadIdx.x == 0) { oki = 1; okf = 1; }
    __syncthreads();
    for (int idx = threadIdx.x; idx < 2048; idx += 256) {
        unsigned int w = m[idx];
        if (w > 1u) oki = 0;
        if (w != 0u && w != 0x3F800000u) okf = 0;
    }
    __syncthreads();
    if (threadIdx.x == 0) g_mask_kind = oki ? 0 : (okf ? 1 : 2);
}

// ---------------------------------------------------------------------------
// GEMM: C = A[8192,512] @ W[512,512] + bias
// BM=128, BN=64, BK=16, 256 threads, thread tile 8x4.
// mode 0: row-major C[row*512+col]   mode 1: head-split to [B,H,N,DH]
// ---------------------------------------------------------------------------
__global__ void gemm_bias(const float* __restrict__ A,
                          const float* __restrict__ W,
                          const float* __restrict__ bias,
                          float* __restrict__ C,
                          int mode) {
    __shared__ float As[16][132];   // [k][m], padded
    __shared__ float Ws[16][64];    // [k][n]
    const int K = 512, Nc = 512;
    const int bx = blockIdx.x;      // col block 0..7
    const int by = blockIdx.y;      // row block 0..63
    const int tid = threadIdx.x;
    const int tx = tid & 15, ty = tid >> 4;

    float acc[8][4];
    #pragma unroll
    for (int i = 0; i < 8; i++)
        #pragma unroll
        for (int j = 0; j < 4; j++) acc[i][j] = 0.f;

    const float* Ablk = A + (size_t)by * 128 * K;
    const float* Wblk = W + (size_t)bx * 64;

    for (int k0 = 0; k0 < K; k0 += 16) {
        // A tile 128x16, vectorized
        #pragma unroll
        for (int t = 0; t < 2; t++) {
            int idx = t * 256 + tid;          // 0..511 float4 slots
            int m = idx >> 2, kg = idx & 3;
            float4 a = *(const float4*)&Ablk[(size_t)m * K + k0 + kg * 4];
            As[kg*4+0][m] = a.x;
            As[kg*4+1][m] = a.y;
            As[kg*4+2][m] = a.z;
            As[kg*4+3][m] = a.w;
        }
        // W tile 16x64, vectorized
        {
            int kk = tid >> 4, n4 = tid & 15;
            float4 w4 = *(const float4*)&Wblk[(size_t)(k0 + kk) * Nc + n4 * 4];
            *(float4*)&Ws[kk][n4 * 4] = w4;
        }
        __syncthreads();
        #pragma unroll
        for (int kk = 0; kk < 16; kk++) {
            float ra[8], rb[4];
            *(float4*)(ra)     = *(const float4*)&As[kk][ty * 8];
            *(float4*)(ra + 4) = *(const float4*)&As[kk][ty * 8 + 4];
            *(float4*)(rb)     = *(const float4*)&Ws[kk][tx * 4];
            #pragma unroll
            for (int i = 0; i < 8; i++)
                #pragma unroll
                for (int j = 0; j < 4; j++)
                    acc[i][j] = fmaf(ra[i], rb[j], acc[i][j]);
        }
        __syncthreads();
    }

    const int colBase = bx * 64 + tx * 4;
    float4 bb = *(const float4*)&bias[colBase];
    #pragma unroll
    for (int i = 0; i < 8; i++) {
        int row = by * 128 + ty * 8 + i;
        float4 v = make_float4(acc[i][0] + bb.x, acc[i][1] + bb.y,
                               acc[i][2] + bb.z, acc[i][3] + bb.w);
        if (mode == 1) {
            int b = row >> 8, n = row & 255;
            // col/64 == bx here, d = tx*4..+3
            *(float4*)&C[((((size_t)b * NH + bx) * NN + n) * DH) + tx * 4] = v;
        } else {
            *(float4*)&C[(size_t)row * Nc + colBase] = v;
        }
    }
}

// ---------------------------------------------------------------------------
// Geometric positional bias: ps[b,i,j] = relu(emb(box) . Wbox + bbox)
// Writes all 8 head copies to pos_out [B,H,N,N]. Block = (i, b), thread = j.
// ---------------------------------------------------------------------------
__global__ void pos_kernel(const float* __restrict__ box,
                           const float* __restrict__ Wbox,
                           const float* __restrict__ bbox,
                           float* __restrict__ pos_out) {
    __shared__ float scx[NN], scy[NN], slw[NN], slh[NN];
    __shared__ float wb[65];
    const int b = blockIdx.y, i = blockIdx.x;
    const int j = threadIdx.x;

    {
        const float* bj = box + ((size_t)b * NN + j) * 4;
        float x0 = bj[0], y0 = bj[1], x1 = bj[2], y1 = bj[3];
        scx[j] = 0.5f * (x0 + x1);
        scy[j] = 0.5f * (y0 + y1);
        slw[j] = __logf(x1 - x0 + 1.0f);
        slh[j] = __logf(y1 - y0 + 1.0f);
    }
    if (j < 64) wb[j] = Wbox[j];
    if (j == 0) wb[64] = bbox[0];
    __syncthreads();

    const float* bi = box + ((size_t)b * NN + i) * 4;
    float xi0 = bi[0], yi0 = bi[1], xi1 = bi[2], yi1 = bi[3];
    float cxi = 0.5f * (xi0 + xi1), cyi = 0.5f * (yi0 + yi1);
    float wi = xi1 - xi0 + 1.0f, hi = yi1 - yi0 + 1.0f;
    float invw = 1.0f / wi, invh = 1.0f / hi;
    float lwi = __logf(wi), lhi = __logf(hi);

    float p0 = __logf(fmaxf(fabsf((cxi - scx[j]) * invw), 1e-3f));
    float p1 = __logf(fmaxf(fabsf((cyi - scy[j]) * invh), 1e-3f));
    float p2 = lwi - slw[j];
    float p3 = lhi - slh[j];

    const float dm[8] = {1.0f, 0.42169651f, 0.17782794f, 0.074989423f,
                         0.031622777f, 0.013335214f, 0.0056234132f, 0.0023713737f};
    float pc[4] = {100.f * p0, 100.f * p1, 100.f * p2, 100.f * p3};

    float s = wb[64];
    #pragma unroll
    for (int c = 0; c < 4; c++) {
        #pragma unroll
        for (int f = 0; f < 8; f++) {
            float m = pc[c] * dm[f];
            float sn, cs;
            __sincosf(m, &sn, &cs);
            s = fmaf(sn, wb[c * 8 + f], s);
            s = fmaf(cs, wb[32 + c * 8 + f], s);
        }
    }
    float ps = fmaxf(s, 0.f);

    size_t base = (size_t)b * NH * NN * NN + (size_t)i * NN + j;
    #pragma unroll
    for (int hh = 0; hh < NH; hh++)
        pos_out[base + (size_t)hh * NN * NN] = ps;
}

// ---------------------------------------------------------------------------
// Fused attention per (b, h, 32-query tile):
//   S = scale*Q Kt + pos; mask; softmax; O = P V  -> g_att [B,N,DM]
// 256 threads. Dynamic smem: Qs[32*64] | KV[64*68] | S[32*260] | mrow[256]
// ---------------------------------------------------------------------------
__global__ void attn_kernel(const void* __restrict__ maskp,
                            const float* __restrict__ pos) {
    extern __shared__ float sm[];
    float* Qs = sm;                         // [32][64]
    float* KV = sm + 2048;                  // [64][68]
    float* S  = sm + 2048 + 4352;           // [32][260]
    unsigned char* mrow = (unsigned char*)(S + 32 * 260);

    const int blk = blockIdx.x;
    const int qt = blk & 7;
    const int h  = (blk >> 3) & 7;
    const int b  = blk >> 6;
    const int tid = threadIdx.x;
    const int tx = tid & 15, ty = tid >> 4;
    const int q0 = qt * 32;
    const int kind = g_mask_kind;

    {
        int idx = b * NN + tid;
        bool mv;
        if (kind == 0)      mv = ((const int*)maskp)[idx] != 0;
        else if (kind == 1) mv = ((const float*)maskp)[idx] != 0.0f;
        else                mv = ((const unsigned char*)maskp)[idx] != 0;
        mrow[tid] = mv ? 1 : 0;
    }

    const float* Qg = g_qh + (((size_t)b * NH + h) * NN + q0) * DH;
    const float* Kg = g_kh + (((size_t)b * NH + h) * NN) * DH;
    const float* Vg = g_vh + (((size_t)b * NH + h) * NN) * DH;

    #pragma unroll
    for (int t = 0; t < 8; t++) {
        int idx = t * 256 + tid;
        Qs[idx] = Qg[idx];                  // [r][d] natural layout, 32x64
    }

    const float* prow = pos + (size_t)b * (NH * NN * NN) + (size_t)q0 * NN;

    // ---- S = scale * Q K^T + pos, masked ----
    for (int kb = 0; kb < 4; kb++) {
        __syncthreads();
        #pragma unroll
        for (int t = 0; t < 16; t++) {       // 64 keys x 64 dims = 4096 elems
            int idx = t * 256 + tid;
            int key = idx >> 6, d = idx & 63;
            KV[d * 68 + key] = Kg[kb * 4096 + idx];   // transposed [d][key]
        }
        __syncthreads();
        float acc[2][4] = {{0.f,0.f,0.f,0.f},{0.f,0.f,0.f,0.f}};
        #pragma unroll
        for (int d = 0; d < 64; d++) {
            float qa = Qs[(ty * 2 + 0) * 64 + d];
            float qb = Qs[(ty * 2 + 1) * 64 + d];
            float4 kv = *(const float4*)&KV[d * 68 + tx * 4];
            acc[0][0] = fmaf(qa, kv.x, acc[0][0]);
            acc[0][1] = fmaf(qa, kv.y, acc[0][1]);
            acc[0][2] = fmaf(qa, kv.z, acc[0][2]);
            acc[0][3] = fmaf(qa, kv.w, acc[0][3]);
            acc[1][0] = fmaf(qb, kv.x, acc[1][0]);
            acc[1][1] = fmaf(qb, kv.y, acc[1][1]);
            acc[1][2] = fmaf(qb, kv.z, acc[1][2]);
            acc[1][3] = fmaf(qb, kv.w, acc[1][3]);
        }
        #pragma unroll
        for (int i = 0; i < 2; i++) {
            int r = ty * 2 + i;
            #pragma unroll
            for (int jj = 0; jj < 4; jj++) {
                int j = kb * 64 + tx * 4 + jj;
                float val = mrow[j] ? -1e9f
                          : fmaf(acc[i][jj], 0.125f, prow[r * NN + j]);
                S[r * 260 + j] = val;
            }
        }
    }
    __syncthreads();

    // ---- softmax: 8 lanes per row ----
    {
        int row = tid >> 3, sub = tid & 7;
        float* Sr = S + row * 260;
        float mx = -3.4e38f;
        #pragma unroll
        for (int t = 0; t < 32; t++) mx = fmaxf(mx, Sr[sub + t * 8]);
        #pragma unroll
        for (int o = 4; o > 0; o >>= 1)
            mx = fmaxf(mx, __shfl_xor_sync(0xffffffffu, mx, o));
        float ssum = 0.f;
        #pragma unroll
        for (int t = 0; t < 32; t++) {
            float e = __expf(Sr[sub + t * 8] - mx);
            Sr[sub + t * 8] = e;
            ssum += e;
        }
        #pragma unroll
        for (int o = 4; o > 0; o >>= 1)
            ssum += __shfl_xor_sync(0xffffffffu, ssum, o);
        float inv = 1.0f / ssum;
        #pragma unroll
        for (int t = 0; t < 32; t++) Sr[sub + t * 8] *= inv;
    }

    // ---- O = P V ----
    float oacc[2][4] = {{0.f,0.f,0.f,0.f},{0.f,0.f,0.f,0.f}};
    for (int kb = 0; kb < 4; kb++) {
        __syncthreads();
        #pragma unroll
        for (int t = 0; t < 16; t++) {       // 64 keys x 64 dims = 4096 elems
            int idx = t * 256 + tid;
            KV[(idx >> 6) * 68 + (idx & 63)] = Vg[kb * 4096 + idx]; // [key][d]
        }
        __syncthreads();
        #pragma unroll
        for (int k = 0; k < 64; k++) {
            float p0 = S[(ty * 2 + 0) * 260 + kb * 64 + k];
            float p1 = S[(ty * 2 + 1) * 260 + kb * 64 + k];
            float4 vv = *(const float4*)&KV[k * 68 + tx * 4];
            oacc[0][0] = fmaf(p0, vv.x, oacc[0][0]);
            oacc[0][1] = fmaf(p0, vv.y, oacc[0][1]);
            oacc[0][2] = fmaf(p0, vv.z, oacc[0][2]);
            oacc[0][3] = fmaf(p0, vv.w, oacc[0][3]);
            oacc[1][0] = fmaf(p1, vv.x, oacc[1][0]);
            oacc[1][1] = fmaf(p1, vv.y, oacc[1][1]);
            oacc[1][2] = fmaf(p1, vv.z, oacc[1][2]);
            oacc[1][3] = fmaf(p1, vv.w, oacc[1][3]);
        }
    }
    #pragma unroll
    for (int i = 0; i < 2; i++) {
        int r = q0 + ty * 2 + i;
        float4 o4 = make_float4(oacc[i][0], oacc[i][1], oacc[i][2], oacc[i][3]);
        *(float4*)&g_att[(((size_t)b * NN + r) * DM) + h * DH + tx * 4] = o4;
    }
}

// ---------------------------------------------------------------------------
extern "C" void kernel_launch(void* const* d_in, const int* in_sizes, int n_in,
                              void* d_out, int out_size) {
    // ---- Input mapping: detect ordering from in_sizes ----
    // dict order:  v(4M) k(4M) q(4M) box(32768) mask(8192) [fg(1)] Wq bq Wk bk Wv bv Wm bm Wbox bbox
    // ASCII order: Wbox(64) Wk Wm Wq Wv bbox(1) bk bm bq bv box(32768) [fg(1)] k mask q v
    const float *v, *k, *q, *box, *Wq, *bq, *Wk, *bk, *Wv, *bv, *Wm, *bm, *Wbox, *bbox;
    const void* mask;

    if (in_sizes[0] == BB * NN * DM) {
        // dict / signature order
        v    = (const float*)d_in[0];
        k    = (const float*)d_in[1];
        q    = (const float*)d_in[2];
        box  = (const float*)d_in[3];
        mask = d_in[4];
        int wb = 5;
        for (int i = 5; i < n_in; i++) {
            if (in_sizes[i] == DM * DM) { wb = i; break; }
        }
        Wq   = (const float*)d_in[wb + 0];
        bq   = (const float*)d_in[wb + 1];
        Wk   = (const float*)d_in[wb + 2];
        bk   = (const float*)d_in[wb + 3];
        Wv   = (const float*)d_in[wb + 4];
        bv   = (const float*)d_in[wb + 5];
        Wm   = (const float*)d_in[wb + 6];
        bm   = (const float*)d_in[wb + 7];
        Wbox = (const float*)d_in[wb + 8];
        bbox = (const float*)d_in[wb + 9];
    } else {
        // ASCII-sorted names
        Wbox = (const float*)d_in[0];
        Wk   = (const float*)d_in[1];
        Wm   = (const float*)d_in[2];
        Wq   = (const float*)d_in[3];
        Wv   = (const float*)d_in[4];
        bbox = (const float*)d_in[5];
        bk   = (const float*)d_in[6];
        bm   = (const float*)d_in[7];
        bq   = (const float*)d_in[8];
        bv   = (const float*)d_in[9];
        box  = (const float*)d_in[10];
        int idx = 11;
        if (idx < n_in && in_sizes[idx] == 1) idx++;   // fg scalar, if present
        k    = (const float*)d_in[idx + 0];
        mask = d_in[idx + 1];
        q    = (const float*)d_in[idx + 2];
        v    = (const float*)d_in[idx + 3];
    }

    // ---- Output routing: branch on out_size ----
    const size_t ATTED_ELEMS = (size_t)BB * NN * DM;            // 4,194,304
    const size_t POS_ELEMS   = (size_t)BB * NH * NN * NN;       // 16,777,216
    float* out = (float*)d_out;

    float *posA, *kA, *vA, *qA, *attA;
    cudaGetSymbolAddress((void**)&qA,   g_qh);
    cudaGetSymbolAddress((void**)&kA,   g_kh);
    cudaGetSymbolAddress((void**)&vA,   g_vh);
    cudaGetSymbolAddress((void**)&attA, g_att);
    cudaGetSymbolAddress((void**)&posA, g_pos);

    float* atted;
    float* pos_out;
    if ((size_t)out_size >= ATTED_ELEMS + POS_ELEMS) {
        atted   = out;                    // tuple order: atted, then pos_scores
        pos_out = out + ATTED_ELEMS;
    } else if ((size_t)out_size == POS_ELEMS) {
        pos_out = out;                    // pos_scores only
        atted   = attA;                   // dump atted into scratch (unused)
    } else {
        atted   = out;                    // atted only — keep pos in scratch,
        pos_out = posA;                   // never write past d_out
    }

    detect_mask_kind<<<1, 256>>>((const unsigned int*)mask);

    dim3 gg(8, 64);
    gemm_bias<<<gg, 256>>>(q, Wq, bq, qA, 1);
    gemm_bias<<<gg, 256>>>(k, Wk, bk, kA, 1);
    gemm_bias<<<gg, 256>>>(v, Wv, bv, vA, 1);

    pos_kernel<<<dim3(NN, BB), 256>>>(box, Wbox, bbox, pos_out);

    static_assert(2048 + 4352 + 32 * 260 == 14720, "smem layout");
    int smem_bytes = (2048 + 4352 + 32 * 260) * 4 + 256;
    cudaFuncSetAttribute(attn_kernel,
                         cudaFuncAttributeMaxDynamicSharedMemorySize, 65536);
    attn_kernel<<<BB * NH * 8, 256, smem_bytes>>>(mask, pos_out);

    gemm_bias<<<gg, 256>>>(attA, Wm, bm, atted, 0);
}

// round 5
// speedup vs baseline: 1.2626x; 1.2626x over previous
#include <cuda_runtime.h>
#include <cstdint>
#include <cstddef>

// Problem constants
#define BB   32
#define NN   256
#define DM   512
#define NH   8
#define DH   64

typedef unsigned long long ull;

// Scratch (allocation-free rule: __device__ globals)
__device__ float g_qh[BB*NH*NN*DH];   // [B,H,N,DH]
__device__ float g_kh[BB*NH*NN*DH];
__device__ float g_vh[BB*NH*NN*DH];
__device__ float g_att[BB*NN*DM];     // [B,N,DM] pre-output-proj
__device__ float g_pos[BB*NH*NN*NN];  // pos_scores fallback when d_out lacks room
__device__ int   g_mask_kind;         // 0=int32, 1=float32, 2=byte

// ---- packed f32x2 helpers (FFMA2 is only reachable via PTX) ----
__device__ __forceinline__ ull fma2(ull a, ull b, ull c) {
    ull d;
    asm("fma.rn.f32x2 %0, %1, %2, %3;" : "=l"(d) : "l"(a), "l"(b), "l"(c));
    return d;
}
__device__ __forceinline__ ull pack2(float x, float y) {
    ull r; asm("mov.b64 %0, {%1, %2};" : "=l"(r) : "f"(x), "f"(y)); return r;
}
__device__ __forceinline__ float2 unpack2(ull v) {
    float x, y; asm("mov.b64 {%0, %1}, %2;" : "=f"(x), "=f"(y) : "l"(v));
    return make_float2(x, y);
}

// ---------------------------------------------------------------------------
// Mask dtype sniffing (bool may arrive as u8/i32/f32).
// ---------------------------------------------------------------------------
__global__ void detect_mask_kind(const unsigned int* __restrict__ m) {
    __shared__ int oki, okf;
    if (threadIdx.x == 0) { oki = 1; okf = 1; }
    __syncthreads();
    for (int idx = threadIdx.x; idx < 2048; idx += 256) {
        unsigned int w = m[idx];
        if (w > 1u) oki = 0;
        if (w != 0u && w != 0x3F800000u) okf = 0;
    }
    __syncthreads();
    if (threadIdx.x == 0) g_mask_kind = oki ? 0 : (okf ? 1 : 2);
}

// ---------------------------------------------------------------------------
// GEMM v2: C = A[8192,512] @ W[512,512] + bias
// BM=128, BN=128, BK=16, 256 threads, 8x8 thread tile via fma.rn.f32x2.
// Register-prefetch double buffering. Split-N col groups (tx*4, 64+tx*4).
// mode 0: row-major C[row*512+col]   mode 1: head-split to [B,H,N,DH]
// ---------------------------------------------------------------------------
__global__ void __launch_bounds__(256, 2)
gemm_bias(const float* __restrict__ A,
          const float* __restrict__ W,
          const float* __restrict__ bias,
          float* __restrict__ C,
          int mode) {
    __shared__ float As[16][128];   // [k][m]
    __shared__ float Ws[16][128];   // [k][n]
    const int K = 512;
    const int bx = blockIdx.x;      // col block 0..3 (128 cols)
    const int by = blockIdx.y;      // row block 0..63
    const int tid = threadIdx.x;
    const int tx = tid & 15, ty = tid >> 4;

    ull acc[8][4];                  // 8 rows x 8 cols (4 packed pairs)
    #pragma unroll
    for (int i = 0; i < 8; i++)
        #pragma unroll
        for (int j = 0; j < 4; j++) acc[i][j] = 0ULL;

    const float* Ablk = A + (size_t)by * 128 * K;
    const float* Wblk = W + (size_t)bx * 128;

    const int aM = tid >> 2, aKg = tid & 3;          // A slot for t=0 (idx=tid)
    const int aM1 = (256 + tid) >> 2, aKg1 = (256 + tid) & 3;
    const int wK = tid >> 5, wN4 = tid & 31;
    const int wK1 = (256 + tid) >> 5, wN41 = (256 + tid) & 31;

    float4 pa0, pa1, pw0, pw1;
    pa0 = *(const float4*)&Ablk[(size_t)aM  * K + aKg  * 4];
    pa1 = *(const float4*)&Ablk[(size_t)aM1 * K + aKg1 * 4];
    pw0 = *(const float4*)&Wblk[(size_t)wK  * DM + wN4  * 4];
    pw1 = *(const float4*)&Wblk[(size_t)wK1 * DM + wN41 * 4];

    for (int k0 = 0; k0 < K; k0 += 16) {
        // commit prefetched tile to smem
        As[aKg*4+0][aM] = pa0.x;  As[aKg*4+1][aM] = pa0.y;
        As[aKg*4+2][aM] = pa0.z;  As[aKg*4+3][aM] = pa0.w;
        As[aKg1*4+0][aM1] = pa1.x; As[aKg1*4+1][aM1] = pa1.y;
        As[aKg1*4+2][aM1] = pa1.z; As[aKg1*4+3][aM1] = pa1.w;
        *(float4*)&Ws[wK][wN4*4]   = pw0;
        *(float4*)&Ws[wK1][wN41*4] = pw1;
        __syncthreads();

        if (k0 + 16 < K) {           // issue next-tile LDGs early
            int kn = k0 + 16;
            pa0 = *(const float4*)&Ablk[(size_t)aM  * K + kn + aKg  * 4];
            pa1 = *(const float4*)&Ablk[(size_t)aM1 * K + kn + aKg1 * 4];
            pw0 = *(const float4*)&Wblk[(size_t)(kn + wK)  * DM + wN4  * 4];
            pw1 = *(const float4*)&Wblk[(size_t)(kn + wK1) * DM + wN41 * 4];
        }

        #pragma unroll
        for (int kk = 0; kk < 16; kk++) {
            float4 a0 = *(const float4*)&As[kk][ty * 4];
            float4 a1 = *(const float4*)&As[kk][64 + ty * 4];
            float4 b0 = *(const float4*)&Ws[kk][tx * 4];
            float4 b1 = *(const float4*)&Ws[kk][64 + tx * 4];
            ull rb[4] = { pack2(b0.x, b0.y), pack2(b0.z, b0.w),
                          pack2(b1.x, b1.y), pack2(b1.z, b1.w) };
            float ra[8] = {a0.x, a0.y, a0.z, a0.w, a1.x, a1.y, a1.z, a1.w};
            #pragma unroll
            for (int r = 0; r < 8; r++) {
                ull ar = pack2(ra[r], ra[r]);
                #pragma unroll
                for (int j = 0; j < 4; j++)
                    acc[r][j] = fma2(ar, rb[j], acc[r][j]);
            }
        }
        __syncthreads();
    }

    float4 bb[2];
    bb[0] = *(const float4*)&bias[bx * 128 + tx * 4];
    bb[1] = *(const float4*)&bias[bx * 128 + 64 + tx * 4];

    #pragma unroll
    for (int half = 0; half < 2; half++) {
        #pragma unroll
        for (int i = 0; i < 4; i++) {
            int r = half * 4 + i;
            int row = by * 128 + half * 64 + ty * 4 + i;
            #pragma unroll
            for (int cg = 0; cg < 2; cg++) {
                float2 u0 = unpack2(acc[r][cg * 2 + 0]);
                float2 u1 = unpack2(acc[r][cg * 2 + 1]);
                float4 bbv = bb[cg];
                float4 val = make_float4(u0.x + bbv.x, u0.y + bbv.y,
                                         u1.x + bbv.z, u1.y + bbv.w);
                if (mode == 1) {
                    int b = row >> 8, n = row & 255;
                    int h = bx * 2 + cg;                // col/64
                    *(float4*)&C[((((size_t)b * NH + h) * NN + n) * DH) + tx * 4] = val;
                } else {
                    *(float4*)&C[(size_t)row * DM + bx * 128 + cg * 64 + tx * 4] = val;
                }
            }
        }
    }
}

// ---------------------------------------------------------------------------
// Geometric positional bias: ps[b,i,j] = relu(emb(box) . Wbox + bbox)
// Writes all 8 head copies to pos_out [B,H,N,N]. Block = (i, b), thread = j.
// ---------------------------------------------------------------------------
__global__ void pos_kernel(const float* __restrict__ box,
                           const float* __restrict__ Wbox,
                           const float* __restrict__ bbox,
                           float* __restrict__ pos_out) {
    __shared__ float scx[NN], scy[NN], slw[NN], slh[NN];
    __shared__ float wb[65];
    const int b = blockIdx.y, i = blockIdx.x;
    const int j = threadIdx.x;

    {
        const float* bj = box + ((size_t)b * NN + j) * 4;
        float x0 = bj[0], y0 = bj[1], x1 = bj[2], y1 = bj[3];
        scx[j] = 0.5f * (x0 + x1);
        scy[j] = 0.5f * (y0 + y1);
        slw[j] = __logf(x1 - x0 + 1.0f);
        slh[j] = __logf(y1 - y0 + 1.0f);
    }
    if (j < 64) wb[j] = Wbox[j];
    if (j == 0) wb[64] = bbox[0];
    __syncthreads();

    const float* bi = box + ((size_t)b * NN + i) * 4;
    float xi0 = bi[0], yi0 = bi[1], xi1 = bi[2], yi1 = bi[3];
    float cxi = 0.5f * (xi0 + xi1), cyi = 0.5f * (yi0 + yi1);
    float wi = xi1 - xi0 + 1.0f, hi = yi1 - yi0 + 1.0f;
    float invw = 1.0f / wi, invh = 1.0f / hi;
    float lwi = __logf(wi), lhi = __logf(hi);

    float p0 = __logf(fmaxf(fabsf((cxi - scx[j]) * invw), 1e-3f));
    float p1 = __logf(fmaxf(fabsf((cyi - scy[j]) * invh), 1e-3f));
    float p2 = lwi - slw[j];
    float p3 = lhi - slh[j];

    const float dm[8] = {1.0f, 0.42169651f, 0.17782794f, 0.074989423f,
                         0.031622777f, 0.013335214f, 0.0056234132f, 0.0023713737f};
    float pc[4] = {100.f * p0, 100.f * p1, 100.f * p2, 100.f * p3};

    float s = wb[64];
    #pragma unroll
    for (int c = 0; c < 4; c++) {
        #pragma unroll
        for (int f = 0; f < 8; f++) {
            float m = pc[c] * dm[f];
            float sn, cs;
            __sincosf(m, &sn, &cs);
            s = fmaf(sn, wb[c * 8 + f], s);
            s = fmaf(cs, wb[32 + c * 8 + f], s);
        }
    }
    float ps = fmaxf(s, 0.f);

    size_t base = (size_t)b * NH * NN * NN + (size_t)i * NN + j;
    #pragma unroll
    for (int hh = 0; hh < NH; hh++)
        pos_out[base + (size_t)hh * NN * NN] = ps;
}

// ---------------------------------------------------------------------------
// Fused attention per (b, h, 32-query tile), f32x2 inner loops:
//   S = scale*Q Kt + pos; mask; softmax; O = P V  -> g_att [B,N,DM]
// 256 threads. Dynamic smem: Qs[32*64] | KV[64*68] | S[32*260] | mrow[256]
// ---------------------------------------------------------------------------
__global__ void attn_kernel(const void* __restrict__ maskp,
                            const float* __restrict__ pos) {
    extern __shared__ float sm[];
    float* Qs = sm;                         // [32][64]
    float* KV = sm + 2048;                  // [64][68]
    float* S  = sm + 2048 + 4352;           // [32][260]
    unsigned char* mrow = (unsigned char*)(S + 32 * 260);

    const int blk = blockIdx.x;
    const int qt = blk & 7;
    const int h  = (blk >> 3) & 7;
    const int b  = blk >> 6;
    const int tid = threadIdx.x;
    const int tx = tid & 15, ty = tid >> 4;
    const int q0 = qt * 32;
    const int kind = g_mask_kind;

    {
        int idx = b * NN + tid;
        bool mv;
        if (kind == 0)      mv = ((const int*)maskp)[idx] != 0;
        else if (kind == 1) mv = ((const float*)maskp)[idx] != 0.0f;
        else                mv = ((const unsigned char*)maskp)[idx] != 0;
        mrow[tid] = mv ? 1 : 0;
    }

    const float* Qg = g_qh + (((size_t)b * NH + h) * NN + q0) * DH;
    const float* Kg = g_kh + (((size_t)b * NH + h) * NN) * DH;
    const float* Vg = g_vh + (((size_t)b * NH + h) * NN) * DH;

    #pragma unroll
    for (int t = 0; t < 8; t++) {
        int idx = t * 256 + tid;
        Qs[idx] = Qg[idx];                  // [r][d] natural layout, 32x64
    }

    const float* prow = pos + (size_t)b * (NH * NN * NN) + (size_t)q0 * NN;

    // ---- S = scale * Q K^T + pos, masked ----
    for (int kb = 0; kb < 4; kb++) {
        __syncthreads();
        #pragma unroll
        for (int t = 0; t < 16; t++) {       // 64 keys x 64 dims = 4096 elems
            int idx = t * 256 + tid;
            int key = idx >> 6, d = idx & 63;
            KV[d * 68 + key] = Kg[kb * 4096 + idx];   // transposed [d][key]
        }
        __syncthreads();
        ull pacc[2][2] = {{0ULL, 0ULL}, {0ULL, 0ULL}};
        #pragma unroll
        for (int d = 0; d < 64; d++) {
            float qa = Qs[(ty * 2 + 0) * 64 + d];
            float qb = Qs[(ty * 2 + 1) * 64 + d];
            ull qa2 = pack2(qa, qa), qb2 = pack2(qb, qb);
            float4 kv = *(const float4*)&KV[d * 68 + tx * 4];
            ull k01 = pack2(kv.x, kv.y), k23 = pack2(kv.z, kv.w);
            pacc[0][0] = fma2(qa2, k01, pacc[0][0]);
            pacc[0][1] = fma2(qa2, k23, pacc[0][1]);
            pacc[1][0] = fma2(qb2, k01, pacc[1][0]);
            pacc[1][1] = fma2(qb2, k23, pacc[1][1]);
        }
        #pragma unroll
        for (int i = 0; i < 2; i++) {
            int r = ty * 2 + i;
            float2 u0 = unpack2(pacc[i][0]);
            float2 u1 = unpack2(pacc[i][1]);
            float av[4] = {u0.x, u0.y, u1.x, u1.y};
            #pragma unroll
            for (int jj = 0; jj < 4; jj++) {
                int j = kb * 64 + tx * 4 + jj;
                float val = mrow[j] ? -1e9f
                          : fmaf(av[jj], 0.125f, prow[r * NN + j]);
                S[r * 260 + j] = val;
            }
        }
    }
    __syncthreads();

    // ---- softmax: 8 lanes per row ----
    {
        int row = tid >> 3, sub = tid & 7;
        float* Sr = S + row * 260;
        float mx = -3.4e38f;
        #pragma unroll
        for (int t = 0; t < 32; t++) mx = fmaxf(mx, Sr[sub + t * 8]);
        #pragma unroll
        for (int o = 4; o > 0; o >>= 1)
            mx = fmaxf(mx, __shfl_xor_sync(0xffffffffu, mx, o));
        float ssum = 0.f;
        #pragma unroll
        for (int t = 0; t < 32; t++) {
            float e = __expf(Sr[sub + t * 8] - mx);
            Sr[sub + t * 8] = e;
            ssum += e;
        }
        #pragma unroll
        for (int o = 4; o > 0; o >>= 1)
            ssum += __shfl_xor_sync(0xffffffffu, ssum, o);
        float inv = 1.0f / ssum;
        #pragma unroll
        for (int t = 0; t < 32; t++) Sr[sub + t * 8] *= inv;
    }

    // ---- O = P V ----
    ull oacc[2][2] = {{0ULL, 0ULL}, {0ULL, 0ULL}};
    for (int kb = 0; kb < 4; kb++) {
        __syncthreads();
        #pragma unroll
        for (int t = 0; t < 16; t++) {       // 64 keys x 64 dims = 4096 elems
            int idx = t * 256 + tid;
            KV[(idx >> 6) * 68 + (idx & 63)] = Vg[kb * 4096 + idx]; // [key][d]
        }
        __syncthreads();
        #pragma unroll
        for (int k = 0; k < 64; k++) {
            float p0 = S[(ty * 2 + 0) * 260 + kb * 64 + k];
            float p1 = S[(ty * 2 + 1) * 260 + kb * 64 + k];
            ull p02 = pack2(p0, p0), p12 = pack2(p1, p1);
            float4 vv = *(const float4*)&KV[k * 68 + tx * 4];
            ull v01 = pack2(vv.x, vv.y), v23 = pack2(vv.z, vv.w);
            oacc[0][0] = fma2(p02, v01, oacc[0][0]);
            oacc[0][1] = fma2(p02, v23, oacc[0][1]);
            oacc[1][0] = fma2(p12, v01, oacc[1][0]);
            oacc[1][1] = fma2(p12, v23, oacc[1][1]);
        }
    }
    #pragma unroll
    for (int i = 0; i < 2; i++) {
        int r = q0 + ty * 2 + i;
        float2 u0 = unpack2(oacc[i][0]);
        float2 u1 = unpack2(oacc[i][1]);
        float4 o4 = make_float4(u0.x, u0.y, u1.x, u1.y);
        *(float4*)&g_att[(((size_t)b * NN + r) * DM) + h * DH + tx * 4] = o4;
    }
}

// ---------------------------------------------------------------------------
extern "C" void kernel_launch(void* const* d_in, const int* in_sizes, int n_in,
                              void* d_out, int out_size) {
    // ---- Input mapping: detect ordering from in_sizes ----
    const float *v, *k, *q, *box, *Wq, *bq, *Wk, *bk, *Wv, *bv, *Wm, *bm, *Wbox, *bbox;
    const void* mask;

    if (in_sizes[0] == BB * NN * DM) {
        // dict / signature order
        v    = (const float*)d_in[0];
        k    = (const float*)d_in[1];
        q    = (const float*)d_in[2];
        box  = (const float*)d_in[3];
        mask = d_in[4];
        int wb = 5;
        for (int i = 5; i < n_in; i++) {
            if (in_sizes[i] == DM * DM) { wb = i; break; }
        }
        Wq   = (const float*)d_in[wb + 0];
        bq   = (const float*)d_in[wb + 1];
        Wk   = (const float*)d_in[wb + 2];
        bk   = (const float*)d_in[wb + 3];
        Wv   = (const float*)d_in[wb + 4];
        bv   = (const float*)d_in[wb + 5];
        Wm   = (const float*)d_in[wb + 6];
        bm   = (const float*)d_in[wb + 7];
        Wbox = (const float*)d_in[wb + 8];
        bbox = (const float*)d_in[wb + 9];
    } else {
        // ASCII-sorted names
        Wbox = (const float*)d_in[0];
        Wk   = (const float*)d_in[1];
        Wm   = (const float*)d_in[2];
        Wq   = (const float*)d_in[3];
        Wv   = (const float*)d_in[4];
        bbox = (const float*)d_in[5];
        bk   = (const float*)d_in[6];
        bm   = (const float*)d_in[7];
        bq   = (const float*)d_in[8];
        bv   = (const float*)d_in[9];
        box  = (const float*)d_in[10];
        int idx = 11;
        if (idx < n_in && in_sizes[idx] == 1) idx++;   // fg scalar, if present
        k    = (const float*)d_in[idx + 0];
        mask = d_in[idx + 1];
        q    = (const float*)d_in[idx + 2];
        v    = (const float*)d_in[idx + 3];
    }

    // ---- Output routing: branch on out_size ----
    const size_t ATTED_ELEMS = (size_t)BB * NN * DM;            // 4,194,304
    const size_t POS_ELEMS   = (size_t)BB * NH * NN * NN;       // 16,777,216
    float* out = (float*)d_out;

    float *posA, *kA, *vA, *qA, *attA;
    cudaGetSymbolAddress((void**)&qA,   g_qh);
    cudaGetSymbolAddress((void**)&kA,   g_kh);
    cudaGetSymbolAddress((void**)&vA,   g_vh);
    cudaGetSymbolAddress((void**)&attA, g_att);
    cudaGetSymbolAddress((void**)&posA, g_pos);

    float* atted;
    float* pos_out;
    if ((size_t)out_size >= ATTED_ELEMS + POS_ELEMS) {
        atted   = out;                    // tuple order: atted, then pos_scores
        pos_out = out + ATTED_ELEMS;
    } else if ((size_t)out_size == POS_ELEMS) {
        pos_out = out;                    // pos_scores only
        atted   = attA;
    } else {
        atted   = out;                    // atted only — keep pos in scratch
        pos_out = posA;
    }

    detect_mask_kind<<<1, 256>>>((const unsigned int*)mask);

    dim3 gg(4, 64);
    gemm_bias<<<gg, 256>>>(q, Wq, bq, qA, 1);
    gemm_bias<<<gg, 256>>>(k, Wk, bk, kA, 1);
    gemm_bias<<<gg, 256>>>(v, Wv, bv, vA, 1);

    pos_kernel<<<dim3(NN, BB), 256>>>(box, Wbox, bbox, pos_out);

    int smem_bytes = (2048 + 4352 + 32 * 260) * 4 + 256;
    cudaFuncSetAttribute(attn_kernel,
                         cudaFuncAttributeMaxDynamicSharedMemorySize, 65536);
    attn_kernel<<<BB * NH * 8, 256, smem_bytes>>>(mask, pos_out);

    gemm_bias<<<gg, 256>>>(attA, Wm, bm, atted, 0);
}

// round 8
// speedup vs baseline: 1.5718x; 1.2449x over previous
#include <cuda_runtime.h>
#include <cuda_bf16.h>
#include <cstdint>
#include <cstddef>

// Problem constants
#define BB   32
#define NN   256
#define DM   512
#define NH   8
#define DH   64

typedef unsigned long long ull;
typedef __nv_bfloat16 bf16;

// Scratch (allocation-free rule: __device__ globals)
__device__ float g_qh[BB*NH*NN*DH];   // [B,H,N,DH]
__device__ float g_kh[BB*NH*NN*DH];
__device__ float g_vh[BB*NH*NN*DH];
__device__ float g_att[BB*NN*DM];     // [B,N,DM] pre-output-proj
__device__ float g_pos[BB*NH*NN*NN];  // pos_scores fallback when d_out lacks room
__device__ bf16  g_ah[BB*NN*DM];      // A hi split (reused per GEMM)
__device__ bf16  g_al[BB*NN*DM];      // A lo split
__device__ bf16  g_wh[DM*DM];         // W^T hi split [n][k]
__device__ bf16  g_wl[DM*DM];         // W^T lo split
__device__ int   g_mask_kind;         // 0=int32, 1=float32, 2=byte

// ---- packed f32x2 helpers (attn kernel) ----
__device__ __forceinline__ ull fma2(ull a, ull b, ull c) {
    ull d;
    asm("fma.rn.f32x2 %0, %1, %2, %3;" : "=l"(d) : "l"(a), "l"(b), "l"(c));
    return d;
}
__device__ __forceinline__ ull pack2(float x, float y) {
    ull r; asm("mov.b64 %0, {%1, %2};" : "=l"(r) : "f"(x), "f"(y)); return r;
}
__device__ __forceinline__ float2 unpack2(ull v) {
    float x, y; asm("mov.b64 {%0, %1}, %2;" : "=f"(x), "=f"(y) : "l"(v));
    return make_float2(x, y);
}

// ---- HMMA helpers (baseline PTX, not 'a'-gated) ----
__device__ __forceinline__ uint32_t smem_u32(const void* p) {
    uint32_t a;
    asm("{ .reg .u64 t; cvta.to.shared.u64 t, %1; cvt.u32.u64 %0, t; }"
        : "=r"(a) : "l"(p));
    return a;
}
__device__ __forceinline__ void mma16816(float* c, const uint32_t* a,
                                         const uint32_t* b) {
    asm volatile(
        "mma.sync.aligned.m16n8k16.row.col.f32.bf16.bf16.f32 "
        "{%0,%1,%2,%3}, {%4,%5,%6,%7}, {%8,%9}, {%0,%1,%2,%3};"
        : "+f"(c[0]), "+f"(c[1]), "+f"(c[2]), "+f"(c[3])
        : "r"(a[0]), "r"(a[1]), "r"(a[2]), "r"(a[3]), "r"(b[0]), "r"(b[1]));
}
__device__ __forceinline__ void ldmA(uint32_t* r, uint32_t addr) {
    asm volatile("ldmatrix.sync.aligned.m8n8.x4.shared.b16 {%0,%1,%2,%3}, [%4];"
        : "=r"(r[0]), "=r"(r[1]), "=r"(r[2]), "=r"(r[3]) : "r"(addr));
}
// B stored [n][k] (col-major from KxN view): NON-trans ldmatrix yields the
// required b-fragment (k pair per lane). This was the R7 bug (.trans).
__device__ __forceinline__ void ldmB(uint32_t* r, uint32_t addr) {
    asm volatile("ldmatrix.sync.aligned.m8n8.x4.shared.b16 {%0,%1,%2,%3}, [%4];"
        : "=r"(r[0]), "=r"(r[1]), "=r"(r[2]), "=r"(r[3]) : "r"(addr));
}
// 64B rows, 4x16B chunks, swizzle chunk ^= (row>>1)&3 -> conflict-free ldmatrix
__device__ __forceinline__ int swz(int row, int ch) {
    return row * 64 + ((ch ^ ((row >> 1) & 3)) << 4);
}

// ---------------------------------------------------------------------------
// Mask dtype sniffing (bool may arrive as u8/i32/f32).
// ---------------------------------------------------------------------------
__global__ void detect_mask_kind(const unsigned int* __restrict__ m) {
    __shared__ int oki, okf;
    if (threadIdx.x == 0) { oki = 1; okf = 1; }
    __syncthreads();
    for (int idx = threadIdx.x; idx < 2048; idx += 256) {
        unsigned int w = m[idx];
        if (w > 1u) oki = 0;
        if (w != 0u && w != 0x3F800000u) okf = 0;
    }
    __syncthreads();
    if (threadIdx.x == 0) g_mask_kind = oki ? 0 : (okf ? 1 : 2);
}

// ---------------------------------------------------------------------------
// fp32 -> (bf16 hi, bf16 lo) elementwise split.
// ---------------------------------------------------------------------------
__global__ void split_lin(const float* __restrict__ src,
                          bf16* __restrict__ hi, bf16* __restrict__ lo) {
    int i = (blockIdx.x * 256 + threadIdx.x) * 4;
    float4 x = *(const float4*)(src + i);
    bf16 h0 = __float2bfloat16(x.x), h1 = __float2bfloat16(x.y);
    bf16 h2 = __float2bfloat16(x.z), h3 = __float2bfloat16(x.w);
    bf16 l0 = __float2bfloat16(x.x - __bfloat162float(h0));
    bf16 l1 = __float2bfloat16(x.y - __bfloat162float(h1));
    bf16 l2 = __float2bfloat16(x.z - __bfloat162float(h2));
    bf16 l3 = __float2bfloat16(x.w - __bfloat162float(h3));
    *(__nv_bfloat162*)(hi + i)     = __nv_bfloat162(h0, h1);
    *(__nv_bfloat162*)(hi + i + 2) = __nv_bfloat162(h2, h3);
    *(__nv_bfloat162*)(lo + i)     = __nv_bfloat162(l0, l1);
    *(__nv_bfloat162*)(lo + i + 2) = __nv_bfloat162(l2, l3);
}

// ---------------------------------------------------------------------------
// W[k][n] fp32 -> transposed bf16 splits WhT[n][k], WlT[n][k]. 512x512.
// ---------------------------------------------------------------------------
__global__ void split_T(const float* __restrict__ W,
                        bf16* __restrict__ hi, bf16* __restrict__ lo) {
    int idx = blockIdx.x * 256 + threadIdx.x;
    int k = idx >> 9, n = idx & 511;
    float x = W[idx];
    bf16 h = __float2bfloat16(x);
    bf16 l = __float2bfloat16(x - __bfloat162float(h));
    hi[n * 512 + k] = h;
    lo[n * 512 + k] = l;
}

// ---------------------------------------------------------------------------
// HMMA GEMM: C[8192,512] = A @ W + bias via bf16 3-term split.
// CTA 128x128, 8 warps (2x4), BK=32, mma.sync m16n8k16.
// mode 0: row-major C   mode 1: head-split to [B,H,N,DH]
// ---------------------------------------------------------------------------
__global__ void __launch_bounds__(256, 2)
gemm_tc(const bf16* __restrict__ Ah, const bf16* __restrict__ Al,
        const bf16* __restrict__ BhT, const bf16* __restrict__ BlT,
        const float* __restrict__ bias, float* __restrict__ C, int mode) {
    __shared__ bf16 sAh[128 * 32], sAl[128 * 32], sWh[128 * 32], sWl[128 * 32];
    const int tid = threadIdx.x, wid = tid >> 5, lane = tid & 31;
    const int m0 = blockIdx.y * 128, n0 = blockIdx.x * 128;
    const int wm = wid >> 2, wn = wid & 3;          // 2x4 warp grid

    const uint32_t sbAh = smem_u32(sAh), sbAl = smem_u32(sAl);
    const uint32_t sbWh = smem_u32(sWh), sbWl = smem_u32(sWl);

    // loader slots: 2 x 16B chunks per buffer per thread
    const int lr = tid >> 2, lch = tid & 3;          // row, chunk for slot 0
    const int lr1 = lr + 64;                         // slot 1

    float acc[4][4][4];
    #pragma unroll
    for (int i = 0; i < 4; i++)
        #pragma unroll
        for (int j = 0; j < 4; j++)
            #pragma unroll
            for (int t = 0; t < 4; t++) acc[i][j][t] = 0.f;

    uint4 pAh0, pAh1, pAl0, pAl1, pWh0, pWh1, pWl0, pWl1;
    {
        size_t ga0 = (size_t)(m0 + lr) * 512 + lch * 8;
        size_t ga1 = (size_t)(m0 + lr1) * 512 + lch * 8;
        size_t gb0 = (size_t)(n0 + lr) * 512 + lch * 8;
        size_t gb1 = (size_t)(n0 + lr1) * 512 + lch * 8;
        pAh0 = *(const uint4*)(Ah + ga0);  pAh1 = *(const uint4*)(Ah + ga1);
        pAl0 = *(const uint4*)(Al + ga0);  pAl1 = *(const uint4*)(Al + ga1);
        pWh0 = *(const uint4*)(BhT + gb0); pWh1 = *(const uint4*)(BhT + gb1);
        pWl0 = *(const uint4*)(BlT + gb0); pWl1 = *(const uint4*)(BlT + gb1);
    }

    const int so0 = swz(lr, lch), so1 = swz(lr1, lch);

    for (int c = 0; c < 16; c++) {
        *(uint4*)((char*)sAh + so0) = pAh0;  *(uint4*)((char*)sAh + so1) = pAh1;
        *(uint4*)((char*)sAl + so0) = pAl0;  *(uint4*)((char*)sAl + so1) = pAl1;
        *(uint4*)((char*)sWh + so0) = pWh0;  *(uint4*)((char*)sWh + so1) = pWh1;
        *(uint4*)((char*)sWl + so0) = pWl0;  *(uint4*)((char*)sWl + so1) = pWl1;
        __syncthreads();

        if (c + 1 < 16) {
            int kn = (c + 1) * 32;
            size_t ga0 = (size_t)(m0 + lr) * 512 + kn + lch * 8;
            size_t ga1 = (size_t)(m0 + lr1) * 512 + kn + lch * 8;
            size_t gb0 = (size_t)(n0 + lr) * 512 + kn + lch * 8;
            size_t gb1 = (size_t)(n0 + lr1) * 512 + kn + lch * 8;
            pAh0 = *(const uint4*)(Ah + ga0);  pAh1 = *(const uint4*)(Ah + ga1);
            pAl0 = *(const uint4*)(Al + ga0);  pAl1 = *(const uint4*)(Al + ga1);
            pWh0 = *(const uint4*)(BhT + gb0); pWh1 = *(const uint4*)(BhT + gb1);
            pWl0 = *(const uint4*)(BlT + gb0); pWl1 = *(const uint4*)(BlT + gb1);
        }

        #pragma unroll
        for (int ks = 0; ks < 2; ks++) {
            // fragment addresses for this lane
            const int arow = wm * 64 + (lane & 7) + ((lane >> 3) & 1) * 8;
            const int akch = ks * 2 + ((lane >> 4) & 1);
            const int nrow = wn * 32 + (lane & 7) + ((lane >> 4) & 1) * 8;
            const int nkch = ks * 2 + ((lane >> 3) & 1);

            uint32_t whf[2][4], wlf[2][4], af[4][4];
            #pragma unroll
            for (int g = 0; g < 2; g++) {               // ntile pairs {0,1},{2,3}
                ldmB(whf[g], sbWh + swz(nrow + g * 16, nkch));
                ldmB(wlf[g], sbWl + swz(nrow + g * 16, nkch));
            }
            #pragma unroll
            for (int mt = 0; mt < 4; mt++)
                ldmA(af[mt], sbAh + swz(arow + mt * 16, akch));
            #pragma unroll
            for (int mt = 0; mt < 4; mt++)
                #pragma unroll
                for (int nt = 0; nt < 4; nt++) {
                    mma16816(acc[mt][nt], af[mt], &whf[nt >> 1][(nt & 1) * 2]);
                    mma16816(acc[mt][nt], af[mt], &wlf[nt >> 1][(nt & 1) * 2]);
                }
            #pragma unroll
            for (int mt = 0; mt < 4; mt++)
                ldmA(af[mt], sbAl + swz(arow + mt * 16, akch));
            #pragma unroll
            for (int mt = 0; mt < 4; mt++)
                #pragma unroll
                for (int nt = 0; nt < 4; nt++)
                    mma16816(acc[mt][nt], af[mt], &whf[nt >> 1][(nt & 1) * 2]);
        }
        __syncthreads();
    }

    // ---- epilogue ----
    #pragma unroll
    for (int mt = 0; mt < 4; mt++) {
        int row = m0 + wm * 64 + mt * 16 + (lane >> 2);
        #pragma unroll
        for (int nt = 0; nt < 4; nt++) {
            int col = n0 + wn * 32 + nt * 8 + (lane & 3) * 2;
            float b0 = __ldg(&bias[col]), b1 = __ldg(&bias[col + 1]);
            float2 v0 = make_float2(acc[mt][nt][0] + b0, acc[mt][nt][1] + b1);
            float2 v1 = make_float2(acc[mt][nt][2] + b0, acc[mt][nt][3] + b1);
            if (mode == 1) {
                int h = col >> 6, d = col & 63;
                int b = row >> 8, n = row & 255;
                float* dst = C + (((size_t)b * NH + h) * NN + n) * DH + d;
                *(float2*)dst = v0;
                int b2 = (row + 8) >> 8, n2 = (row + 8) & 255;
                float* dst2 = C + (((size_t)b2 * NH + h) * NN + n2) * DH + d;
                *(float2*)dst2 = v1;
            } else {
                *(float2*)(C + (size_t)row * DM + col) = v0;
                *(float2*)(C + (size_t)(row + 8) * DM + col) = v1;
            }
        }
    }
}

// ---------------------------------------------------------------------------
// Geometric positional bias (unchanged).
// ---------------------------------------------------------------------------
__global__ void pos_kernel(const float* __restrict__ box,
                           const float* __restrict__ Wbox,
                           const float* __restrict__ bbox,
                           float* __restrict__ pos_out) {
    __shared__ float scx[NN], scy[NN], slw[NN], slh[NN];
    __shared__ float wb[65];
    const int b = blockIdx.y, i = blockIdx.x;
    const int j = threadIdx.x;

    {
        const float* bj = box + ((size_t)b * NN + j) * 4;
        float x0 = bj[0], y0 = bj[1], x1 = bj[2], y1 = bj[3];
        scx[j] = 0.5f * (x0 + x1);
        scy[j] = 0.5f * (y0 + y1);
        slw[j] = __logf(x1 - x0 + 1.0f);
        slh[j] = __logf(y1 - y0 + 1.0f);
    }
    if (j < 64) wb[j] = Wbox[j];
    if (j == 0) wb[64] = bbox[0];
    __syncthreads();

    const float* bi = box + ((size_t)b * NN + i) * 4;
    float xi0 = bi[0], yi0 = bi[1], xi1 = bi[2], yi1 = bi[3];
    float cxi = 0.5f * (xi0 + xi1), cyi = 0.5f * (yi0 + yi1);
    float wi = xi1 - xi0 + 1.0f, hi = yi1 - yi0 + 1.0f;
    float invw = 1.0f / wi, invh = 1.0f / hi;
    float lwi = __logf(wi), lhi = __logf(hi);

    float p0 = __logf(fmaxf(fabsf((cxi - scx[j]) * invw), 1e-3f));
    float p1 = __logf(fmaxf(fabsf((cyi - scy[j]) * invh), 1e-3f));
    float p2 = lwi - slw[j];
    float p3 = lhi - slh[j];

    const float dm[8] = {1.0f, 0.42169651f, 0.17782794f, 0.074989423f,
                         0.031622777f, 0.013335214f, 0.0056234132f, 0.0023713737f};
    float pc[4] = {100.f * p0, 100.f * p1, 100.f * p2, 100.f * p3};

    float s = wb[64];
    #pragma unroll
    for (int c = 0; c < 4; c++) {
        #pragma unroll
        for (int f = 0; f < 8; f++) {
            float m = pc[c] * dm[f];
            float sn, cs;
            __sincosf(m, &sn, &cs);
            s = fmaf(sn, wb[c * 8 + f], s);
            s = fmaf(cs, wb[32 + c * 8 + f], s);
        }
    }
    float ps = fmaxf(s, 0.f);

    size_t base = (size_t)b * NH * NN * NN + (size_t)i * NN + j;
    #pragma unroll
    for (int hh = 0; hh < NH; hh++)
        pos_out[base + (size_t)hh * NN * NN] = ps;
}

// ---------------------------------------------------------------------------
// Fused attention (unchanged from R5).
// ---------------------------------------------------------------------------
__global__ void attn_kernel(const void* __restrict__ maskp,
                            const float* __restrict__ pos) {
    extern __shared__ float sm[];
    float* Qs = sm;                         // [32][64]
    float* KV = sm + 2048;                  // [64][68]
    float* S  = sm + 2048 + 4352;           // [32][260]
    unsigned char* mrow = (unsigned char*)(S + 32 * 260);

    const int blk = blockIdx.x;
    const int qt = blk & 7;
    const int h  = (blk >> 3) & 7;
    const int b  = blk >> 6;
    const int tid = threadIdx.x;
    const int tx = tid & 15, ty = tid >> 4;
    const int q0 = qt * 32;
    const int kind = g_mask_kind;

    {
        int idx = b * NN + tid;
        bool mv;
        if (kind == 0)      mv = ((const int*)maskp)[idx] != 0;
        else if (kind == 1) mv = ((const float*)maskp)[idx] != 0.0f;
        else                mv = ((const unsigned char*)maskp)[idx] != 0;
        mrow[tid] = mv ? 1 : 0;
    }

    const float* Qg = g_qh + (((size_t)b * NH + h) * NN + q0) * DH;
    const float* Kg = g_kh + (((size_t)b * NH + h) * NN) * DH;
    const float* Vg = g_vh + (((size_t)b * NH + h) * NN) * DH;

    #pragma unroll
    for (int t = 0; t < 8; t++) {
        int idx = t * 256 + tid;
        Qs[idx] = Qg[idx];
    }

    const float* prow = pos + (size_t)b * (NH * NN * NN) + (size_t)q0 * NN;

    for (int kb = 0; kb < 4; kb++) {
        __syncthreads();
        #pragma unroll
        for (int t = 0; t < 16; t++) {
            int idx = t * 256 + tid;
            int key = idx >> 6, d = idx & 63;
            KV[d * 68 + key] = Kg[kb * 4096 + idx];
        }
        __syncthreads();
        ull pacc[2][2] = {{0ULL, 0ULL}, {0ULL, 0ULL}};
        #pragma unroll
        for (int d = 0; d < 64; d++) {
            float qa = Qs[(ty * 2 + 0) * 64 + d];
            float qb = Qs[(ty * 2 + 1) * 64 + d];
            ull qa2 = pack2(qa, qa), qb2 = pack2(qb, qb);
            float4 kv = *(const float4*)&KV[d * 68 + tx * 4];
            ull k01 = pack2(kv.x, kv.y), k23 = pack2(kv.z, kv.w);
            pacc[0][0] = fma2(qa2, k01, pacc[0][0]);
            pacc[0][1] = fma2(qa2, k23, pacc[0][1]);
            pacc[1][0] = fma2(qb2, k01, pacc[1][0]);
            pacc[1][1] = fma2(qb2, k23, pacc[1][1]);
        }
        #pragma unroll
        for (int i = 0; i < 2; i++) {
            int r = ty * 2 + i;
            float2 u0 = unpack2(pacc[i][0]);
            float2 u1 = unpack2(pacc[i][1]);
            float av[4] = {u0.x, u0.y, u1.x, u1.y};
            #pragma unroll
            for (int jj = 0; jj < 4; jj++) {
                int j = kb * 64 + tx * 4 + jj;
                float val = mrow[j] ? -1e9f
                          : fmaf(av[jj], 0.125f, prow[r * NN + j]);
                S[r * 260 + j] = val;
            }
        }
    }
    __syncthreads();

    {
        int row = tid >> 3, sub = tid & 7;
        float* Sr = S + row * 260;
        float mx = -3.4e38f;
        #pragma unroll
        for (int t = 0; t < 32; t++) mx = fmaxf(mx, Sr[sub + t * 8]);
        #pragma unroll
        for (int o = 4; o > 0; o >>= 1)
            mx = fmaxf(mx, __shfl_xor_sync(0xffffffffu, mx, o));
        float ssum = 0.f;
        #pragma unroll
        for (int t = 0; t < 32; t++) {
            float e = __expf(Sr[sub + t * 8] - mx);
            Sr[sub + t * 8] = e;
            ssum += e;
        }
        #pragma unroll
        for (int o = 4; o > 0; o >>= 1)
            ssum += __shfl_xor_sync(0xffffffffu, ssum, o);
        float inv = 1.0f / ssum;
        #pragma unroll
        for (int t = 0; t < 32; t++) Sr[sub + t * 8] *= inv;
    }

    ull oacc[2][2] = {{0ULL, 0ULL}, {0ULL, 0ULL}};
    for (int kb = 0; kb < 4; kb++) {
        __syncthreads();
        #pragma unroll
        for (int t = 0; t < 16; t++) {
            int idx = t * 256 + tid;
            KV[(idx >> 6) * 68 + (idx & 63)] = Vg[kb * 4096 + idx];
        }
        __syncthreads();
        #pragma unroll
        for (int k = 0; k < 64; k++) {
            float p0 = S[(ty * 2 + 0) * 260 + kb * 64 + k];
            float p1 = S[(ty * 2 + 1) * 260 + kb * 64 + k];
            ull p02 = pack2(p0, p0), p12 = pack2(p1, p1);
            float4 vv = *(const float4*)&KV[k * 68 + tx * 4];
            ull v01 = pack2(vv.x, vv.y), v23 = pack2(vv.z, vv.w);
            oacc[0][0] = fma2(p02, v01, oacc[0][0]);
            oacc[0][1] = fma2(p02, v23, oacc[0][1]);
            oacc[1][0] = fma2(p12, v01, oacc[1][0]);
            oacc[1][1] = fma2(p12, v23, oacc[1][1]);
        }
    }
    #pragma unroll
    for (int i = 0; i < 2; i++) {
        int r = q0 + ty * 2 + i;
        float2 u0 = unpack2(oacc[i][0]);
        float2 u1 = unpack2(oacc[i][1]);
        float4 o4 = make_float4(u0.x, u0.y, u1.x, u1.y);
        *(float4*)&g_att[(((size_t)b * NN + r) * DM) + h * DH + tx * 4] = o4;
    }
}

// ---------------------------------------------------------------------------
extern "C" void kernel_launch(void* const* d_in, const int* in_sizes, int n_in,
                              void* d_out, int out_size) {
    const float *v, *k, *q, *box, *Wq, *bq, *Wk, *bk, *Wv, *bv, *Wm, *bm, *Wbox, *bbox;
    const void* mask;

    if (in_sizes[0] == BB * NN * DM) {
        v    = (const float*)d_in[0];
        k    = (const float*)d_in[1];
        q    = (const float*)d_in[2];
        box  = (const float*)d_in[3];
        mask = d_in[4];
        int wb = 5;
        for (int i = 5; i < n_in; i++) {
            if (in_sizes[i] == DM * DM) { wb = i; break; }
        }
        Wq   = (const float*)d_in[wb + 0];
        bq   = (const float*)d_in[wb + 1];
        Wk   = (const float*)d_in[wb + 2];
        bk   = (const float*)d_in[wb + 3];
        Wv   = (const float*)d_in[wb + 4];
        bv   = (const float*)d_in[wb + 5];
        Wm   = (const float*)d_in[wb + 6];
        bm   = (const float*)d_in[wb + 7];
        Wbox = (const float*)d_in[wb + 8];
        bbox = (const float*)d_in[wb + 9];
    } else {
        Wbox = (const float*)d_in[0];
        Wk   = (const float*)d_in[1];
        Wm   = (const float*)d_in[2];
        Wq   = (const float*)d_in[3];
        Wv   = (const float*)d_in[4];
        bbox = (const float*)d_in[5];
        bk   = (const float*)d_in[6];
        bm   = (const float*)d_in[7];
        bq   = (const float*)d_in[8];
        bv   = (const float*)d_in[9];
        box  = (const float*)d_in[10];
        int idx = 11;
        if (idx < n_in && in_sizes[idx] == 1) idx++;
        k    = (const float*)d_in[idx + 0];
        mask = d_in[idx + 1];
        q    = (const float*)d_in[idx + 2];
        v    = (const float*)d_in[idx + 3];
    }

    const size_t ATTED_ELEMS = (size_t)BB * NN * DM;
    const size_t POS_ELEMS   = (size_t)BB * NH * NN * NN;
    float* out = (float*)d_out;

    float *posA, *kA, *vA, *qA, *attA;
    bf16 *ahA, *alA, *whA, *wlA;
    cudaGetSymbolAddress((void**)&qA,   g_qh);
    cudaGetSymbolAddress((void**)&kA,   g_kh);
    cudaGetSymbolAddress((void**)&vA,   g_vh);
    cudaGetSymbolAddress((void**)&attA, g_att);
    cudaGetSymbolAddress((void**)&posA, g_pos);
    cudaGetSymbolAddress((void**)&ahA,  g_ah);
    cudaGetSymbolAddress((void**)&alA,  g_al);
    cudaGetSymbolAddress((void**)&whA,  g_wh);
    cudaGetSymbolAddress((void**)&wlA,  g_wl);

    float* atted;
    float* pos_out;
    if ((size_t)out_size >= ATTED_ELEMS + POS_ELEMS) {
        atted   = out;
        pos_out = out + ATTED_ELEMS;
    } else if ((size_t)out_size == POS_ELEMS) {
        pos_out = out;
        atted   = attA;
    } else {
        atted   = out;
        pos_out = posA;
    }

    detect_mask_kind<<<1, 256>>>((const unsigned int*)mask);

    cudaFuncSetAttribute(attn_kernel,
                         cudaFuncAttributeMaxDynamicSharedMemorySize, 65536);

    const int SPLIT_BLKS = (BB * NN * DM) / (4 * 256);   // 4096
    dim3 gt(4, 64);

    // Q projection
    split_T<<<1024, 256>>>(Wq, whA, wlA);
    split_lin<<<SPLIT_BLKS, 256>>>(q, ahA, alA);
    gemm_tc<<<gt, 256>>>(ahA, alA, whA, wlA, bq, qA, 1);
    // K projection
    split_T<<<1024, 256>>>(Wk, whA, wlA);
    split_lin<<<SPLIT_BLKS, 256>>>(k, ahA, alA);
    gemm_tc<<<gt, 256>>>(ahA, alA, whA, wlA, bk, kA, 1);
    // V projection
    split_T<<<1024, 256>>>(Wv, whA, wlA);
    split_lin<<<SPLIT_BLKS, 256>>>(v, ahA, alA);
    gemm_tc<<<gt, 256>>>(ahA, alA, whA, wlA, bv, vA, 1);

    pos_kernel<<<dim3(NN, BB), 256>>>(box, Wbox, bbox, pos_out);

    int smem_bytes = (2048 + 4352 + 32 * 260) * 4 + 256;
    attn_kernel<<<BB * NH * 8, 256, smem_bytes>>>(mask, pos_out);

    // Output projection
    split_T<<<1024, 256>>>(Wm, whA, wlA);
    split_lin<<<SPLIT_BLKS, 256>>>(attA, ahA, alA);
    gemm_tc<<<gt, 256>>>(ahA, alA, whA, wlA, bm, atted, 0);
}

// round 9
// speedup vs baseline: 1.7985x; 1.1442x over previous
#include <cuda_runtime.h>
#include <cuda_bf16.h>
#include <cstdint>
#include <cstddef>

// Problem constants
#define BB   32
#define NN   256
#define DM   512
#define NH   8
#define DH   64

typedef unsigned long long ull;
typedef __nv_bfloat16 bf16;

// Scratch (allocation-free rule: __device__ globals)
__device__ float g_qh[BB*NH*NN*DH];   // [B,H,N,DH]
__device__ float g_kh[BB*NH*NN*DH];
__device__ float g_vh[BB*NH*NN*DH];
__device__ float g_att[BB*NN*DM];     // [B,N,DM] pre-output-proj
__device__ float g_pos[BB*NH*NN*NN];  // pos_scores fallback when d_out lacks room
__device__ bf16  g_ah[BB*NN*DM];      // A hi split (reused per GEMM)
__device__ bf16  g_al[BB*NN*DM];      // A lo split
__device__ bf16  g_wh[DM*DM];         // W^T hi split [n][k]
__device__ bf16  g_wl[DM*DM];         // W^T lo split
__device__ int   g_mask_kind;         // 0=int32, 1=float32, 2=byte

// ---- packed f32x2 helpers (attn kernel) ----
__device__ __forceinline__ ull fma2(ull a, ull b, ull c) {
    ull d;
    asm("fma.rn.f32x2 %0, %1, %2, %3;" : "=l"(d) : "l"(a), "l"(b), "l"(c));
    return d;
}
__device__ __forceinline__ ull pack2(float x, float y) {
    ull r; asm("mov.b64 %0, {%1, %2};" : "=l"(r) : "f"(x), "f"(y)); return r;
}
__device__ __forceinline__ float2 unpack2(ull v) {
    float x, y; asm("mov.b64 {%0, %1}, %2;" : "=f"(x), "=f"(y) : "l"(v));
    return make_float2(x, y);
}

// ---- HMMA helpers (baseline PTX, not 'a'-gated) ----
__device__ __forceinline__ uint32_t smem_u32(const void* p) {
    uint32_t a;
    asm("{ .reg .u64 t; cvta.to.shared.u64 t, %1; cvt.u32.u64 %0, t; }"
        : "=r"(a) : "l"(p));
    return a;
}
__device__ __forceinline__ void mma16816(float* c, const uint32_t* a,
                                         const uint32_t* b) {
    asm volatile(
        "mma.sync.aligned.m16n8k16.row.col.f32.bf16.bf16.f32 "
        "{%0,%1,%2,%3}, {%4,%5,%6,%7}, {%8,%9}, {%0,%1,%2,%3};"
        : "+f"(c[0]), "+f"(c[1]), "+f"(c[2]), "+f"(c[3])
        : "r"(a[0]), "r"(a[1]), "r"(a[2]), "r"(a[3]), "r"(b[0]), "r"(b[1]));
}
__device__ __forceinline__ void ldmA(uint32_t* r, uint32_t addr) {
    asm volatile("ldmatrix.sync.aligned.m8n8.x4.shared.b16 {%0,%1,%2,%3}, [%4];"
        : "=r"(r[0]), "=r"(r[1]), "=r"(r[2]), "=r"(r[3]) : "r"(addr));
}
// B stored [n][k]: NON-trans ldmatrix yields the required b-fragment.
__device__ __forceinline__ void ldmB(uint32_t* r, uint32_t addr) {
    asm volatile("ldmatrix.sync.aligned.m8n8.x4.shared.b16 {%0,%1,%2,%3}, [%4];"
        : "=r"(r[0]), "=r"(r[1]), "=r"(r[2]), "=r"(r[3]) : "r"(addr));
}
// 64B rows, 4x16B chunks, swizzle chunk ^= (row>>1)&3 -> conflict-free ldmatrix
__device__ __forceinline__ int swz(int row, int ch) {
    return row * 64 + ((ch ^ ((row >> 1) & 3)) << 4);
}
// ---- cp.async (Ampere-baseline) ----
__device__ __forceinline__ void cpa16(uint32_t dst, const void* src) {
    asm volatile("cp.async.cg.shared.global [%0], [%1], 16;"
                 :: "r"(dst), "l"(src) : "memory");
}
__device__ __forceinline__ void cpa_commit() {
    asm volatile("cp.async.commit_group;" ::: "memory");
}

// ---------------------------------------------------------------------------
// Mask dtype sniffing (bool may arrive as u8/i32/f32).
// ---------------------------------------------------------------------------
__global__ void detect_mask_kind(const unsigned int* __restrict__ m) {
    __shared__ int oki, okf;
    if (threadIdx.x == 0) { oki = 1; okf = 1; }
    __syncthreads();
    for (int idx = threadIdx.x; idx < 2048; idx += 256) {
        unsigned int w = m[idx];
        if (w > 1u) oki = 0;
        if (w != 0u && w != 0x3F800000u) okf = 0;
    }
    __syncthreads();
    if (threadIdx.x == 0) g_mask_kind = oki ? 0 : (okf ? 1 : 2);
}

// ---------------------------------------------------------------------------
// fp32 -> (bf16 hi, bf16 lo) elementwise split.
// ---------------------------------------------------------------------------
__global__ void split_lin(const float* __restrict__ src,
                          bf16* __restrict__ hi, bf16* __restrict__ lo) {
    int i = (blockIdx.x * 256 + threadIdx.x) * 4;
    float4 x = *(const float4*)(src + i);
    bf16 h0 = __float2bfloat16(x.x), h1 = __float2bfloat16(x.y);
    bf16 h2 = __float2bfloat16(x.z), h3 = __float2bfloat16(x.w);
    bf16 l0 = __float2bfloat16(x.x - __bfloat162float(h0));
    bf16 l1 = __float2bfloat16(x.y - __bfloat162float(h1));
    bf16 l2 = __float2bfloat16(x.z - __bfloat162float(h2));
    bf16 l3 = __float2bfloat16(x.w - __bfloat162float(h3));
    *(__nv_bfloat162*)(hi + i)     = __nv_bfloat162(h0, h1);
    *(__nv_bfloat162*)(hi + i + 2) = __nv_bfloat162(h2, h3);
    *(__nv_bfloat162*)(lo + i)     = __nv_bfloat162(l0, l1);
    *(__nv_bfloat162*)(lo + i + 2) = __nv_bfloat162(l2, l3);
}

// ---------------------------------------------------------------------------
// W[k][n] fp32 -> transposed bf16 splits WhT[n][k], WlT[n][k]. 512x512.
// ---------------------------------------------------------------------------
__global__ void split_T(const float* __restrict__ W,
                        bf16* __restrict__ hi, bf16* __restrict__ lo) {
    int idx = blockIdx.x * 256 + threadIdx.x;
    int k = idx >> 9, n = idx & 511;
    float x = W[idx];
    bf16 h = __float2bfloat16(x);
    bf16 l = __float2bfloat16(x - __bfloat162float(h));
    hi[n * 512 + k] = h;
    lo[n * 512 + k] = l;
}

// ---------------------------------------------------------------------------
// HMMA GEMM v2: cp.async 2-stage pipelined smem (dynamic, 2 x 32KB).
// CTA 128x128, 8 warps (2x4), BK=32, mma.sync m16n8k16, bf16 3-term split.
// mode 0: row-major C   mode 1: head-split to [B,H,N,DH]
// Stage layout (bytes): AH=0, AL=8192, WH=16384, WL=24576; stage stride 32768.
// ---------------------------------------------------------------------------
__device__ __forceinline__ void issue_tile(
    uint32_t bs, int kn, int m0, int n0, int lr, int lr1, int lch,
    int so0, int so1,
    const bf16* __restrict__ Ah, const bf16* __restrict__ Al,
    const bf16* __restrict__ Bh, const bf16* __restrict__ Bl) {
    size_t ga0 = (size_t)(m0 + lr)  * 512 + kn + lch * 8;
    size_t ga1 = (size_t)(m0 + lr1) * 512 + kn + lch * 8;
    size_t gb0 = (size_t)(n0 + lr)  * 512 + kn + lch * 8;
    size_t gb1 = (size_t)(n0 + lr1) * 512 + kn + lch * 8;
    cpa16(bs +         so0, Ah + ga0);  cpa16(bs +         so1, Ah + ga1);
    cpa16(bs +  8192 + so0, Al + ga0);  cpa16(bs +  8192 + so1, Al + ga1);
    cpa16(bs + 16384 + so0, Bh + gb0);  cpa16(bs + 16384 + so1, Bh + gb1);
    cpa16(bs + 24576 + so0, Bl + gb0);  cpa16(bs + 24576 + so1, Bl + gb1);
    cpa_commit();
}

__global__ void __launch_bounds__(256, 2)
gemm_tc(const bf16* __restrict__ Ah, const bf16* __restrict__ Al,
        const bf16* __restrict__ BhT, const bf16* __restrict__ BlT,
        const float* __restrict__ bias, float* __restrict__ C, int mode) {
    extern __shared__ char dsm[];
    const uint32_t sb = smem_u32(dsm);
    const int tid = threadIdx.x, wid = tid >> 5, lane = tid & 31;
    const int m0 = blockIdx.y * 128, n0 = blockIdx.x * 128;
    const int wm = wid >> 2, wn = wid & 3;          // 2x4 warp grid
    const int lr = tid >> 2, lch = tid & 3, lr1 = lr + 64;
    const int so0 = swz(lr, lch), so1 = swz(lr1, lch);

    float acc[4][4][4];
    #pragma unroll
    for (int i = 0; i < 4; i++)
        #pragma unroll
        for (int j = 0; j < 4; j++)
            #pragma unroll
            for (int t = 0; t < 4; t++) acc[i][j][t] = 0.f;

    issue_tile(sb, 0, m0, n0, lr, lr1, lch, so0, so1, Ah, Al, BhT, BlT);

    for (int c = 0; c < 16; c++) {
        if (c + 1 < 16) {
            issue_tile(sb + ((c + 1) & 1) * 32768, (c + 1) * 32,
                       m0, n0, lr, lr1, lch, so0, so1, Ah, Al, BhT, BlT);
            asm volatile("cp.async.wait_group %0;" :: "n"(1) : "memory");
        } else {
            asm volatile("cp.async.wait_group %0;" :: "n"(0) : "memory");
        }
        __syncthreads();

        const uint32_t bs = sb + (c & 1) * 32768;
        const uint32_t sbAh = bs, sbAl = bs + 8192;
        const uint32_t sbWh = bs + 16384, sbWl = bs + 24576;

        #pragma unroll
        for (int ks = 0; ks < 2; ks++) {
            const int arow = wm * 64 + (lane & 7) + ((lane >> 3) & 1) * 8;
            const int akch = ks * 2 + ((lane >> 4) & 1);
            const int nrow = wn * 32 + (lane & 7) + ((lane >> 4) & 1) * 8;
            const int nkch = ks * 2 + ((lane >> 3) & 1);

            uint32_t whf[2][4], wlf[2][4], af[4][4];
            #pragma unroll
            for (int g = 0; g < 2; g++) {               // ntile pairs {0,1},{2,3}
                ldmB(whf[g], sbWh + swz(nrow + g * 16, nkch));
                ldmB(wlf[g], sbWl + swz(nrow + g * 16, nkch));
            }
            #pragma unroll
            for (int mt = 0; mt < 4; mt++)
                ldmA(af[mt], sbAh + swz(arow + mt * 16, akch));
            #pragma unroll
            for (int mt = 0; mt < 4; mt++)
                #pragma unroll
                for (int nt = 0; nt < 4; nt++) {
                    mma16816(acc[mt][nt], af[mt], &whf[nt >> 1][(nt & 1) * 2]);
                    mma16816(acc[mt][nt], af[mt], &wlf[nt >> 1][(nt & 1) * 2]);
                }
            #pragma unroll
            for (int mt = 0; mt < 4; mt++)
                ldmA(af[mt], sbAl + swz(arow + mt * 16, akch));
            #pragma unroll
            for (int mt = 0; mt < 4; mt++)
                #pragma unroll
                for (int nt = 0; nt < 4; nt++)
                    mma16816(acc[mt][nt], af[mt], &whf[nt >> 1][(nt & 1) * 2]);
        }
        __syncthreads();
    }

    // ---- epilogue ----
    #pragma unroll
    for (int mt = 0; mt < 4; mt++) {
        int row = m0 + wm * 64 + mt * 16 + (lane >> 2);
        #pragma unroll
        for (int nt = 0; nt < 4; nt++) {
            int col = n0 + wn * 32 + nt * 8 + (lane & 3) * 2;
            float b0 = __ldg(&bias[col]), b1 = __ldg(&bias[col + 1]);
            float2 v0 = make_float2(acc[mt][nt][0] + b0, acc[mt][nt][1] + b1);
            float2 v1 = make_float2(acc[mt][nt][2] + b0, acc[mt][nt][3] + b1);
            if (mode == 1) {
                int h = col >> 6, d = col & 63;
                int b = row >> 8, n = row & 255;
                float* dst = C + (((size_t)b * NH + h) * NN + n) * DH + d;
                *(float2*)dst = v0;
                int b2 = (row + 8) >> 8, n2 = (row + 8) & 255;
                float* dst2 = C + (((size_t)b2 * NH + h) * NN + n2) * DH + d;
                *(float2*)dst2 = v1;
            } else {
                *(float2*)(C + (size_t)row * DM + col) = v0;
                *(float2*)(C + (size_t)(row + 8) * DM + col) = v1;
            }
        }
    }
}

// ---------------------------------------------------------------------------
// Geometric positional bias (unchanged).
// ---------------------------------------------------------------------------
__global__ void pos_kernel(const float* __restrict__ box,
                           const float* __restrict__ Wbox,
                           const float* __restrict__ bbox,
                           float* __restrict__ pos_out) {
    __shared__ float scx[NN], scy[NN], slw[NN], slh[NN];
    __shared__ float wb[65];
    const int b = blockIdx.y, i = blockIdx.x;
    const int j = threadIdx.x;

    {
        const float* bj = box + ((size_t)b * NN + j) * 4;
        float x0 = bj[0], y0 = bj[1], x1 = bj[2], y1 = bj[3];
        scx[j] = 0.5f * (x0 + x1);
        scy[j] = 0.5f * (y0 + y1);
        slw[j] = __logf(x1 - x0 + 1.0f);
        slh[j] = __logf(y1 - y0 + 1.0f);
    }
    if (j < 64) wb[j] = Wbox[j];
    if (j == 0) wb[64] = bbox[0];
    __syncthreads();

    const float* bi = box + ((size_t)b * NN + i) * 4;
    float xi0 = bi[0], yi0 = bi[1], xi1 = bi[2], yi1 = bi[3];
    float cxi = 0.5f * (xi0 + xi1), cyi = 0.5f * (yi0 + yi1);
    float wi = xi1 - xi0 + 1.0f, hi = yi1 - yi0 + 1.0f;
    float invw = 1.0f / wi, invh = 1.0f / hi;
    float lwi = __logf(wi), lhi = __logf(hi);

    float p0 = __logf(fmaxf(fabsf((cxi - scx[j]) * invw), 1e-3f));
    float p1 = __logf(fmaxf(fabsf((cyi - scy[j]) * invh), 1e-3f));
    float p2 = lwi - slw[j];
    float p3 = lhi - slh[j];

    const float dm[8] = {1.0f, 0.42169651f, 0.17782794f, 0.074989423f,
                         0.031622777f, 0.013335214f, 0.0056234132f, 0.0023713737f};
    float pc[4] = {100.f * p0, 100.f * p1, 100.f * p2, 100.f * p3};

    float s = wb[64];
    #pragma unroll
    for (int c = 0; c < 4; c++) {
        #pragma unroll
        for (int f = 0; f < 8; f++) {
            float m = pc[c] * dm[f];
            float sn, cs;
            __sincosf(m, &sn, &cs);
            s = fmaf(sn, wb[c * 8 + f], s);
            s = fmaf(cs, wb[32 + c * 8 + f], s);
        }
    }
    float ps = fmaxf(s, 0.f);

    size_t base = (size_t)b * NH * NN * NN + (size_t)i * NN + j;
    #pragma unroll
    for (int hh = 0; hh < NH; hh++)
        pos_out[base + (size_t)hh * NN * NN] = ps;
}

// ---------------------------------------------------------------------------
// Fused attention (unchanged from R5).
// ---------------------------------------------------------------------------
__global__ void attn_kernel(const void* __restrict__ maskp,
                            const float* __restrict__ pos) {
    extern __shared__ float sm[];
    float* Qs = sm;                         // [32][64]
    float* KV = sm + 2048;                  // [64][68]
    float* S  = sm + 2048 + 4352;           // [32][260]
    unsigned char* mrow = (unsigned char*)(S + 32 * 260);

    const int blk = blockIdx.x;
    const int qt = blk & 7;
    const int h  = (blk >> 3) & 7;
    const int b  = blk >> 6;
    const int tid = threadIdx.x;
    const int tx = tid & 15, ty = tid >> 4;
    const int q0 = qt * 32;
    const int kind = g_mask_kind;

    {
        int idx = b * NN + tid;
        bool mv;
        if (kind == 0)      mv = ((const int*)maskp)[idx] != 0;
        else if (kind == 1) mv = ((const float*)maskp)[idx] != 0.0f;
        else                mv = ((const unsigned char*)maskp)[idx] != 0;
        mrow[tid] = mv ? 1 : 0;
    }

    const float* Qg = g_qh + (((size_t)b * NH + h) * NN + q0) * DH;
    const float* Kg = g_kh + (((size_t)b * NH + h) * NN) * DH;
    const float* Vg = g_vh + (((size_t)b * NH + h) * NN) * DH;

    #pragma unroll
    for (int t = 0; t < 8; t++) {
        int idx = t * 256 + tid;
        Qs[idx] = Qg[idx];
    }

    const float* prow = pos + (size_t)b * (NH * NN * NN) + (size_t)q0 * NN;

    for (int kb = 0; kb < 4; kb++) {
        __syncthreads();
        #pragma unroll
        for (int t = 0; t < 16; t++) {
            int idx = t * 256 + tid;
            int key = idx >> 6, d = idx & 63;
            KV[d * 68 + key] = Kg[kb * 4096 + idx];
        }
        __syncthreads();
        ull pacc[2][2] = {{0ULL, 0ULL}, {0ULL, 0ULL}};
        #pragma unroll
        for (int d = 0; d < 64; d++) {
            float qa = Qs[(ty * 2 + 0) * 64 + d];
            float qb = Qs[(ty * 2 + 1) * 64 + d];
            ull qa2 = pack2(qa, qa), qb2 = pack2(qb, qb);
            float4 kv = *(const float4*)&KV[d * 68 + tx * 4];
            ull k01 = pack2(kv.x, kv.y), k23 = pack2(kv.z, kv.w);
            pacc[0][0] = fma2(qa2, k01, pacc[0][0]);
            pacc[0][1] = fma2(qa2, k23, pacc[0][1]);
            pacc[1][0] = fma2(qb2, k01, pacc[1][0]);
            pacc[1][1] = fma2(qb2, k23, pacc[1][1]);
        }
        #pragma unroll
        for (int i = 0; i < 2; i++) {
            int r = ty * 2 + i;
            float2 u0 = unpack2(pacc[i][0]);
            float2 u1 = unpack2(pacc[i][1]);
            float av[4] = {u0.x, u0.y, u1.x, u1.y};
            #pragma unroll
            for (int jj = 0; jj < 4; jj++) {
                int j = kb * 64 + tx * 4 + jj;
                float val = mrow[j] ? -1e9f
                          : fmaf(av[jj], 0.125f, prow[r * NN + j]);
                S[r * 260 + j] = val;
            }
        }
    }
    __syncthreads();

    {
        int row = tid >> 3, sub = tid & 7;
        float* Sr = S + row * 260;
        float mx = -3.4e38f;
        #pragma unroll
        for (int t = 0; t < 32; t++) mx = fmaxf(mx, Sr[sub + t * 8]);
        #pragma unroll
        for (int o = 4; o > 0; o >>= 1)
            mx = fmaxf(mx, __shfl_xor_sync(0xffffffffu, mx, o));
        float ssum = 0.f;
        #pragma unroll
        for (int t = 0; t < 32; t++) {
            float e = __expf(Sr[sub + t * 8] - mx);
            Sr[sub + t * 8] = e;
            ssum += e;
        }
        #pragma unroll
        for (int o = 4; o > 0; o >>= 1)
            ssum += __shfl_xor_sync(0xffffffffu, ssum, o);
        float inv = 1.0f / ssum;
        #pragma unroll
        for (int t = 0; t < 32; t++) Sr[sub + t * 8] *= inv;
    }

    ull oacc[2][2] = {{0ULL, 0ULL}, {0ULL, 0ULL}};
    for (int kb = 0; kb < 4; kb++) {
        __syncthreads();
        #pragma unroll
        for (int t = 0; t < 16; t++) {
            int idx = t * 256 + tid;
            KV[(idx >> 6) * 68 + (idx & 63)] = Vg[kb * 4096 + idx];
        }
        __syncthreads();
        #pragma unroll
        for (int k = 0; k < 64; k++) {
            float p0 = S[(ty * 2 + 0) * 260 + kb * 64 + k];
            float p1 = S[(ty * 2 + 1) * 260 + kb * 64 + k];
            ull p02 = pack2(p0, p0), p12 = pack2(p1, p1);
            float4 vv = *(const float4*)&KV[k * 68 + tx * 4];
            ull v01 = pack2(vv.x, vv.y), v23 = pack2(vv.z, vv.w);
            oacc[0][0] = fma2(p02, v01, oacc[0][0]);
            oacc[0][1] = fma2(p02, v23, oacc[0][1]);
            oacc[1][0] = fma2(p12, v01, oacc[1][0]);
            oacc[1][1] = fma2(p12, v23, oacc[1][1]);
        }
    }
    #pragma unroll
    for (int i = 0; i < 2; i++) {
        int r = q0 + ty * 2 + i;
        float2 u0 = unpack2(oacc[i][0]);
        float2 u1 = unpack2(oacc[i][1]);
        float4 o4 = make_float4(u0.x, u0.y, u1.x, u1.y);
        *(float4*)&g_att[(((size_t)b * NN + r) * DM) + h * DH + tx * 4] = o4;
    }
}

// ---------------------------------------------------------------------------
extern "C" void kernel_launch(void* const* d_in, const int* in_sizes, int n_in,
                              void* d_out, int out_size) {
    const float *v, *k, *q, *box, *Wq, *bq, *Wk, *bk, *Wv, *bv, *Wm, *bm, *Wbox, *bbox;
    const void* mask;

    if (in_sizes[0] == BB * NN * DM) {
        v    = (const float*)d_in[0];
        k    = (const float*)d_in[1];
        q    = (const float*)d_in[2];
        box  = (const float*)d_in[3];
        mask = d_in[4];
        int wb = 5;
        for (int i = 5; i < n_in; i++) {
            if (in_sizes[i] == DM * DM) { wb = i; break; }
        }
        Wq   = (const float*)d_in[wb + 0];
        bq   = (const float*)d_in[wb + 1];
        Wk   = (const float*)d_in[wb + 2];
        bk   = (const float*)d_in[wb + 3];
        Wv   = (const float*)d_in[wb + 4];
        bv   = (const float*)d_in[wb + 5];
        Wm   = (const float*)d_in[wb + 6];
        bm   = (const float*)d_in[wb + 7];
        Wbox = (const float*)d_in[wb + 8];
        bbox = (const float*)d_in[wb + 9];
    } else {
        Wbox = (const float*)d_in[0];
        Wk   = (const float*)d_in[1];
        Wm   = (const float*)d_in[2];
        Wq   = (const float*)d_in[3];
        Wv   = (const float*)d_in[4];
        bbox = (const float*)d_in[5];
        bk   = (const float*)d_in[6];
        bm   = (const float*)d_in[7];
        bq   = (const float*)d_in[8];
        bv   = (const float*)d_in[9];
        box  = (const float*)d_in[10];
        int idx = 11;
        if (idx < n_in && in_sizes[idx] == 1) idx++;
        k    = (const float*)d_in[idx + 0];
        mask = d_in[idx + 1];
        q    = (const float*)d_in[idx + 2];
        v    = (const float*)d_in[idx + 3];
    }

    const size_t ATTED_ELEMS = (size_t)BB * NN * DM;
    const size_t POS_ELEMS   = (size_t)BB * NH * NN * NN;
    float* out = (float*)d_out;

    float *posA, *kA, *vA, *qA, *attA;
    bf16 *ahA, *alA, *whA, *wlA;
    cudaGetSymbolAddress((void**)&qA,   g_qh);
    cudaGetSymbolAddress((void**)&kA,   g_kh);
    cudaGetSymbolAddress((void**)&vA,   g_vh);
    cudaGetSymbolAddress((void**)&attA, g_att);
    cudaGetSymbolAddress((void**)&posA, g_pos);
    cudaGetSymbolAddress((void**)&ahA,  g_ah);
    cudaGetSymbolAddress((void**)&alA,  g_al);
    cudaGetSymbolAddress((void**)&whA,  g_wh);
    cudaGetSymbolAddress((void**)&wlA,  g_wl);

    float* atted;
    float* pos_out;
    if ((size_t)out_size >= ATTED_ELEMS + POS_ELEMS) {
        atted   = out;
        pos_out = out + ATTED_ELEMS;
    } else if ((size_t)out_size == POS_ELEMS) {
        pos_out = out;
        atted   = attA;
    } else {
        atted   = out;
        pos_out = posA;
    }

    detect_mask_kind<<<1, 256>>>((const unsigned int*)mask);

    cudaFuncSetAttribute(gemm_tc,
                         cudaFuncAttributeMaxDynamicSharedMemorySize, 65536);
    cudaFuncSetAttribute(attn_kernel,
                         cudaFuncAttributeMaxDynamicSharedMemorySize, 65536);

    const int SPLIT_BLKS = (BB * NN * DM) / (4 * 256);   // 4096
    dim3 gt(4, 64);

    // Q projection
    split_T<<<1024, 256>>>(Wq, whA, wlA);
    split_lin<<<SPLIT_BLKS, 256>>>(q, ahA, alA);
    gemm_tc<<<gt, 256, 65536>>>(ahA, alA, whA, wlA, bq, qA, 1);
    // K projection
    split_T<<<1024, 256>>>(Wk, whA, wlA);
    split_lin<<<SPLIT_BLKS, 256>>>(k, ahA, alA);
    gemm_tc<<<gt, 256, 65536>>>(ahA, alA, whA, wlA, bk, kA, 1);
    // V projection
    split_T<<<1024, 256>>>(Wv, whA, wlA);
    split_lin<<<SPLIT_BLKS, 256>>>(v, ahA, alA);
    gemm_tc<<<gt, 256, 65536>>>(ahA, alA, whA, wlA, bv, vA, 1);

    pos_kernel<<<dim3(NN, BB), 256>>>(box, Wbox, bbox, pos_out);

    int smem_bytes = (2048 + 4352 + 32 * 260) * 4 + 256;
    attn_kernel<<<BB * NH * 8, 256, smem_bytes>>>(mask, pos_out);

    // Output projection
    split_T<<<1024, 256>>>(Wm, whA, wlA);
    split_lin<<<SPLIT_BLKS, 256>>>(attA, ahA, alA);
    gemm_tc<<<gt, 256, 65536>>>(ahA, alA, whA, wlA, bm, atted, 0);
}

// round 10
// speedup vs baseline: 2.1043x; 1.1701x over previous
#include <cuda_runtime.h>
#include <cuda_bf16.h>
#include <cstdint>
#include <cstddef>

// Problem constants
#define BB   32
#define NN   256
#define DM   512
#define NH   8
#define DH   64

typedef unsigned long long ull;
typedef __nv_bfloat16 bf16;

// Scratch (allocation-free rule: __device__ globals)
__device__ float g_att[BB*NN*DM];     // [B,N,DM] pre-output-proj
__device__ float g_pos[BB*NH*NN*NN];  // pos_scores fallback when d_out lacks room
__device__ bf16  g_ah[BB*NN*DM];      // A hi split (reused per GEMM)
__device__ bf16  g_al[BB*NN*DM];      // A lo split
__device__ bf16  g_wh[DM*DM];         // W^T hi split [n][k]
__device__ bf16  g_wl[DM*DM];         // W^T lo split
__device__ bf16  g_qhh[BB*NH*NN*DH], g_qhl[BB*NH*NN*DH];  // Q heads hi/lo
__device__ bf16  g_khh[BB*NH*NN*DH], g_khl[BB*NH*NN*DH];  // K heads hi/lo
__device__ bf16  g_vhh[BB*NH*NN*DH], g_vhl[BB*NH*NN*DH];  // V heads hi/lo
__device__ int   g_mask_kind;         // 0=int32, 1=float32, 2=byte

// ---- HMMA helpers (baseline PTX, not 'a'-gated) ----
__device__ __forceinline__ uint32_t smem_u32(const void* p) {
    uint32_t a;
    asm("{ .reg .u64 t; cvta.to.shared.u64 t, %1; cvt.u32.u64 %0, t; }"
        : "=r"(a) : "l"(p));
    return a;
}
__device__ __forceinline__ void mma16816(float* c, const uint32_t* a,
                                         const uint32_t* b) {
    asm volatile(
        "mma.sync.aligned.m16n8k16.row.col.f32.bf16.bf16.f32 "
        "{%0,%1,%2,%3}, {%4,%5,%6,%7}, {%8,%9}, {%0,%1,%2,%3};"
        : "+f"(c[0]), "+f"(c[1]), "+f"(c[2]), "+f"(c[3])
        : "r"(a[0]), "r"(a[1]), "r"(a[2]), "r"(a[3]), "r"(b[0]), "r"(b[1]));
}
__device__ __forceinline__ void ldmA(uint32_t* r, uint32_t addr) {
    asm volatile("ldmatrix.sync.aligned.m8n8.x4.shared.b16 {%0,%1,%2,%3}, [%4];"
        : "=r"(r[0]), "=r"(r[1]), "=r"(r[2]), "=r"(r[3]) : "r"(addr));
}
__device__ __forceinline__ void ldmB(uint32_t* r, uint32_t addr) {
    asm volatile("ldmatrix.sync.aligned.m8n8.x4.shared.b16 {%0,%1,%2,%3}, [%4];"
        : "=r"(r[0]), "=r"(r[1]), "=r"(r[2]), "=r"(r[3]) : "r"(addr));
}
// trans variant: [k][n]-stored data -> b-fragment (V tiles)
__device__ __forceinline__ void ldmVT(uint32_t* r, uint32_t addr) {
    asm volatile("ldmatrix.sync.aligned.m8n8.x4.trans.shared.b16 {%0,%1,%2,%3}, [%4];"
        : "=r"(r[0]), "=r"(r[1]), "=r"(r[2]), "=r"(r[3]) : "r"(addr));
}
// gemm smem: 64B rows, 4x16B chunks
__device__ __forceinline__ int swz(int row, int ch) {
    return row * 64 + ((ch ^ ((row >> 1) & 3)) << 4);
}
// attn smem: 128B rows (64 bf16), 8x16B chunks
__device__ __forceinline__ int swz128(int row, int ch) {
    return row * 128 + ((ch ^ (row & 7)) << 4);
}
// P smem: 512B rows (256 bf16), 32x16B chunks
__device__ __forceinline__ int swzP(int row, int ch) {
    return row * 512 + ((ch ^ (row & 7)) << 4);
}
// ---- cp.async (Ampere-baseline) ----
__device__ __forceinline__ void cpa16(uint32_t dst, const void* src) {
    asm volatile("cp.async.cg.shared.global [%0], [%1], 16;"
                 :: "r"(dst), "l"(src) : "memory");
}
__device__ __forceinline__ void cpa_commit() {
    asm volatile("cp.async.commit_group;" ::: "memory");
}

// ---------------------------------------------------------------------------
// Mask dtype sniffing (bool may arrive as u8/i32/f32).
// ---------------------------------------------------------------------------
__global__ void detect_mask_kind(const unsigned int* __restrict__ m) {
    __shared__ int oki, okf;
    if (threadIdx.x == 0) { oki = 1; okf = 1; }
    __syncthreads();
    for (int idx = threadIdx.x; idx < 2048; idx += 256) {
        unsigned int w = m[idx];
        if (w > 1u) oki = 0;
        if (w != 0u && w != 0x3F800000u) okf = 0;
    }
    __syncthreads();
    if (threadIdx.x == 0) g_mask_kind = oki ? 0 : (okf ? 1 : 2);
}

// ---------------------------------------------------------------------------
// fp32 -> (bf16 hi, bf16 lo) elementwise split.
// ---------------------------------------------------------------------------
__global__ void split_lin(const float* __restrict__ src,
                          bf16* __restrict__ hi, bf16* __restrict__ lo) {
    int i = (blockIdx.x * 256 + threadIdx.x) * 4;
    float4 x = *(const float4*)(src + i);
    bf16 h0 = __float2bfloat16(x.x), h1 = __float2bfloat16(x.y);
    bf16 h2 = __float2bfloat16(x.z), h3 = __float2bfloat16(x.w);
    bf16 l0 = __float2bfloat16(x.x - __bfloat162float(h0));
    bf16 l1 = __float2bfloat16(x.y - __bfloat162float(h1));
    bf16 l2 = __float2bfloat16(x.z - __bfloat162float(h2));
    bf16 l3 = __float2bfloat16(x.w - __bfloat162float(h3));
    *(__nv_bfloat162*)(hi + i)     = __nv_bfloat162(h0, h1);
    *(__nv_bfloat162*)(hi + i + 2) = __nv_bfloat162(h2, h3);
    *(__nv_bfloat162*)(lo + i)     = __nv_bfloat162(l0, l1);
    *(__nv_bfloat162*)(lo + i + 2) = __nv_bfloat162(l2, l3);
}

// ---------------------------------------------------------------------------
// W[k][n] fp32 -> transposed bf16 splits WhT[n][k], WlT[n][k]. 512x512.
// ---------------------------------------------------------------------------
__global__ void split_T(const float* __restrict__ W,
                        bf16* __restrict__ hi, bf16* __restrict__ lo) {
    int idx = blockIdx.x * 256 + threadIdx.x;
    int k = idx >> 9, n = idx & 511;
    float x = W[idx];
    bf16 h = __float2bfloat16(x);
    bf16 l = __float2bfloat16(x - __bfloat162float(h));
    hi[n * 512 + k] = h;
    lo[n * 512 + k] = l;
}

// ---------------------------------------------------------------------------
// HMMA GEMM: cp.async 2-stage pipeline. CTA 128x128, 8 warps (2x4), BK=32.
// mode 0: fp32 row-major C.  mode 1: bf16 hi/lo head-split [B,H,N,DH].
// ---------------------------------------------------------------------------
__device__ __forceinline__ void issue_tile(
    uint32_t bs, int kn, int m0, int n0, int lr, int lr1, int lch,
    int so0, int so1,
    const bf16* __restrict__ Ah, const bf16* __restrict__ Al,
    const bf16* __restrict__ Bh, const bf16* __restrict__ Bl) {
    size_t ga0 = (size_t)(m0 + lr)  * 512 + kn + lch * 8;
    size_t ga1 = (size_t)(m0 + lr1) * 512 + kn + lch * 8;
    size_t gb0 = (size_t)(n0 + lr)  * 512 + kn + lch * 8;
    size_t gb1 = (size_t)(n0 + lr1) * 512 + kn + lch * 8;
    cpa16(bs +         so0, Ah + ga0);  cpa16(bs +         so1, Ah + ga1);
    cpa16(bs +  8192 + so0, Al + ga0);  cpa16(bs +  8192 + so1, Al + ga1);
    cpa16(bs + 16384 + so0, Bh + gb0);  cpa16(bs + 16384 + so1, Bh + gb1);
    cpa16(bs + 24576 + so0, Bl + gb0);  cpa16(bs + 24576 + so1, Bl + gb1);
    cpa_commit();
}

__global__ void __launch_bounds__(256, 2)
gemm_tc(const bf16* __restrict__ Ah, const bf16* __restrict__ Al,
        const bf16* __restrict__ BhT, const bf16* __restrict__ BlT,
        const float* __restrict__ bias, float* __restrict__ C,
        bf16* __restrict__ Chi, bf16* __restrict__ Clo, int mode) {
    extern __shared__ char dsm[];
    const uint32_t sb = smem_u32(dsm);
    const int tid = threadIdx.x, wid = tid >> 5, lane = tid & 31;
    const int m0 = blockIdx.y * 128, n0 = blockIdx.x * 128;
    const int wm = wid >> 2, wn = wid & 3;
    const int lr = tid >> 2, lch = tid & 3, lr1 = lr + 64;
    const int so0 = swz(lr, lch), so1 = swz(lr1, lch);

    float acc[4][4][4];
    #pragma unroll
    for (int i = 0; i < 4; i++)
        #pragma unroll
        for (int j = 0; j < 4; j++)
            #pragma unroll
            for (int t = 0; t < 4; t++) acc[i][j][t] = 0.f;

    issue_tile(sb, 0, m0, n0, lr, lr1, lch, so0, so1, Ah, Al, BhT, BlT);

    for (int c = 0; c < 16; c++) {
        if (c + 1 < 16) {
            issue_tile(sb + ((c + 1) & 1) * 32768, (c + 1) * 32,
                       m0, n0, lr, lr1, lch, so0, so1, Ah, Al, BhT, BlT);
            asm volatile("cp.async.wait_group %0;" :: "n"(1) : "memory");
        } else {
            asm volatile("cp.async.wait_group %0;" :: "n"(0) : "memory");
        }
        __syncthreads();

        const uint32_t bs = sb + (c & 1) * 32768;
        const uint32_t sbAh = bs, sbAl = bs + 8192;
        const uint32_t sbWh = bs + 16384, sbWl = bs + 24576;

        #pragma unroll
        for (int ks = 0; ks < 2; ks++) {
            const int arow = wm * 64 + (lane & 7) + ((lane >> 3) & 1) * 8;
            const int akch = ks * 2 + ((lane >> 4) & 1);
            const int nrow = wn * 32 + (lane & 7) + ((lane >> 4) & 1) * 8;
            const int nkch = ks * 2 + ((lane >> 3) & 1);

            uint32_t whf[2][4], wlf[2][4], af[4][4];
            #pragma unroll
            for (int g = 0; g < 2; g++) {
                ldmB(whf[g], sbWh + swz(nrow + g * 16, nkch));
                ldmB(wlf[g], sbWl + swz(nrow + g * 16, nkch));
            }
            #pragma unroll
            for (int mt = 0; mt < 4; mt++)
                ldmA(af[mt], sbAh + swz(arow + mt * 16, akch));
            #pragma unroll
            for (int mt = 0; mt < 4; mt++)
                #pragma unroll
                for (int nt = 0; nt < 4; nt++) {
                    mma16816(acc[mt][nt], af[mt], &whf[nt >> 1][(nt & 1) * 2]);
                    mma16816(acc[mt][nt], af[mt], &wlf[nt >> 1][(nt & 1) * 2]);
                }
            #pragma unroll
            for (int mt = 0; mt < 4; mt++)
                ldmA(af[mt], sbAl + swz(arow + mt * 16, akch));
            #pragma unroll
            for (int mt = 0; mt < 4; mt++)
                #pragma unroll
                for (int nt = 0; nt < 4; nt++)
                    mma16816(acc[mt][nt], af[mt], &whf[nt >> 1][(nt & 1) * 2]);
        }
        __syncthreads();
    }

    // ---- epilogue ----
    #pragma unroll
    for (int mt = 0; mt < 4; mt++) {
        int row = m0 + wm * 64 + mt * 16 + (lane >> 2);
        #pragma unroll
        for (int nt = 0; nt < 4; nt++) {
            int col = n0 + wn * 32 + nt * 8 + (lane & 3) * 2;
            float b0 = __ldg(&bias[col]), b1 = __ldg(&bias[col + 1]);
            float2 v0 = make_float2(acc[mt][nt][0] + b0, acc[mt][nt][1] + b1);
            float2 v1 = make_float2(acc[mt][nt][2] + b0, acc[mt][nt][3] + b1);
            if (mode == 1) {
                int h = col >> 6, d = col & 63;
                #pragma unroll
                for (int half = 0; half < 2; half++) {
                    float2 v = half ? v1 : v0;
                    int rr = row + half * 8;
                    int b = rr >> 8, n = rr & 255;
                    size_t base = (((size_t)b * NH + h) * NN + n) * DH + d;
                    bf16 h0 = __float2bfloat16(v.x), h1 = __float2bfloat16(v.y);
                    bf16 l0 = __float2bfloat16(v.x - __bfloat162float(h0));
                    bf16 l1 = __float2bfloat16(v.y - __bfloat162float(h1));
                    *(__nv_bfloat162*)&Chi[base] = __nv_bfloat162(h0, h1);
                    *(__nv_bfloat162*)&Clo[base] = __nv_bfloat162(l0, l1);
                }
            } else {
                *(float2*)(C + (size_t)row * DM + col) = v0;
                *(float2*)(C + (size_t)(row + 8) * DM + col) = v1;
            }
        }
    }
}

// ---------------------------------------------------------------------------
// Geometric positional bias (unchanged).
// ---------------------------------------------------------------------------
__global__ void pos_kernel(const float* __restrict__ box,
                           const float* __restrict__ Wbox,
                           const float* __restrict__ bbox,
                           float* __restrict__ pos_out) {
    __shared__ float scx[NN], scy[NN], slw[NN], slh[NN];
    __shared__ float wb[65];
    const int b = blockIdx.y, i = blockIdx.x;
    const int j = threadIdx.x;

    {
        const float* bj = box + ((size_t)b * NN + j) * 4;
        float x0 = bj[0], y0 = bj[1], x1 = bj[2], y1 = bj[3];
        scx[j] = 0.5f * (x0 + x1);
        scy[j] = 0.5f * (y0 + y1);
        slw[j] = __logf(x1 - x0 + 1.0f);
        slh[j] = __logf(y1 - y0 + 1.0f);
    }
    if (j < 64) wb[j] = Wbox[j];
    if (j == 0) wb[64] = bbox[0];
    __syncthreads();

    const float* bi = box + ((size_t)b * NN + i) * 4;
    float xi0 = bi[0], yi0 = bi[1], xi1 = bi[2], yi1 = bi[3];
    float cxi = 0.5f * (xi0 + xi1), cyi = 0.5f * (yi0 + yi1);
    float wi = xi1 - xi0 + 1.0f, hi = yi1 - yi0 + 1.0f;
    float invw = 1.0f / wi, invh = 1.0f / hi;
    float lwi = __logf(wi), lhi = __logf(hi);

    float p0 = __logf(fmaxf(fabsf((cxi - scx[j]) * invw), 1e-3f));
    float p1 = __logf(fmaxf(fabsf((cyi - scy[j]) * invh), 1e-3f));
    float p2 = lwi - slw[j];
    float p3 = lhi - slh[j];

    const float dm[8] = {1.0f, 0.42169651f, 0.17782794f, 0.074989423f,
                         0.031622777f, 0.013335214f, 0.0056234132f, 0.0023713737f};
    float pc[4] = {100.f * p0, 100.f * p1, 100.f * p2, 100.f * p3};

    float s = wb[64];
    #pragma unroll
    for (int c = 0; c < 4; c++) {
        #pragma unroll
        for (int f = 0; f < 8; f++) {
            float m = pc[c] * dm[f];
            float sn, cs;
            __sincosf(m, &sn, &cs);
            s = fmaf(sn, wb[c * 8 + f], s);
            s = fmaf(cs, wb[32 + c * 8 + f], s);
        }
    }
    float ps = fmaxf(s, 0.f);

    size_t base = (size_t)b * NH * NN * NN + (size_t)i * NN + j;
    #pragma unroll
    for (int hh = 0; hh < NH; hh++)
        pos_out[base + (size_t)hh * NN * NN] = ps;
}

// ---------------------------------------------------------------------------
// HMMA attention per (b, h, 32-q tile). bf16-split QK^T and PV via mma.sync.
// smem: Qh 0..4K | Ql 4K..8K | Kt/Vt hi 8K..16K | lo 16K..24K |
//       S fp32 24576..58368 (32x264)  [overlaid: Phi 24576+16K, Plo 40960+16K]
//       mrow @58368. Total 58624 bytes.
// ---------------------------------------------------------------------------
#define AT_SQH 0
#define AT_SQL 4096
#define AT_SKH 8192
#define AT_SKL 16384
#define AT_S   24576
#define AT_PHI 24576
#define AT_PLO 40960
#define AT_MR  58368
#define AT_TOT 58624

__global__ void __launch_bounds__(256, 2)
attn_tc(const void* __restrict__ maskp, const float* __restrict__ pos) {
    extern __shared__ char sm8[];
    const uint32_t sb = smem_u32(sm8);
    float* S = (float*)(sm8 + AT_S);
    unsigned char* mrow = (unsigned char*)(sm8 + AT_MR);

    const int blk = blockIdx.x;
    const int qt = blk & 7, h = (blk >> 3) & 7, b = blk >> 6;
    const int tid = threadIdx.x, wid = tid >> 5, lane = tid & 31;
    const int wm = wid >> 2, wn = wid & 3;          // 2 x 4 warp grid
    const int q0 = qt * 32;
    const int kind = g_mask_kind;

    {
        int idx = b * NN + tid;
        bool mv;
        if (kind == 0)      mv = ((const int*)maskp)[idx] != 0;
        else if (kind == 1) mv = ((const float*)maskp)[idx] != 0.0f;
        else                mv = ((const unsigned char*)maskp)[idx] != 0;
        mrow[tid] = mv ? 1 : 0;
    }

    const size_t hb = ((size_t)b * NH + h) * NN;
    const bf16* Qh = g_qhh + (hb + q0) * DH;
    const bf16* Ql = g_qhl + (hb + q0) * DH;
    const bf16* Kh = g_khh + hb * DH;
    const bf16* Kl = g_khl + hb * DH;
    const bf16* Vh = g_vhh + hb * DH;
    const bf16* Vl = g_vhl + hb * DH;

    // load Q tiles (32 rows x 64 d): one 16B chunk per buffer per thread
    {
        int row = tid >> 3, ch = tid & 7;
        *(uint4*)(sm8 + AT_SQH + swz128(row, ch)) = *(const uint4*)(Qh + row * 64 + ch * 8);
        *(uint4*)(sm8 + AT_SQL + swz128(row, ch)) = *(const uint4*)(Ql + row * 64 + ch * 8);
    }
    const float* prow = pos + (size_t)b * (NH * NN * NN) + (size_t)q0 * NN;

    // ---- S = scale * Q K^T + pos, masked (HMMA) ----
    for (int kb = 0; kb < 4; kb++) {
        if (kb) __syncthreads();
        #pragma unroll
        for (int t = 0; t < 2; t++) {          // 64 rows x 8 chunks = 512 slots
            int idx = t * 256 + tid;
            int row = idx >> 3, ch = idx & 7;
            const bf16* src = Kh + (size_t)(kb * 64 + row) * 64 + ch * 8;
            const bf16* srl = Kl + (size_t)(kb * 64 + row) * 64 + ch * 8;
            *(uint4*)(sm8 + AT_SKH + swz128(row, ch)) = *(const uint4*)src;
            *(uint4*)(sm8 + AT_SKL + swz128(row, ch)) = *(const uint4*)srl;
        }
        __syncthreads();

        float acc[2][4] = {{0.f,0.f,0.f,0.f},{0.f,0.f,0.f,0.f}};
        #pragma unroll
        for (int ks = 0; ks < 4; ks++) {       // d chunks of 16
            const int arow = wm * 16 + (lane & 7) + ((lane >> 3) & 1) * 8;
            const int akch = ks * 2 + ((lane >> 4) & 1);
            const int nrow = wn * 16 + (lane & 7) + ((lane >> 4) & 1) * 8;
            const int nkch = ks * 2 + ((lane >> 3) & 1);
            uint32_t aH[4], aL[4], bH[4], bL[4];
            ldmA(aH, sb + AT_SQH + swz128(arow, akch));
            ldmA(aL, sb + AT_SQL + swz128(arow, akch));
            ldmB(bH, sb + AT_SKH + swz128(nrow, nkch));
            ldmB(bL, sb + AT_SKL + swz128(nrow, nkch));
            #pragma unroll
            for (int nt = 0; nt < 2; nt++) {
                mma16816(acc[nt], aH, bH + nt * 2);
                mma16816(acc[nt], aH, bL + nt * 2);
                mma16816(acc[nt], aL, bH + nt * 2);
            }
        }
        #pragma unroll
        for (int nt = 0; nt < 2; nt++) {
            int col = kb * 64 + wn * 16 + nt * 8 + (lane & 3) * 2;
            #pragma unroll
            for (int half = 0; half < 2; half++) {
                int r = wm * 16 + (lane >> 2) + half * 8;
                float a0 = acc[nt][half * 2 + 0], a1 = acc[nt][half * 2 + 1];
                float v0 = mrow[col]     ? -1e9f : fmaf(a0, 0.125f, prow[r * NN + col]);
                float v1 = mrow[col + 1] ? -1e9f : fmaf(a1, 0.125f, prow[r * NN + col + 1]);
                S[r * 264 + col]     = v0;
                S[r * 264 + col + 1] = v1;
            }
        }
    }
    __syncthreads();

    // ---- softmax: 8 lanes per row ----
    {
        int row = tid >> 3, sub = tid & 7;
        float* Sr = S + row * 264;
        float mx = -3.4e38f;
        #pragma unroll
        for (int t = 0; t < 32; t++) mx = fmaxf(mx, Sr[sub + t * 8]);
        #pragma unroll
        for (int o = 4; o > 0; o >>= 1)
            mx = fmaxf(mx, __shfl_xor_sync(0xffffffffu, mx, o));
        float ssum = 0.f;
        #pragma unroll
        for (int t = 0; t < 32; t++) {
            float e = __expf(Sr[sub + t * 8] - mx);
            Sr[sub + t * 8] = e;
            ssum += e;
        }
        #pragma unroll
        for (int o = 4; o > 0; o >>= 1)
            ssum += __shfl_xor_sync(0xffffffffu, ssum, o);
        float inv = 1.0f / ssum;
        #pragma unroll
        for (int t = 0; t < 32; t++) Sr[sub + t * 8] *= inv;
    }
    __syncthreads();

    // ---- convert P (fp32 S) -> bf16 hi/lo, overlaid on S region ----
    {
        int row = tid >> 3, cb = (tid & 7) * 4;
        float tmp[32];
        #pragma unroll
        for (int c4 = 0; c4 < 4; c4++)
            #pragma unroll
            for (int e = 0; e < 8; e++)
                tmp[c4 * 8 + e] = S[row * 264 + (cb + c4) * 8 + e];
        __syncthreads();
        #pragma unroll
        for (int c4 = 0; c4 < 4; c4++) {
            uint32_t hi4[4], lo4[4];
            #pragma unroll
            for (int p = 0; p < 4; p++) {
                float x0 = tmp[c4 * 8 + p * 2], x1 = tmp[c4 * 8 + p * 2 + 1];
                bf16 h0 = __float2bfloat16(x0), h1 = __float2bfloat16(x1);
                bf16 l0 = __float2bfloat16(x0 - __bfloat162float(h0));
                bf16 l1 = __float2bfloat16(x1 - __bfloat162float(h1));
                __nv_bfloat162 hp(h0, h1), lp(l0, l1);
                hi4[p] = *(uint32_t*)&hp;
                lo4[p] = *(uint32_t*)&lp;
            }
            *(uint4*)(sm8 + AT_PHI + swzP(row, cb + c4)) = make_uint4(hi4[0], hi4[1], hi4[2], hi4[3]);
            *(uint4*)(sm8 + AT_PLO + swzP(row, cb + c4)) = make_uint4(lo4[0], lo4[1], lo4[2], lo4[3]);
        }
    }

    // ---- O = P V (HMMA, V via ldmatrix.trans) ----
    float oacc[2][4] = {{0.f,0.f,0.f,0.f},{0.f,0.f,0.f,0.f}};
    for (int kb = 0; kb < 4; kb++) {
        __syncthreads();                        // P writes / prior V reads done
        #pragma unroll
        for (int t = 0; t < 2; t++) {
            int idx = t * 256 + tid;
            int row = idx >> 3, ch = idx & 7;
            const bf16* src = Vh + (size_t)(kb * 64 + row) * 64 + ch * 8;
            const bf16* srl = Vl + (size_t)(kb * 64 + row) * 64 + ch * 8;
            *(uint4*)(sm8 + AT_SKH + swz128(row, ch)) = *(const uint4*)src;
            *(uint4*)(sm8 + AT_SKL + swz128(row, ch)) = *(const uint4*)srl;
        }
        __syncthreads();
        #pragma unroll
        for (int ks = 0; ks < 4; ks++) {        // keys 16 per step
            const int arow = wm * 16 + (lane & 7) + ((lane >> 3) & 1) * 8;
            const int akch = kb * 8 + ks * 2 + ((lane >> 4) & 1);   // global key chunk
            const int vrow = ks * 16 + (lane & 7) + ((lane >> 3) & 1) * 8;
            const int vch  = wn * 2 + ((lane >> 4) & 1);            // d chunks
            uint32_t pH[4], pL[4], vH[4], vL[4];
            ldmA(pH, sb + AT_PHI + swzP(arow, akch));
            ldmA(pL, sb + AT_PLO + swzP(arow, akch));
            ldmVT(vH, sb + AT_SKH + swz128(vrow, vch));
            ldmVT(vL, sb + AT_SKL + swz128(vrow, vch));
            #pragma unroll
            for (int nt = 0; nt < 2; nt++) {
                mma16816(oacc[nt], pH, vH + nt * 2);
                mma16816(oacc[nt], pH, vL + nt * 2);
                mma16816(oacc[nt], pL, vH + nt * 2);
            }
        }
    }

    // ---- store O ----
    #pragma unroll
    for (int nt = 0; nt < 2; nt++) {
        int dcol = h * 64 + wn * 16 + nt * 8 + (lane & 3) * 2;
        #pragma unroll
        for (int half = 0; half < 2; half++) {
            int drow = q0 + wm * 16 + (lane >> 2) + half * 8;
            float2 v = make_float2(oacc[nt][half * 2], oacc[nt][half * 2 + 1]);
            *(float2*)&g_att[((size_t)b * NN + drow) * DM + dcol] = v;
        }
    }
}

// ---------------------------------------------------------------------------
extern "C" void kernel_launch(void* const* d_in, const int* in_sizes, int n_in,
                              void* d_out, int out_size) {
    const float *v, *k, *q, *box, *Wq, *bq, *Wk, *bk, *Wv, *bv, *Wm, *bm, *Wbox, *bbox;
    const void* mask;

    if (in_sizes[0] == BB * NN * DM) {
        v    = (const float*)d_in[0];
        k    = (const float*)d_in[1];
        q    = (const float*)d_in[2];
        box  = (const float*)d_in[3];
        mask = d_in[4];
        int wb = 5;
        for (int i = 5; i < n_in; i++) {
            if (in_sizes[i] == DM * DM) { wb = i; break; }
        }
        Wq   = (const float*)d_in[wb + 0];
        bq   = (const float*)d_in[wb + 1];
        Wk   = (const float*)d_in[wb + 2];
        bk   = (const float*)d_in[wb + 3];
        Wv   = (const float*)d_in[wb + 4];
        bv   = (const float*)d_in[wb + 5];
        Wm   = (const float*)d_in[wb + 6];
        bm   = (const float*)d_in[wb + 7];
        Wbox = (const float*)d_in[wb + 8];
        bbox = (const float*)d_in[wb + 9];
    } else {
        Wbox = (const float*)d_in[0];
        Wk   = (const float*)d_in[1];
        Wm   = (const float*)d_in[2];
        Wq   = (const float*)d_in[3];
        Wv   = (const float*)d_in[4];
        bbox = (const float*)d_in[5];
        bk   = (const float*)d_in[6];
        bm   = (const float*)d_in[7];
        bq   = (const float*)d_in[8];
        bv   = (const float*)d_in[9];
        box  = (const float*)d_in[10];
        int idx = 11;
        if (idx < n_in && in_sizes[idx] == 1) idx++;
        k    = (const float*)d_in[idx + 0];
        mask = d_in[idx + 1];
        q    = (const float*)d_in[idx + 2];
        v    = (const float*)d_in[idx + 3];
    }

    const size_t ATTED_ELEMS = (size_t)BB * NN * DM;
    const size_t POS_ELEMS   = (size_t)BB * NH * NN * NN;
    float* out = (float*)d_out;

    float *posA, *attA;
    bf16 *ahA, *alA, *whA, *wlA;
    bf16 *qhhA, *qhlA, *khhA, *khlA, *vhhA, *vhlA;
    cudaGetSymbolAddress((void**)&attA, g_att);
    cudaGetSymbolAddress((void**)&posA, g_pos);
    cudaGetSymbolAddress((void**)&ahA,  g_ah);
    cudaGetSymbolAddress((void**)&alA,  g_al);
    cudaGetSymbolAddress((void**)&whA,  g_wh);
    cudaGetSymbolAddress((void**)&wlA,  g_wl);
    cudaGetSymbolAddress((void**)&qhhA, g_qhh);
    cudaGetSymbolAddress((void**)&qhlA, g_qhl);
    cudaGetSymbolAddress((void**)&khhA, g_khh);
    cudaGetSymbolAddress((void**)&khlA, g_khl);
    cudaGetSymbolAddress((void**)&vhhA, g_vhh);
    cudaGetSymbolAddress((void**)&vhlA, g_vhl);

    float* atted;
    float* pos_out;
    if ((size_t)out_size >= ATTED_ELEMS + POS_ELEMS) {
        atted   = out;
        pos_out = out + ATTED_ELEMS;
    } else if ((size_t)out_size == POS_ELEMS) {
        pos_out = out;
        atted   = attA;
    } else {
        atted   = out;
        pos_out = posA;
    }

    detect_mask_kind<<<1, 256>>>((const unsigned int*)mask);

    cudaFuncSetAttribute(gemm_tc,
                         cudaFuncAttributeMaxDynamicSharedMemorySize, 65536);
    cudaFuncSetAttribute(attn_tc,
                         cudaFuncAttributeMaxDynamicSharedMemorySize, 65536);

    const int SPLIT_BLKS = (BB * NN * DM) / (4 * 256);   // 4096
    dim3 gt(4, 64);

    // Q projection -> bf16 head-split
    split_T<<<1024, 256>>>(Wq, whA, wlA);
    split_lin<<<SPLIT_BLKS, 256>>>(q, ahA, alA);
    gemm_tc<<<gt, 256, 65536>>>(ahA, alA, whA, wlA, bq, nullptr, qhhA, qhlA, 1);
    // K projection
    split_T<<<1024, 256>>>(Wk, whA, wlA);
    split_lin<<<SPLIT_BLKS, 256>>>(k, ahA, alA);
    gemm_tc<<<gt, 256, 65536>>>(ahA, alA, whA, wlA, bk, nullptr, khhA, khlA, 1);
    // V projection
    split_T<<<1024, 256>>>(Wv, whA, wlA);
    split_lin<<<SPLIT_BLKS, 256>>>(v, ahA, alA);
    gemm_tc<<<gt, 256, 65536>>>(ahA, alA, whA, wlA, bv, nullptr, vhhA, vhlA, 1);

    pos_kernel<<<dim3(NN, BB), 256>>>(box, Wbox, bbox, pos_out);

    attn_tc<<<BB * NH * 8, 256, AT_TOT>>>(mask, pos_out);

    // Output projection
    split_T<<<1024, 256>>>(Wm, whA, wlA);
    split_lin<<<SPLIT_BLKS, 256>>>(attA, ahA, alA);
    gemm_tc<<<gt, 256, 65536>>>(ahA, alA, whA, wlA, bm, atted, nullptr, nullptr, 0);
}

// round 11
// speedup vs baseline: 2.1716x; 1.0320x over previous
#include <cuda_runtime.h>
#include <cuda_bf16.h>
#include <cstdint>
#include <cstddef>

// Problem constants
#define BB   32
#define NN   256
#define DM   512
#define NH   8
#define DH   64

typedef unsigned long long ull;
typedef __nv_bfloat16 bf16;

// Scratch (allocation-free rule: __device__ globals)
__device__ float g_pos[BB*NH*NN*NN];  // pos_scores fallback when d_out lacks room
__device__ bf16  g_ah[BB*NN*DM];      // attn output hi split (A of final gemm)
__device__ bf16  g_al[BB*NN*DM];      // attn output lo split
__device__ bf16  g_aqh[3*BB*NN*DM];   // q,k,v input hi splits (3 slabs)
__device__ bf16  g_aql[3*BB*NN*DM];   // q,k,v input lo splits
__device__ bf16  g_wh4[4*DM*DM];      // W^T hi splits: Wq,Wk,Wv,Wm slabs
__device__ bf16  g_wl4[4*DM*DM];
__device__ bf16  g_qhh[BB*NH*NN*DH], g_qhl[BB*NH*NN*DH];  // Q heads hi/lo
__device__ bf16  g_khh[BB*NH*NN*DH], g_khl[BB*NH*NN*DH];  // K heads hi/lo
__device__ bf16  g_vhh[BB*NH*NN*DH], g_vhl[BB*NH*NN*DH];  // V heads hi/lo
__device__ int   g_mask_kind;         // 0=int32, 1=float32, 2=byte

// ---- HMMA helpers (baseline PTX, not 'a'-gated) ----
__device__ __forceinline__ uint32_t smem_u32(const void* p) {
    uint32_t a;
    asm("{ .reg .u64 t; cvta.to.shared.u64 t, %1; cvt.u32.u64 %0, t; }"
        : "=r"(a) : "l"(p));
    return a;
}
__device__ __forceinline__ void mma16816(float* c, const uint32_t* a,
                                         const uint32_t* b) {
    asm volatile(
        "mma.sync.aligned.m16n8k16.row.col.f32.bf16.bf16.f32 "
        "{%0,%1,%2,%3}, {%4,%5,%6,%7}, {%8,%9}, {%0,%1,%2,%3};"
        : "+f"(c[0]), "+f"(c[1]), "+f"(c[2]), "+f"(c[3])
        : "r"(a[0]), "r"(a[1]), "r"(a[2]), "r"(a[3]), "r"(b[0]), "r"(b[1]));
}
__device__ __forceinline__ void ldmA(uint32_t* r, uint32_t addr) {
    asm volatile("ldmatrix.sync.aligned.m8n8.x4.shared.b16 {%0,%1,%2,%3}, [%4];"
        : "=r"(r[0]), "=r"(r[1]), "=r"(r[2]), "=r"(r[3]) : "r"(addr));
}
__device__ __forceinline__ void ldmB(uint32_t* r, uint32_t addr) {
    asm volatile("ldmatrix.sync.aligned.m8n8.x4.shared.b16 {%0,%1,%2,%3}, [%4];"
        : "=r"(r[0]), "=r"(r[1]), "=r"(r[2]), "=r"(r[3]) : "r"(addr));
}
// trans variant: [k][n]-stored data -> b-fragment (V tiles)
__device__ __forceinline__ void ldmVT(uint32_t* r, uint32_t addr) {
    asm volatile("ldmatrix.sync.aligned.m8n8.x4.trans.shared.b16 {%0,%1,%2,%3}, [%4];"
        : "=r"(r[0]), "=r"(r[1]), "=r"(r[2]), "=r"(r[3]) : "r"(addr));
}
// gemm smem: 64B rows, 4x16B chunks
__device__ __forceinline__ int swz(int row, int ch) {
    return row * 64 + ((ch ^ ((row >> 1) & 3)) << 4);
}
// attn smem: 128B rows (64 bf16), 8x16B chunks
__device__ __forceinline__ int swz128(int row, int ch) {
    return row * 128 + ((ch ^ (row & 7)) << 4);
}
// P smem: 512B rows (256 bf16), 32x16B chunks
__device__ __forceinline__ int swzP(int row, int ch) {
    return row * 512 + ((ch ^ (row & 7)) << 4);
}
// ---- cp.async (Ampere-baseline) ----
__device__ __forceinline__ void cpa16(uint32_t dst, const void* src) {
    asm volatile("cp.async.cg.shared.global [%0], [%1], 16;"
                 :: "r"(dst), "l"(src) : "memory");
}
__device__ __forceinline__ void cpa_commit() {
    asm volatile("cp.async.commit_group;" ::: "memory");
}
__device__ __forceinline__ void split2(float x, bf16& h, bf16& l) {
    h = __float2bfloat16(x);
    l = __float2bfloat16(x - __bfloat162float(h));
}

// ---------------------------------------------------------------------------
// Mask dtype sniffing (bool may arrive as u8/i32/f32).
// ---------------------------------------------------------------------------
__global__ void detect_mask_kind(const unsigned int* __restrict__ m) {
    __shared__ int oki, okf;
    if (threadIdx.x == 0) { oki = 1; okf = 1; }
    __syncthreads();
    for (int idx = threadIdx.x; idx < 2048; idx += 256) {
        unsigned int w = m[idx];
        if (w > 1u) oki = 0;
        if (w != 0u && w != 0x3F800000u) okf = 0;
    }
    __syncthreads();
    if (threadIdx.x == 0) g_mask_kind = oki ? 0 : (okf ? 1 : 2);
}

// ---------------------------------------------------------------------------
// Split q,k,v (3 x 4M fp32) -> bf16 hi/lo slabs. grid 12288 x 256, float4.
// ---------------------------------------------------------------------------
__global__ void split_qkv(const float* __restrict__ q,
                          const float* __restrict__ k,
                          const float* __restrict__ v,
                          bf16* __restrict__ hi, bf16* __restrict__ lo) {
    int gi = blockIdx.x * 256 + threadIdx.x;       // 0 .. 3M-1 (float4 slots)
    const int SLAB4 = BB * NN * DM / 4;            // 1M float4 per slab
    int slab = gi / SLAB4;
    int r4 = gi - slab * SLAB4;
    const float* src = (slab == 0) ? q : (slab == 1) ? k : v;
    int i = r4 * 4;
    float4 x = *(const float4*)(src + i);
    bf16 h0, l0, h1, l1, h2, l2, h3, l3;
    split2(x.x, h0, l0); split2(x.y, h1, l1);
    split2(x.z, h2, l2); split2(x.w, h3, l3);
    size_t o = (size_t)slab * (BB * NN * DM) + i;
    *(__nv_bfloat162*)(hi + o)     = __nv_bfloat162(h0, h1);
    *(__nv_bfloat162*)(hi + o + 2) = __nv_bfloat162(h2, h3);
    *(__nv_bfloat162*)(lo + o)     = __nv_bfloat162(l0, l1);
    *(__nv_bfloat162*)(lo + o + 2) = __nv_bfloat162(l2, l3);
}

// ---------------------------------------------------------------------------
// Split + transpose all 4 weights [k][n] -> [n][k] hi/lo slabs. grid 4096x256.
// ---------------------------------------------------------------------------
__global__ void split_w4(const float* __restrict__ W0,
                         const float* __restrict__ W1,
                         const float* __restrict__ W2,
                         const float* __restrict__ W3,
                         bf16* __restrict__ hi, bf16* __restrict__ lo) {
    int gi = blockIdx.x * 256 + threadIdx.x;       // 0 .. 1M-1
    int w = gi >> 18, r = gi & 0x3FFFF;
    int k = r >> 9, n = r & 511;
    const float* W = (w == 0) ? W0 : (w == 1) ? W1 : (w == 2) ? W2 : W3;
    float x = W[r];
    bf16 h, l; split2(x, h, l);
    size_t o = (size_t)w * (DM * DM) + n * 512 + k;
    hi[o] = h;  lo[o] = l;
}

// ---------------------------------------------------------------------------
// HMMA GEMM body: cp.async 2-stage pipeline. CTA 128x128, 8 warps, BK=32.
// mode 0: fp32 row-major C.  mode 1: bf16 hi/lo head-split [B,H,N,DH].
// ---------------------------------------------------------------------------
__device__ __forceinline__ void issue_tile(
    uint32_t bs, int kn, int m0, int n0, int lr, int lr1, int lch,
    int so0, int so1,
    const bf16* __restrict__ Ah, const bf16* __restrict__ Al,
    const bf16* __restrict__ Bh, const bf16* __restrict__ Bl) {
    size_t ga0 = (size_t)(m0 + lr)  * 512 + kn + lch * 8;
    size_t ga1 = (size_t)(m0 + lr1) * 512 + kn + lch * 8;
    size_t gb0 = (size_t)(n0 + lr)  * 512 + kn + lch * 8;
    size_t gb1 = (size_t)(n0 + lr1) * 512 + kn + lch * 8;
    cpa16(bs +         so0, Ah + ga0);  cpa16(bs +         so1, Ah + ga1);
    cpa16(bs +  8192 + so0, Al + ga0);  cpa16(bs +  8192 + so1, Al + ga1);
    cpa16(bs + 16384 + so0, Bh + gb0);  cpa16(bs + 16384 + so1, Bh + gb1);
    cpa16(bs + 24576 + so0, Bl + gb0);  cpa16(bs + 24576 + so1, Bl + gb1);
    cpa_commit();
}

__device__ __forceinline__ void gemm_body(
    char* dsm, const bf16* __restrict__ Ah, const bf16* __restrict__ Al,
    const bf16* __restrict__ BhT, const bf16* __restrict__ BlT,
    const float* __restrict__ bias, float* __restrict__ C,
    bf16* __restrict__ Chi, bf16* __restrict__ Clo, int mode,
    int m0, int n0) {
    const uint32_t sb = smem_u32(dsm);
    const int tid = threadIdx.x, wid = tid >> 5, lane = tid & 31;
    const int wm = wid >> 2, wn = wid & 3;
    const int lr = tid >> 2, lch = tid & 3, lr1 = lr + 64;
    const int so0 = swz(lr, lch), so1 = swz(lr1, lch);

    float acc[4][4][4];
    #pragma unroll
    for (int i = 0; i < 4; i++)
        #pragma unroll
        for (int j = 0; j < 4; j++)
            #pragma unroll
            for (int t = 0; t < 4; t++) acc[i][j][t] = 0.f;

    issue_tile(sb, 0, m0, n0, lr, lr1, lch, so0, so1, Ah, Al, BhT, BlT);

    for (int c = 0; c < 16; c++) {
        if (c + 1 < 16) {
            issue_tile(sb + ((c + 1) & 1) * 32768, (c + 1) * 32,
                       m0, n0, lr, lr1, lch, so0, so1, Ah, Al, BhT, BlT);
            asm volatile("cp.async.wait_group %0;" :: "n"(1) : "memory");
        } else {
            asm volatile("cp.async.wait_group %0;" :: "n"(0) : "memory");
        }
        __syncthreads();

        const uint32_t bs = sb + (c & 1) * 32768;
        const uint32_t sbAh = bs, sbAl = bs + 8192;
        const uint32_t sbWh = bs + 16384, sbWl = bs + 24576;

        #pragma unroll
        for (int ks = 0; ks < 2; ks++) {
            const int arow = wm * 64 + (lane & 7) + ((lane >> 3) & 1) * 8;
            const int akch = ks * 2 + ((lane >> 4) & 1);
            const int nrow = wn * 32 + (lane & 7) + ((lane >> 4) & 1) * 8;
            const int nkch = ks * 2 + ((lane >> 3) & 1);

            uint32_t whf[2][4], wlf[2][4], af[4][4];
            #pragma unroll
            for (int g = 0; g < 2; g++) {
                ldmB(whf[g], sbWh + swz(nrow + g * 16, nkch));
                ldmB(wlf[g], sbWl + swz(nrow + g * 16, nkch));
            }
            #pragma unroll
            for (int mt = 0; mt < 4; mt++)
                ldmA(af[mt], sbAh + swz(arow + mt * 16, akch));
            #pragma unroll
            for (int mt = 0; mt < 4; mt++)
                #pragma unroll
                for (int nt = 0; nt < 4; nt++) {
                    mma16816(acc[mt][nt], af[mt], &whf[nt >> 1][(nt & 1) * 2]);
                    mma16816(acc[mt][nt], af[mt], &wlf[nt >> 1][(nt & 1) * 2]);
                }
            #pragma unroll
            for (int mt = 0; mt < 4; mt++)
                ldmA(af[mt], sbAl + swz(arow + mt * 16, akch));
            #pragma unroll
            for (int mt = 0; mt < 4; mt++)
                #pragma unroll
                for (int nt = 0; nt < 4; nt++)
                    mma16816(acc[mt][nt], af[mt], &whf[nt >> 1][(nt & 1) * 2]);
        }
        __syncthreads();
    }

    // ---- epilogue ----
    #pragma unroll
    for (int mt = 0; mt < 4; mt++) {
        int row = m0 + wm * 64 + mt * 16 + (lane >> 2);
        #pragma unroll
        for (int nt = 0; nt < 4; nt++) {
            int col = n0 + wn * 32 + nt * 8 + (lane & 3) * 2;
            float b0 = __ldg(&bias[col]), b1 = __ldg(&bias[col + 1]);
            float2 v0 = make_float2(acc[mt][nt][0] + b0, acc[mt][nt][1] + b1);
            float2 v1 = make_float2(acc[mt][nt][2] + b0, acc[mt][nt][3] + b1);
            if (mode == 1) {
                int h = col >> 6, d = col & 63;
                #pragma unroll
                for (int half = 0; half < 2; half++) {
                    float2 v = half ? v1 : v0;
                    int rr = row + half * 8;
                    int b = rr >> 8, n = rr & 255;
                    size_t base = (((size_t)b * NH + h) * NN + n) * DH + d;
                    bf16 h0, l0, h1, l1;
                    split2(v.x, h0, l0); split2(v.y, h1, l1);
                    *(__nv_bfloat162*)&Chi[base] = __nv_bfloat162(h0, h1);
                    *(__nv_bfloat162*)&Clo[base] = __nv_bfloat162(l0, l1);
                }
            } else {
                *(float2*)(C + (size_t)row * DM + col) = v0;
                *(float2*)(C + (size_t)(row + 8) * DM + col) = v1;
            }
        }
    }
}

// Batched Q/K/V projection: blockIdx.z selects projection.
__global__ void __launch_bounds__(256, 2)
gemm_qkv(const bf16* __restrict__ Aqh, const bf16* __restrict__ Aql,
         const bf16* __restrict__ Wh4, const bf16* __restrict__ Wl4,
         const float* __restrict__ bq, const float* __restrict__ bk,
         const float* __restrict__ bv,
         bf16* __restrict__ Qhh, bf16* __restrict__ Qhl,
         bf16* __restrict__ Khh, bf16* __restrict__ Khl,
         bf16* __restrict__ Vhh, bf16* __restrict__ Vhl) {
    extern __shared__ char dsm[];
    const int z = blockIdx.z;
    const size_t aoff = (size_t)z * (BB * NN * DM);
    const size_t woff = (size_t)z * (DM * DM);
    const float* bias = (z == 0) ? bq : (z == 1) ? bk : bv;
    bf16* Chi = (z == 0) ? Qhh : (z == 1) ? Khh : Vhh;
    bf16* Clo = (z == 0) ? Qhl : (z == 1) ? Khl : Vhl;
    gemm_body(dsm, Aqh + aoff, Aql + aoff, Wh4 + woff, Wl4 + woff,
              bias, nullptr, Chi, Clo, 1, blockIdx.y * 128, blockIdx.x * 128);
}

// Output projection (mode 0, Wm = slab 3).
__global__ void __launch_bounds__(256, 2)
gemm_out(const bf16* __restrict__ Ah, const bf16* __restrict__ Al,
         const bf16* __restrict__ Wh4, const bf16* __restrict__ Wl4,
         const float* __restrict__ bias, float* __restrict__ C) {
    extern __shared__ char dsm[];
    gemm_body(dsm, Ah, Al, Wh4 + (size_t)3 * DM * DM, Wl4 + (size_t)3 * DM * DM,
              bias, C, nullptr, nullptr, 0, blockIdx.y * 128, blockIdx.x * 128);
}

// ---------------------------------------------------------------------------
// Geometric positional bias (unchanged).
// ---------------------------------------------------------------------------
__global__ void pos_kernel(const float* __restrict__ box,
                           const float* __restrict__ Wbox,
                           const float* __restrict__ bbox,
                           float* __restrict__ pos_out) {
    __shared__ float scx[NN], scy[NN], slw[NN], slh[NN];
    __shared__ float wb[65];
    const int b = blockIdx.y, i = blockIdx.x;
    const int j = threadIdx.x;

    {
        const float* bj = box + ((size_t)b * NN + j) * 4;
        float x0 = bj[0], y0 = bj[1], x1 = bj[2], y1 = bj[3];
        scx[j] = 0.5f * (x0 + x1);
        scy[j] = 0.5f * (y0 + y1);
        slw[j] = __logf(x1 - x0 + 1.0f);
        slh[j] = __logf(y1 - y0 + 1.0f);
    }
    if (j < 64) wb[j] = Wbox[j];
    if (j == 0) wb[64] = bbox[0];
    __syncthreads();

    const float* bi = box + ((size_t)b * NN + i) * 4;
    float xi0 = bi[0], yi0 = bi[1], xi1 = bi[2], yi1 = bi[3];
    float cxi = 0.5f * (xi0 + xi1), cyi = 0.5f * (yi0 + yi1);
    float wi = xi1 - xi0 + 1.0f, hi = yi1 - yi0 + 1.0f;
    float invw = 1.0f / wi, invh = 1.0f / hi;
    float lwi = __logf(wi), lhi = __logf(hi);

    float p0 = __logf(fmaxf(fabsf((cxi - scx[j]) * invw), 1e-3f));
    float p1 = __logf(fmaxf(fabsf((cyi - scy[j]) * invh), 1e-3f));
    float p2 = lwi - slw[j];
    float p3 = lhi - slh[j];

    const float dm[8] = {1.0f, 0.42169651f, 0.17782794f, 0.074989423f,
                         0.031622777f, 0.013335214f, 0.0056234132f, 0.0023713737f};
    float pc[4] = {100.f * p0, 100.f * p1, 100.f * p2, 100.f * p3};

    float s = wb[64];
    #pragma unroll
    for (int c = 0; c < 4; c++) {
        #pragma unroll
        for (int f = 0; f < 8; f++) {
            float m = pc[c] * dm[f];
            float sn, cs;
            __sincosf(m, &sn, &cs);
            s = fmaf(sn, wb[c * 8 + f], s);
            s = fmaf(cs, wb[32 + c * 8 + f], s);
        }
    }
    float ps = fmaxf(s, 0.f);

    size_t base = (size_t)b * NH * NN * NN + (size_t)i * NN + j;
    #pragma unroll
    for (int hh = 0; hh < NH; hh++)
        pos_out[base + (size_t)hh * NN * NN] = ps;
}

// ---------------------------------------------------------------------------
// HMMA attention per (b, h, 32-q tile). bf16-split QK^T and PV via mma.sync.
// Epilogue writes O as bf16 hi/lo directly into final-gemm A buffers.
// ---------------------------------------------------------------------------
#define AT_SQH 0
#define AT_SQL 4096
#define AT_SKH 8192
#define AT_SKL 16384
#define AT_S   24576
#define AT_PHI 24576
#define AT_PLO 40960
#define AT_MR  58368
#define AT_TOT 58624

__global__ void __launch_bounds__(256, 2)
attn_tc(const void* __restrict__ maskp, const float* __restrict__ pos,
        bf16* __restrict__ Oh, bf16* __restrict__ Ol) {
    extern __shared__ char sm8[];
    const uint32_t sb = smem_u32(sm8);
    float* S = (float*)(sm8 + AT_S);
    unsigned char* mrow = (unsigned char*)(sm8 + AT_MR);

    const int blk = blockIdx.x;
    const int qt = blk & 7, h = (blk >> 3) & 7, b = blk >> 6;
    const int tid = threadIdx.x, wid = tid >> 5, lane = tid & 31;
    const int wm = wid >> 2, wn = wid & 3;          // 2 x 4 warp grid
    const int q0 = qt * 32;
    const int kind = g_mask_kind;

    {
        int idx = b * NN + tid;
        bool mv;
        if (kind == 0)      mv = ((const int*)maskp)[idx] != 0;
        else if (kind == 1) mv = ((const float*)maskp)[idx] != 0.0f;
        else                mv = ((const unsigned char*)maskp)[idx] != 0;
        mrow[tid] = mv ? 1 : 0;
    }

    const size_t hb = ((size_t)b * NH + h) * NN;
    const bf16* Qh = g_qhh + (hb + q0) * DH;
    const bf16* Ql = g_qhl + (hb + q0) * DH;
    const bf16* Kh = g_khh + hb * DH;
    const bf16* Kl = g_khl + hb * DH;
    const bf16* Vh = g_vhh + hb * DH;
    const bf16* Vl = g_vhl + hb * DH;

    {
        int row = tid >> 3, ch = tid & 7;
        *(uint4*)(sm8 + AT_SQH + swz128(row, ch)) = *(const uint4*)(Qh + row * 64 + ch * 8);
        *(uint4*)(sm8 + AT_SQL + swz128(row, ch)) = *(const uint4*)(Ql + row * 64 + ch * 8);
    }
    const float* prow = pos + (size_t)b * (NH * NN * NN) + (size_t)q0 * NN;

    // ---- S = scale * Q K^T + pos, masked (HMMA) ----
    for (int kb = 0; kb < 4; kb++) {
        if (kb) __syncthreads();
        #pragma unroll
        for (int t = 0; t < 2; t++) {
            int idx = t * 256 + tid;
            int row = idx >> 3, ch = idx & 7;
            const bf16* src = Kh + (size_t)(kb * 64 + row) * 64 + ch * 8;
            const bf16* srl = Kl + (size_t)(kb * 64 + row) * 64 + ch * 8;
            *(uint4*)(sm8 + AT_SKH + swz128(row, ch)) = *(const uint4*)src;
            *(uint4*)(sm8 + AT_SKL + swz128(row, ch)) = *(const uint4*)srl;
        }
        __syncthreads();

        float acc[2][4] = {{0.f,0.f,0.f,0.f},{0.f,0.f,0.f,0.f}};
        #pragma unroll
        for (int ks = 0; ks < 4; ks++) {
            const int arow = wm * 16 + (lane & 7) + ((lane >> 3) & 1) * 8;
            const int akch = ks * 2 + ((lane >> 4) & 1);
            const int nrow = wn * 16 + (lane & 7) + ((lane >> 4) & 1) * 8;
            const int nkch = ks * 2 + ((lane >> 3) & 1);
            uint32_t aH[4], aL[4], bH[4], bL[4];
            ldmA(aH, sb + AT_SQH + swz128(arow, akch));
            ldmA(aL, sb + AT_SQL + swz128(arow, akch));
            ldmB(bH, sb + AT_SKH + swz128(nrow, nkch));
            ldmB(bL, sb + AT_SKL + swz128(nrow, nkch));
            #pragma unroll
            for (int nt = 0; nt < 2; nt++) {
                mma16816(acc[nt], aH, bH + nt * 2);
                mma16816(acc[nt], aH, bL + nt * 2);
                mma16816(acc[nt], aL, bH + nt * 2);
            }
        }
        #pragma unroll
        for (int nt = 0; nt < 2; nt++) {
            int col = kb * 64 + wn * 16 + nt * 8 + (lane & 3) * 2;
            #pragma unroll
            for (int half = 0; half < 2; half++) {
                int r = wm * 16 + (lane >> 2) + half * 8;
                float a0 = acc[nt][half * 2 + 0], a1 = acc[nt][half * 2 + 1];
                float v0 = mrow[col]     ? -1e9f : fmaf(a0, 0.125f, prow[r * NN + col]);
                float v1 = mrow[col + 1] ? -1e9f : fmaf(a1, 0.125f, prow[r * NN + col + 1]);
                S[r * 264 + col]     = v0;
                S[r * 264 + col + 1] = v1;
            }
        }
    }
    __syncthreads();

    // ---- softmax: 8 lanes per row ----
    {
        int row = tid >> 3, sub = tid & 7;
        float* Sr = S + row * 264;
        float mx = -3.4e38f;
        #pragma unroll
        for (int t = 0; t < 32; t++) mx = fmaxf(mx, Sr[sub + t * 8]);
        #pragma unroll
        for (int o = 4; o > 0; o >>= 1)
            mx = fmaxf(mx, __shfl_xor_sync(0xffffffffu, mx, o));
        float ssum = 0.f;
        #pragma unroll
        for (int t = 0; t < 32; t++) {
            float e = __expf(Sr[sub + t * 8] - mx);
            Sr[sub + t * 8] = e;
            ssum += e;
        }
        #pragma unroll
        for (int o = 4; o > 0; o >>= 1)
            ssum += __shfl_xor_sync(0xffffffffu, ssum, o);
        float inv = 1.0f / ssum;
        #pragma unroll
        for (int t = 0; t < 32; t++) Sr[sub + t * 8] *= inv;
    }
    __syncthreads();

    // ---- convert P (fp32 S) -> bf16 hi/lo, overlaid on S region ----
    {
        int row = tid >> 3, cb = (tid & 7) * 4;
        float tmp[32];
        #pragma unroll
        for (int c4 = 0; c4 < 4; c4++)
            #pragma unroll
            for (int e = 0; e < 8; e++)
                tmp[c4 * 8 + e] = S[row * 264 + (cb + c4) * 8 + e];
        __syncthreads();
        #pragma unroll
        for (int c4 = 0; c4 < 4; c4++) {
            uint32_t hi4[4], lo4[4];
            #pragma unroll
            for (int p = 0; p < 4; p++) {
                float x0 = tmp[c4 * 8 + p * 2], x1 = tmp[c4 * 8 + p * 2 + 1];
                bf16 h0, l0, h1, l1;
                split2(x0, h0, l0); split2(x1, h1, l1);
                __nv_bfloat162 hp(h0, h1), lp(l0, l1);
                hi4[p] = *(uint32_t*)&hp;
                lo4[p] = *(uint32_t*)&lp;
            }
            *(uint4*)(sm8 + AT_PHI + swzP(row, cb + c4)) = make_uint4(hi4[0], hi4[1], hi4[2], hi4[3]);
            *(uint4*)(sm8 + AT_PLO + swzP(row, cb + c4)) = make_uint4(lo4[0], lo4[1], lo4[2], lo4[3]);
        }
    }

    // ---- O = P V (HMMA, V via ldmatrix.trans) ----
    float oacc[2][4] = {{0.f,0.f,0.f,0.f},{0.f,0.f,0.f,0.f}};
    for (int kb = 0; kb < 4; kb++) {
        __syncthreads();
        #pragma unroll
        for (int t = 0; t < 2; t++) {
            int idx = t * 256 + tid;
            int row = idx >> 3, ch = idx & 7;
            const bf16* src = Vh + (size_t)(kb * 64 + row) * 64 + ch * 8;
            const bf16* srl = Vl + (size_t)(kb * 64 + row) * 64 + ch * 8;
            *(uint4*)(sm8 + AT_SKH + swz128(row, ch)) = *(const uint4*)src;
            *(uint4*)(sm8 + AT_SKL + swz128(row, ch)) = *(const uint4*)srl;
        }
        __syncthreads();
        #pragma unroll
        for (int ks = 0; ks < 4; ks++) {
            const int arow = wm * 16 + (lane & 7) + ((lane >> 3) & 1) * 8;
            const int akch = kb * 8 + ks * 2 + ((lane >> 4) & 1);
            const int vrow = ks * 16 + (lane & 7) + ((lane >> 3) & 1) * 8;
            const int vch  = wn * 2 + ((lane >> 4) & 1);
            uint32_t pH[4], pL[4], vH[4], vL[4];
            ldmA(pH, sb + AT_PHI + swzP(arow, akch));
            ldmA(pL, sb + AT_PLO + swzP(arow, akch));
            ldmVT(vH, sb + AT_SKH + swz128(vrow, vch));
            ldmVT(vL, sb + AT_SKL + swz128(vrow, vch));
            #pragma unroll
            for (int nt = 0; nt < 2; nt++) {
                mma16816(oacc[nt], pH, vH + nt * 2);
                mma16816(oacc[nt], pH, vL + nt * 2);
                mma16816(oacc[nt], pL, vH + nt * 2);
            }
        }
    }

    // ---- store O directly as bf16 hi/lo (A of output projection) ----
    #pragma unroll
    for (int nt = 0; nt < 2; nt++) {
        int dcol = h * 64 + wn * 16 + nt * 8 + (lane & 3) * 2;
        #pragma unroll
        for (int half = 0; half < 2; half++) {
            int drow = q0 + wm * 16 + (lane >> 2) + half * 8;
            float x0 = oacc[nt][half * 2], x1 = oacc[nt][half * 2 + 1];
            bf16 h0, l0, h1, l1;
            split2(x0, h0, l0); split2(x1, h1, l1);
            size_t base = ((size_t)b * NN + drow) * DM + dcol;
            *(__nv_bfloat162*)&Oh[base] = __nv_bfloat162(h0, h1);
            *(__nv_bfloat162*)&Ol[base] = __nv_bfloat162(l0, l1);
        }
    }
}

// ---------------------------------------------------------------------------
extern "C" void kernel_launch(void* const* d_in, const int* in_sizes, int n_in,
                              void* d_out, int out_size) {
    const float *v, *k, *q, *box, *Wq, *bq, *Wk, *bk, *Wv, *bv, *Wm, *bm, *Wbox, *bbox;
    const void* mask;

    if (in_sizes[0] == BB * NN * DM) {
        v    = (const float*)d_in[0];
        k    = (const float*)d_in[1];
        q    = (const float*)d_in[2];
        box  = (const float*)d_in[3];
        mask = d_in[4];
        int wb = 5;
        for (int i = 5; i < n_in; i++) {
            if (in_sizes[i] == DM * DM) { wb = i; break; }
        }
        Wq   = (const float*)d_in[wb + 0];
        bq   = (const float*)d_in[wb + 1];
        Wk   = (const float*)d_in[wb + 2];
        bk   = (const float*)d_in[wb + 3];
        Wv   = (const float*)d_in[wb + 4];
        bv   = (const float*)d_in[wb + 5];
        Wm   = (const float*)d_in[wb + 6];
        bm   = (const float*)d_in[wb + 7];
        Wbox = (const float*)d_in[wb + 8];
        bbox = (const float*)d_in[wb + 9];
    } else {
        Wbox = (const float*)d_in[0];
        Wk   = (const float*)d_in[1];
        Wm   = (const float*)d_in[2];
        Wq   = (const float*)d_in[3];
        Wv   = (const float*)d_in[4];
        bbox = (const float*)d_in[5];
        bk   = (const float*)d_in[6];
        bm   = (const float*)d_in[7];
        bq   = (const float*)d_in[8];
        bv   = (const float*)d_in[9];
        box  = (const float*)d_in[10];
        int idx = 11;
        if (idx < n_in && in_sizes[idx] == 1) idx++;
        k    = (const float*)d_in[idx + 0];
        mask = d_in[idx + 1];
        q    = (const float*)d_in[idx + 2];
        v    = (const float*)d_in[idx + 3];
    }

    const size_t ATTED_ELEMS = (size_t)BB * NN * DM;
    const size_t POS_ELEMS   = (size_t)BB * NH * NN * NN;
    float* out = (float*)d_out;

    float *posA;
    bf16 *ahA, *alA, *aqhA, *aqlA, *wh4A, *wl4A;
    bf16 *qhhA, *qhlA, *khhA, *khlA, *vhhA, *vhlA;
    cudaGetSymbolAddress((void**)&posA, g_pos);
    cudaGetSymbolAddress((void**)&ahA,  g_ah);
    cudaGetSymbolAddress((void**)&alA,  g_al);
    cudaGetSymbolAddress((void**)&aqhA, g_aqh);
    cudaGetSymbolAddress((void**)&aqlA, g_aql);
    cudaGetSymbolAddress((void**)&wh4A, g_wh4);
    cudaGetSymbolAddress((void**)&wl4A, g_wl4);
    cudaGetSymbolAddress((void**)&qhhA, g_qhh);
    cudaGetSymbolAddress((void**)&qhlA, g_qhl);
    cudaGetSymbolAddress((void**)&khhA, g_khh);
    cudaGetSymbolAddress((void**)&khlA, g_khl);
    cudaGetSymbolAddress((void**)&vhhA, g_vhh);
    cudaGetSymbolAddress((void**)&vhlA, g_vhl);

    float* atted;
    float* pos_out;
    static float s_dummy_att[1];  // never used when out has room
    if ((size_t)out_size >= ATTED_ELEMS + POS_ELEMS) {
        atted   = out;
        pos_out = out + ATTED_ELEMS;
    } else if ((size_t)out_size == POS_ELEMS) {
        pos_out = out;
        atted   = posA;            // scratch sink (unused result)
    } else {
        atted   = out;
        pos_out = posA;
    }

    detect_mask_kind<<<1, 256>>>((const unsigned int*)mask);

    cudaFuncSetAttribute(gemm_qkv,
                         cudaFuncAttributeMaxDynamicSharedMemorySize, 65536);
    cudaFuncSetAttribute(gemm_out,
                         cudaFuncAttributeMaxDynamicSharedMemorySize, 65536);
    cudaFuncSetAttribute(attn_tc,
                         cudaFuncAttributeMaxDynamicSharedMemorySize, 65536);

    // Upfront splits: all 4 weights, then q/k/v inputs
    split_w4<<<4096, 256>>>(Wq, Wk, Wv, Wm, wh4A, wl4A);
    split_qkv<<<3 * (BB * NN * DM) / (4 * 256), 256>>>(q, k, v, aqhA, aqlA);

    // Batched Q/K/V projections
    gemm_qkv<<<dim3(4, 64, 3), 256, 65536>>>(aqhA, aqlA, wh4A, wl4A,
                                             bq, bk, bv,
                                             qhhA, qhlA, khhA, khlA, vhhA, vhlA);

    pos_kernel<<<dim3(NN, BB), 256>>>(box, Wbox, bbox, pos_out);

    // Attention writes bf16 hi/lo A for the output projection directly
    attn_tc<<<BB * NH * 8, 256, AT_TOT>>>(mask, pos_out, ahA, alA);

    // Output projection
    gemm_out<<<dim3(4, 64), 256, 65536>>>(ahA, alA, wh4A, wl4A, bm, atted);
}

// round 12
// speedup vs baseline: 2.3365x; 1.0759x over previous
#include <cuda_runtime.h>
#include <cuda_bf16.h>
#include <cstdint>
#include <cstddef>

// Problem constants
#define BB   32
#define NN   256
#define DM   512
#define NH   8
#define DH   64

typedef unsigned long long ull;
typedef __nv_bfloat16 bf16;

// Scratch (allocation-free rule: __device__ globals)
__device__ float g_pos[BB*NH*NN*NN];  // pos_scores fallback when d_out lacks room
__device__ bf16  g_ah[BB*NN*DM];      // attn output hi split (A of final gemm)
__device__ bf16  g_al[BB*NN*DM];      // attn output lo split
__device__ bf16  g_aqh[3*BB*NN*DM];   // q,k,v input hi splits (3 slabs)
__device__ bf16  g_aql[3*BB*NN*DM];   // q,k,v input lo splits
__device__ bf16  g_wh4[4*DM*DM];      // W^T hi splits: Wq,Wk,Wv,Wm slabs
__device__ bf16  g_wl4[4*DM*DM];
__device__ bf16  g_qhh[BB*NH*NN*DH], g_qhl[BB*NH*NN*DH];  // Q heads hi/lo
__device__ bf16  g_khh[BB*NH*NN*DH], g_khl[BB*NH*NN*DH];  // K heads hi/lo
__device__ bf16  g_vhh[BB*NH*NN*DH], g_vhl[BB*NH*NN*DH];  // V heads hi/lo
__device__ int   g_mask_kind;         // 0=int32, 1=float32, 2=byte

// ---- HMMA helpers (baseline PTX, not 'a'-gated) ----
__device__ __forceinline__ uint32_t smem_u32(const void* p) {
    uint32_t a;
    asm("{ .reg .u64 t; cvta.to.shared.u64 t, %1; cvt.u32.u64 %0, t; }"
        : "=r"(a) : "l"(p));
    return a;
}
__device__ __forceinline__ void mma16816(float* c, const uint32_t* a,
                                         const uint32_t* b) {
    asm volatile(
        "mma.sync.aligned.m16n8k16.row.col.f32.bf16.bf16.f32 "
        "{%0,%1,%2,%3}, {%4,%5,%6,%7}, {%8,%9}, {%0,%1,%2,%3};"
        : "+f"(c[0]), "+f"(c[1]), "+f"(c[2]), "+f"(c[3])
        : "r"(a[0]), "r"(a[1]), "r"(a[2]), "r"(a[3]), "r"(b[0]), "r"(b[1]));
}
__device__ __forceinline__ void ldmA(uint32_t* r, uint32_t addr) {
    asm volatile("ldmatrix.sync.aligned.m8n8.x4.shared.b16 {%0,%1,%2,%3}, [%4];"
        : "=r"(r[0]), "=r"(r[1]), "=r"(r[2]), "=r"(r[3]) : "r"(addr));
}
__device__ __forceinline__ void ldmB(uint32_t* r, uint32_t addr) {
    asm volatile("ldmatrix.sync.aligned.m8n8.x4.shared.b16 {%0,%1,%2,%3}, [%4];"
        : "=r"(r[0]), "=r"(r[1]), "=r"(r[2]), "=r"(r[3]) : "r"(addr));
}
// trans variant: [k][n]-stored data -> b-fragment (V tiles)
__device__ __forceinline__ void ldmVT(uint32_t* r, uint32_t addr) {
    asm volatile("ldmatrix.sync.aligned.m8n8.x4.trans.shared.b16 {%0,%1,%2,%3}, [%4];"
        : "=r"(r[0]), "=r"(r[1]), "=r"(r[2]), "=r"(r[3]) : "r"(addr));
}
// gemm smem: 64B rows, 4x16B chunks
__device__ __forceinline__ int swz(int row, int ch) {
    return row * 64 + ((ch ^ ((row >> 1) & 3)) << 4);
}
// attn smem: 128B rows (64 bf16), 8x16B chunks
__device__ __forceinline__ int swz128(int row, int ch) {
    return row * 128 + ((ch ^ (row & 7)) << 4);
}
// P smem: 512B rows (256 bf16), 32x16B chunks
__device__ __forceinline__ int swzP(int row, int ch) {
    return row * 512 + ((ch ^ (row & 7)) << 4);
}
// ---- cp.async (Ampere-baseline) ----
__device__ __forceinline__ void cpa16(uint32_t dst, const void* src) {
    asm volatile("cp.async.cg.shared.global [%0], [%1], 16;"
                 :: "r"(dst), "l"(src) : "memory");
}
__device__ __forceinline__ void cpa_commit() {
    asm volatile("cp.async.commit_group;" ::: "memory");
}
__device__ __forceinline__ void split2(float x, bf16& h, bf16& l) {
    h = __float2bfloat16(x);
    l = __float2bfloat16(x - __bfloat162float(h));
}

// ---------------------------------------------------------------------------
// Mask dtype sniffing (bool may arrive as u8/i32/f32).
// ---------------------------------------------------------------------------
__global__ void detect_mask_kind(const unsigned int* __restrict__ m) {
    __shared__ int oki, okf;
    if (threadIdx.x == 0) { oki = 1; okf = 1; }
    __syncthreads();
    for (int idx = threadIdx.x; idx < 2048; idx += 256) {
        unsigned int w = m[idx];
        if (w > 1u) oki = 0;
        if (w != 0u && w != 0x3F800000u) okf = 0;
    }
    __syncthreads();
    if (threadIdx.x == 0) g_mask_kind = oki ? 0 : (okf ? 1 : 2);
}

// ---------------------------------------------------------------------------
// Split q,k,v (3 x 4M fp32) -> bf16 hi/lo slabs. grid 12288 x 256, float4.
// ---------------------------------------------------------------------------
__global__ void split_qkv(const float* __restrict__ q,
                          const float* __restrict__ k,
                          const float* __restrict__ v,
                          bf16* __restrict__ hi, bf16* __restrict__ lo) {
    int gi = blockIdx.x * 256 + threadIdx.x;
    const int SLAB4 = BB * NN * DM / 4;
    int slab = gi / SLAB4;
    int r4 = gi - slab * SLAB4;
    const float* src = (slab == 0) ? q : (slab == 1) ? k : v;
    int i = r4 * 4;
    float4 x = *(const float4*)(src + i);
    bf16 h0, l0, h1, l1, h2, l2, h3, l3;
    split2(x.x, h0, l0); split2(x.y, h1, l1);
    split2(x.z, h2, l2); split2(x.w, h3, l3);
    size_t o = (size_t)slab * (BB * NN * DM) + i;
    *(__nv_bfloat162*)(hi + o)     = __nv_bfloat162(h0, h1);
    *(__nv_bfloat162*)(hi + o + 2) = __nv_bfloat162(h2, h3);
    *(__nv_bfloat162*)(lo + o)     = __nv_bfloat162(l0, l1);
    *(__nv_bfloat162*)(lo + o + 2) = __nv_bfloat162(l2, l3);
}

// ---------------------------------------------------------------------------
// Split + transpose all 4 weights [k][n] -> [n][k] hi/lo slabs. grid 4096x256.
// ---------------------------------------------------------------------------
__global__ void split_w4(const float* __restrict__ W0,
                         const float* __restrict__ W1,
                         const float* __restrict__ W2,
                         const float* __restrict__ W3,
                         bf16* __restrict__ hi, bf16* __restrict__ lo) {
    int gi = blockIdx.x * 256 + threadIdx.x;
    int w = gi >> 18, r = gi & 0x3FFFF;
    int k = r >> 9, n = r & 511;
    const float* W = (w == 0) ? W0 : (w == 1) ? W1 : (w == 2) ? W2 : W3;
    float x = W[r];
    bf16 h, l; split2(x, h, l);
    size_t o = (size_t)w * (DM * DM) + n * 512 + k;
    hi[o] = h;  lo[o] = l;
}

// ---------------------------------------------------------------------------
// HMMA GEMM body: cp.async 2-stage pipeline. CTA 128x128, 8 warps, BK=32.
// mode 0: fp32 row-major C.  mode 1: bf16 hi/lo head-split [B,H,N,DH].
// ---------------------------------------------------------------------------
__device__ __forceinline__ void issue_tile(
    uint32_t bs, int kn, int m0, int n0, int lr, int lr1, int lch,
    int so0, int so1,
    const bf16* __restrict__ Ah, const bf16* __restrict__ Al,
    const bf16* __restrict__ Bh, const bf16* __restrict__ Bl) {
    size_t ga0 = (size_t)(m0 + lr)  * 512 + kn + lch * 8;
    size_t ga1 = (size_t)(m0 + lr1) * 512 + kn + lch * 8;
    size_t gb0 = (size_t)(n0 + lr)  * 512 + kn + lch * 8;
    size_t gb1 = (size_t)(n0 + lr1) * 512 + kn + lch * 8;
    cpa16(bs +         so0, Ah + ga0);  cpa16(bs +         so1, Ah + ga1);
    cpa16(bs +  8192 + so0, Al + ga0);  cpa16(bs +  8192 + so1, Al + ga1);
    cpa16(bs + 16384 + so0, Bh + gb0);  cpa16(bs + 16384 + so1, Bh + gb1);
    cpa16(bs + 24576 + so0, Bl + gb0);  cpa16(bs + 24576 + so1, Bl + gb1);
    cpa_commit();
}

__device__ __forceinline__ void gemm_body(
    char* dsm, const bf16* __restrict__ Ah, const bf16* __restrict__ Al,
    const bf16* __restrict__ BhT, const bf16* __restrict__ BlT,
    const float* __restrict__ bias, float* __restrict__ C,
    bf16* __restrict__ Chi, bf16* __restrict__ Clo, int mode,
    int m0, int n0) {
    const uint32_t sb = smem_u32(dsm);
    const int tid = threadIdx.x, wid = tid >> 5, lane = tid & 31;
    const int wm = wid >> 2, wn = wid & 3;
    const int lr = tid >> 2, lch = tid & 3, lr1 = lr + 64;
    const int so0 = swz(lr, lch), so1 = swz(lr1, lch);

    float acc[4][4][4];
    #pragma unroll
    for (int i = 0; i < 4; i++)
        #pragma unroll
        for (int j = 0; j < 4; j++)
            #pragma unroll
            for (int t = 0; t < 4; t++) acc[i][j][t] = 0.f;

    issue_tile(sb, 0, m0, n0, lr, lr1, lch, so0, so1, Ah, Al, BhT, BlT);

    for (int c = 0; c < 16; c++) {
        if (c + 1 < 16) {
            issue_tile(sb + ((c + 1) & 1) * 32768, (c + 1) * 32,
                       m0, n0, lr, lr1, lch, so0, so1, Ah, Al, BhT, BlT);
            asm volatile("cp.async.wait_group %0;" :: "n"(1) : "memory");
        } else {
            asm volatile("cp.async.wait_group %0;" :: "n"(0) : "memory");
        }
        __syncthreads();

        const uint32_t bs = sb + (c & 1) * 32768;
        const uint32_t sbAh = bs, sbAl = bs + 8192;
        const uint32_t sbWh = bs + 16384, sbWl = bs + 24576;

        #pragma unroll
        for (int ks = 0; ks < 2; ks++) {
            const int arow = wm * 64 + (lane & 7) + ((lane >> 3) & 1) * 8;
            const int akch = ks * 2 + ((lane >> 4) & 1);
            const int nrow = wn * 32 + (lane & 7) + ((lane >> 4) & 1) * 8;
            const int nkch = ks * 2 + ((lane >> 3) & 1);

            uint32_t whf[2][4], wlf[2][4], af[4][4];
            #pragma unroll
            for (int g = 0; g < 2; g++) {
                ldmB(whf[g], sbWh + swz(nrow + g * 16, nkch));
                ldmB(wlf[g], sbWl + swz(nrow + g * 16, nkch));
            }
            #pragma unroll
            for (int mt = 0; mt < 4; mt++)
                ldmA(af[mt], sbAh + swz(arow + mt * 16, akch));
            #pragma unroll
            for (int mt = 0; mt < 4; mt++)
                #pragma unroll
                for (int nt = 0; nt < 4; nt++) {
                    mma16816(acc[mt][nt], af[mt], &whf[nt >> 1][(nt & 1) * 2]);
                    mma16816(acc[mt][nt], af[mt], &wlf[nt >> 1][(nt & 1) * 2]);
                }
            #pragma unroll
            for (int mt = 0; mt < 4; mt++)
                ldmA(af[mt], sbAl + swz(arow + mt * 16, akch));
            #pragma unroll
            for (int mt = 0; mt < 4; mt++)
                #pragma unroll
                for (int nt = 0; nt < 4; nt++)
                    mma16816(acc[mt][nt], af[mt], &whf[nt >> 1][(nt & 1) * 2]);
        }
        __syncthreads();
    }

    // ---- epilogue ----
    #pragma unroll
    for (int mt = 0; mt < 4; mt++) {
        int row = m0 + wm * 64 + mt * 16 + (lane >> 2);
        #pragma unroll
        for (int nt = 0; nt < 4; nt++) {
            int col = n0 + wn * 32 + nt * 8 + (lane & 3) * 2;
            float b0 = __ldg(&bias[col]), b1 = __ldg(&bias[col + 1]);
            float2 v0 = make_float2(acc[mt][nt][0] + b0, acc[mt][nt][1] + b1);
            float2 v1 = make_float2(acc[mt][nt][2] + b0, acc[mt][nt][3] + b1);
            if (mode == 1) {
                int h = col >> 6, d = col & 63;
                #pragma unroll
                for (int half = 0; half < 2; half++) {
                    float2 v = half ? v1 : v0;
                    int rr = row + half * 8;
                    int b = rr >> 8, n = rr & 255;
                    size_t base = (((size_t)b * NH + h) * NN + n) * DH + d;
                    bf16 h0, l0, h1, l1;
                    split2(v.x, h0, l0); split2(v.y, h1, l1);
                    *(__nv_bfloat162*)&Chi[base] = __nv_bfloat162(h0, h1);
                    *(__nv_bfloat162*)&Clo[base] = __nv_bfloat162(l0, l1);
                }
            } else {
                *(float2*)(C + (size_t)row * DM + col) = v0;
                *(float2*)(C + (size_t)(row + 8) * DM + col) = v1;
            }
        }
    }
}

// Persistent batched Q/K/V projection: 768 tiles over gridDim.x CTAs.
__global__ void __launch_bounds__(256, 2)
gemm_qkv(const bf16* __restrict__ Aqh, const bf16* __restrict__ Aql,
         const bf16* __restrict__ Wh4, const bf16* __restrict__ Wl4,
         const float* __restrict__ bq, const float* __restrict__ bk,
         const float* __restrict__ bv,
         bf16* __restrict__ Qhh, bf16* __restrict__ Qhl,
         bf16* __restrict__ Khh, bf16* __restrict__ Khl,
         bf16* __restrict__ Vhh, bf16* __restrict__ Vhl) {
    extern __shared__ char dsm[];
    for (int t = blockIdx.x; t < 768; t += gridDim.x) {
        int z = t >> 8, rem = t & 255;
        const size_t aoff = (size_t)z * (BB * NN * DM);
        const size_t woff = (size_t)z * (DM * DM);
        const float* bias = (z == 0) ? bq : (z == 1) ? bk : bv;
        bf16* Chi = (z == 0) ? Qhh : (z == 1) ? Khh : Vhh;
        bf16* Clo = (z == 0) ? Qhl : (z == 1) ? Khl : Vhl;
        gemm_body(dsm, Aqh + aoff, Aql + aoff, Wh4 + woff, Wl4 + woff,
                  bias, nullptr, Chi, Clo, 1, (rem >> 2) * 128, (rem & 3) * 128);
    }
}

// Output projection (mode 0, Wm = slab 3).
__global__ void __launch_bounds__(256, 2)
gemm_out(const bf16* __restrict__ Ah, const bf16* __restrict__ Al,
         const bf16* __restrict__ Wh4, const bf16* __restrict__ Wl4,
         const float* __restrict__ bias, float* __restrict__ C) {
    extern __shared__ char dsm[];
    gemm_body(dsm, Ah, Al, Wh4 + (size_t)3 * DM * DM, Wl4 + (size_t)3 * DM * DM,
              bias, C, nullptr, nullptr, 0, blockIdx.y * 128, blockIdx.x * 128);
}

// ---------------------------------------------------------------------------
// Geometric positional bias (unchanged).
// ---------------------------------------------------------------------------
__global__ void pos_kernel(const float* __restrict__ box,
                           const float* __restrict__ Wbox,
                           const float* __restrict__ bbox,
                           float* __restrict__ pos_out) {
    __shared__ float scx[NN], scy[NN], slw[NN], slh[NN];
    __shared__ float wb[65];
    const int b = blockIdx.y, i = blockIdx.x;
    const int j = threadIdx.x;

    {
        const float* bj = box + ((size_t)b * NN + j) * 4;
        float x0 = bj[0], y0 = bj[1], x1 = bj[2], y1 = bj[3];
        scx[j] = 0.5f * (x0 + x1);
        scy[j] = 0.5f * (y0 + y1);
        slw[j] = __logf(x1 - x0 + 1.0f);
        slh[j] = __logf(y1 - y0 + 1.0f);
    }
    if (j < 64) wb[j] = Wbox[j];
    if (j == 0) wb[64] = bbox[0];
    __syncthreads();

    const float* bi = box + ((size_t)b * NN + i) * 4;
    float xi0 = bi[0], yi0 = bi[1], xi1 = bi[2], yi1 = bi[3];
    float cxi = 0.5f * (xi0 + xi1), cyi = 0.5f * (yi0 + yi1);
    float wi = xi1 - xi0 + 1.0f, hi = yi1 - yi0 + 1.0f;
    float invw = 1.0f / wi, invh = 1.0f / hi;
    float lwi = __logf(wi), lhi = __logf(hi);

    float p0 = __logf(fmaxf(fabsf((cxi - scx[j]) * invw), 1e-3f));
    float p1 = __logf(fmaxf(fabsf((cyi - scy[j]) * invh), 1e-3f));
    float p2 = lwi - slw[j];
    float p3 = lhi - slh[j];

    const float dm[8] = {1.0f, 0.42169651f, 0.17782794f, 0.074989423f,
                         0.031622777f, 0.013335214f, 0.0056234132f, 0.0023713737f};
    float pc[4] = {100.f * p0, 100.f * p1, 100.f * p2, 100.f * p3};

    float s = wb[64];
    #pragma unroll
    for (int c = 0; c < 4; c++) {
        #pragma unroll
        for (int f = 0; f < 8; f++) {
            float m = pc[c] * dm[f];
            float sn, cs;
            __sincosf(m, &sn, &cs);
            s = fmaf(sn, wb[c * 8 + f], s);
            s = fmaf(cs, wb[32 + c * 8 + f], s);
        }
    }
    float ps = fmaxf(s, 0.f);

    size_t base = (size_t)b * NH * NN * NN + (size_t)i * NN + j;
    #pragma unroll
    for (int hh = 0; hh < NH; hh++)
        pos_out[base + (size_t)hh * NN * NN] = ps;
}

// ---------------------------------------------------------------------------
// HMMA attention per (b, h, 32-q tile). cp.async double-buffered K/V stages.
// smem: Qh 0..4K | Ql 4..8K | KV stage0 8..24K | KV stage1 24..40K |
//       S fp32 40960..74752 (32x264) [overlay Phi @40960, Plo @57344] |
//       mrow @74752. Total 75008.
// ---------------------------------------------------------------------------
#define AT_SQH 0
#define AT_SQL 4096
#define AT_KH(s) (8192 + (s) * 16384)
#define AT_KL(s) (16384 + (s) * 16384)
#define AT_S   40960
#define AT_PHI 40960
#define AT_PLO 57344
#define AT_MR  74752
#define AT_TOT 75008

__device__ __forceinline__ void issue_kv(char* sm8, int s,
                                         const bf16* __restrict__ Gh,
                                         const bf16* __restrict__ Gl,
                                         int kb, int tid) {
    const uint32_t sbase = smem_u32(sm8);
    #pragma unroll
    for (int t = 0; t < 2; t++) {
        int idx = t * 256 + tid;
        int row = idx >> 3, ch = idx & 7;
        const bf16* sh = Gh + (size_t)(kb * 64 + row) * 64 + ch * 8;
        const bf16* sl = Gl + (size_t)(kb * 64 + row) * 64 + ch * 8;
        cpa16(sbase + AT_KH(s) + swz128(row, ch), sh);
        cpa16(sbase + AT_KL(s) + swz128(row, ch), sl);
    }
    cpa_commit();
}

__global__ void __launch_bounds__(256, 2)
attn_tc(const void* __restrict__ maskp, const float* __restrict__ pos,
        bf16* __restrict__ Oh, bf16* __restrict__ Ol) {
    extern __shared__ char sm8[];
    const uint32_t sb = smem_u32(sm8);
    float* S = (float*)(sm8 + AT_S);
    unsigned char* mrow = (unsigned char*)(sm8 + AT_MR);

    const int blk = blockIdx.x;
    const int qt = blk & 7, h = (blk >> 3) & 7, b = blk >> 6;
    const int tid = threadIdx.x, wid = tid >> 5, lane = tid & 31;
    const int wm = wid >> 2, wn = wid & 3;          // 2 x 4 warp grid
    const int q0 = qt * 32;
    const int kind = g_mask_kind;

    const size_t hb = ((size_t)b * NH + h) * NN;
    const bf16* Qh = g_qhh + (hb + q0) * DH;
    const bf16* Ql = g_qhl + (hb + q0) * DH;
    const bf16* Kh = g_khh + hb * DH;
    const bf16* Kl = g_khl + hb * DH;
    const bf16* Vh = g_vhh + hb * DH;
    const bf16* Vl = g_vhl + hb * DH;

    // Prefetch K0 into stage 0 (group 0)
    issue_kv(sm8, 0, Kh, Kl, 0, tid);

    {
        int idx = b * NN + tid;
        bool mv;
        if (kind == 0)      mv = ((const int*)maskp)[idx] != 0;
        else if (kind == 1) mv = ((const float*)maskp)[idx] != 0.0f;
        else                mv = ((const unsigned char*)maskp)[idx] != 0;
        mrow[tid] = mv ? 1 : 0;
    }
    {
        int row = tid >> 3, ch = tid & 7;
        *(uint4*)(sm8 + AT_SQH + swz128(row, ch)) = *(const uint4*)(Qh + row * 64 + ch * 8);
        *(uint4*)(sm8 + AT_SQL + swz128(row, ch)) = *(const uint4*)(Ql + row * 64 + ch * 8);
    }
    const float* prow = pos + (size_t)b * (NH * NN * NN) + (size_t)q0 * NN;

    // ---- S = scale * Q K^T + pos, masked (HMMA) ----
    for (int kb = 0; kb < 4; kb++) {
        if (kb) __syncthreads();               // all done computing stage (kb+1)&1
        if (kb + 1 < 4) issue_kv(sm8, (kb + 1) & 1, Kh, Kl, kb + 1, tid);
        else            issue_kv(sm8, 0, Vh, Vl, 0, tid);   // V0 prefetch
        asm volatile("cp.async.wait_group %0;" :: "n"(1) : "memory");
        __syncthreads();

        const int st = kb & 1;
        float acc[2][4] = {{0.f,0.f,0.f,0.f},{0.f,0.f,0.f,0.f}};
        #pragma unroll
        for (int ks = 0; ks < 4; ks++) {
            const int arow = wm * 16 + (lane & 7) + ((lane >> 3) & 1) * 8;
            const int akch = ks * 2 + ((lane >> 4) & 1);
            const int nrow = wn * 16 + (lane & 7) + ((lane >> 4) & 1) * 8;
            const int nkch = ks * 2 + ((lane >> 3) & 1);
            uint32_t aH[4], aL[4], bH[4], bL[4];
            ldmA(aH, sb + AT_SQH + swz128(arow, akch));
            ldmA(aL, sb + AT_SQL + swz128(arow, akch));
            ldmB(bH, sb + AT_KH(st) + swz128(nrow, nkch));
            ldmB(bL, sb + AT_KL(st) + swz128(nrow, nkch));
            #pragma unroll
            for (int nt = 0; nt < 2; nt++) {
                mma16816(acc[nt], aH, bH + nt * 2);
                mma16816(acc[nt], aH, bL + nt * 2);
                mma16816(acc[nt], aL, bH + nt * 2);
            }
        }
        #pragma unroll
        for (int nt = 0; nt < 2; nt++) {
            int col = kb * 64 + wn * 16 + nt * 8 + (lane & 3) * 2;
            #pragma unroll
            for (int half = 0; half < 2; half++) {
                int r = wm * 16 + (lane >> 2) + half * 8;
                float a0 = acc[nt][half * 2 + 0], a1 = acc[nt][half * 2 + 1];
                float v0 = mrow[col]     ? -1e9f : fmaf(a0, 0.125f, prow[r * NN + col]);
                float v1 = mrow[col + 1] ? -1e9f : fmaf(a1, 0.125f, prow[r * NN + col + 1]);
                S[r * 264 + col]     = v0;
                S[r * 264 + col + 1] = v1;
            }
        }
    }
    __syncthreads();

    // ---- softmax: 8 lanes per row ----
    {
        int row = tid >> 3, sub = tid & 7;
        float* Sr = S + row * 264;
        float mx = -3.4e38f;
        #pragma unroll
        for (int t = 0; t < 32; t++) mx = fmaxf(mx, Sr[sub + t * 8]);
        #pragma unroll
        for (int o = 4; o > 0; o >>= 1)
            mx = fmaxf(mx, __shfl_xor_sync(0xffffffffu, mx, o));
        float ssum = 0.f;
        #pragma unroll
        for (int t = 0; t < 32; t++) {
            float e = __expf(Sr[sub + t * 8] - mx);
            Sr[sub + t * 8] = e;
            ssum += e;
        }
        #pragma unroll
        for (int o = 4; o > 0; o >>= 1)
            ssum += __shfl_xor_sync(0xffffffffu, ssum, o);
        float inv = 1.0f / ssum;
        #pragma unroll
        for (int t = 0; t < 32; t++) Sr[sub + t * 8] *= inv;
    }
    __syncthreads();

    // ---- convert P (fp32 S) -> bf16 hi/lo, overlaid on S region ----
    {
        int row = tid >> 3, cb = (tid & 7) * 4;
        float tmp[32];
        #pragma unroll
        for (int c4 = 0; c4 < 4; c4++)
            #pragma unroll
            for (int e = 0; e < 8; e++)
                tmp[c4 * 8 + e] = S[row * 264 + (cb + c4) * 8 + e];
        __syncthreads();
        #pragma unroll
        for (int c4 = 0; c4 < 4; c4++) {
            uint32_t hi4[4], lo4[4];
            #pragma unroll
            for (int p = 0; p < 4; p++) {
                float x0 = tmp[c4 * 8 + p * 2], x1 = tmp[c4 * 8 + p * 2 + 1];
                bf16 h0, l0, h1, l1;
                split2(x0, h0, l0); split2(x1, h1, l1);
                __nv_bfloat162 hp(h0, h1), lp(l0, l1);
                hi4[p] = *(uint32_t*)&hp;
                lo4[p] = *(uint32_t*)&lp;
            }
            *(uint4*)(sm8 + AT_PHI + swzP(row, cb + c4)) = make_uint4(hi4[0], hi4[1], hi4[2], hi4[3]);
            *(uint4*)(sm8 + AT_PLO + swzP(row, cb + c4)) = make_uint4(lo4[0], lo4[1], lo4[2], lo4[3]);
        }
    }

    // ---- O = P V (HMMA, V via ldmatrix.trans, double-buffered stages) ----
    float oacc[2][4] = {{0.f,0.f,0.f,0.f},{0.f,0.f,0.f,0.f}};
    for (int kb = 0; kb < 4; kb++) {
        __syncthreads();                        // P writes / prior stage reads done
        if (kb + 1 < 4) {
            issue_kv(sm8, (kb + 1) & 1, Vh, Vl, kb + 1, tid);
            asm volatile("cp.async.wait_group %0;" :: "n"(1) : "memory");
        } else {
            asm volatile("cp.async.wait_group %0;" :: "n"(0) : "memory");
        }
        __syncthreads();
        const int st = kb & 1;
        #pragma unroll
        for (int ks = 0; ks < 4; ks++) {
            const int arow = wm * 16 + (lane & 7) + ((lane >> 3) & 1) * 8;
            const int akch = kb * 8 + ks * 2 + ((lane >> 4) & 1);
            const int vrow = ks * 16 + (lane & 7) + ((lane >> 3) & 1) * 8;
            const int vch  = wn * 2 + ((lane >> 4) & 1);
            uint32_t pH[4], pL[4], vH[4], vL[4];
            ldmA(pH, sb + AT_PHI + swzP(arow, akch));
            ldmA(pL, sb + AT_PLO + swzP(arow, akch));
            ldmVT(vH, sb + AT_KH(st) + swz128(vrow, vch));
            ldmVT(vL, sb + AT_KL(st) + swz128(vrow, vch));
            #pragma unroll
            for (int nt = 0; nt < 2; nt++) {
                mma16816(oacc[nt], pH, vH + nt * 2);
                mma16816(oacc[nt], pH, vL + nt * 2);
                mma16816(oacc[nt], pL, vH + nt * 2);
            }
        }
    }

    // ---- store O directly as bf16 hi/lo (A of output projection) ----
    #pragma unroll
    for (int nt = 0; nt < 2; nt++) {
        int dcol = h * 64 + wn * 16 + nt * 8 + (lane & 3) * 2;
        #pragma unroll
        for (int half = 0; half < 2; half++) {
            int drow = q0 + wm * 16 + (lane >> 2) + half * 8;
            float x0 = oacc[nt][half * 2], x1 = oacc[nt][half * 2 + 1];
            bf16 h0, l0, h1, l1;
            split2(x0, h0, l0); split2(x1, h1, l1);
            size_t base = ((size_t)b * NN + drow) * DM + dcol;
            *(__nv_bfloat162*)&Oh[base] = __nv_bfloat162(h0, h1);
            *(__nv_bfloat162*)&Ol[base] = __nv_bfloat162(l0, l1);
        }
    }
}

// ---------------------------------------------------------------------------
extern "C" void kernel_launch(void* const* d_in, const int* in_sizes, int n_in,
                              void* d_out, int out_size) {
    const float *v, *k, *q, *box, *Wq, *bq, *Wk, *bk, *Wv, *bv, *Wm, *bm, *Wbox, *bbox;
    const void* mask;

    if (in_sizes[0] == BB * NN * DM) {
        v    = (const float*)d_in[0];
        k    = (const float*)d_in[1];
        q    = (const float*)d_in[2];
        box  = (const float*)d_in[3];
        mask = d_in[4];
        int wb = 5;
        for (int i = 5; i < n_in; i++) {
            if (in_sizes[i] == DM * DM) { wb = i; break; }
        }
        Wq   = (const float*)d_in[wb + 0];
        bq   = (const float*)d_in[wb + 1];
        Wk   = (const float*)d_in[wb + 2];
        bk   = (const float*)d_in[wb + 3];
        Wv   = (const float*)d_in[wb + 4];
        bv   = (const float*)d_in[wb + 5];
        Wm   = (const float*)d_in[wb + 6];
        bm   = (const float*)d_in[wb + 7];
        Wbox = (const float*)d_in[wb + 8];
        bbox = (const float*)d_in[wb + 9];
    } else {
        Wbox = (const float*)d_in[0];
        Wk   = (const float*)d_in[1];
        Wm   = (const float*)d_in[2];
        Wq   = (const float*)d_in[3];
        Wv   = (const float*)d_in[4];
        bbox = (const float*)d_in[5];
        bk   = (const float*)d_in[6];
        bm   = (const float*)d_in[7];
        bq   = (const float*)d_in[8];
        bv   = (const float*)d_in[9];
        box  = (const float*)d_in[10];
        int idx = 11;
        if (idx < n_in && in_sizes[idx] == 1) idx++;
        k    = (const float*)d_in[idx + 0];
        mask = d_in[idx + 1];
        q    = (const float*)d_in[idx + 2];
        v    = (const float*)d_in[idx + 3];
    }

    const size_t ATTED_ELEMS = (size_t)BB * NN * DM;
    const size_t POS_ELEMS   = (size_t)BB * NH * NN * NN;
    float* out = (float*)d_out;

    float *posA;
    bf16 *ahA, *alA, *aqhA, *aqlA, *wh4A, *wl4A;
    bf16 *qhhA, *qhlA, *khhA, *khlA, *vhhA, *vhlA;
    cudaGetSymbolAddress((void**)&posA, g_pos);
    cudaGetSymbolAddress((void**)&ahA,  g_ah);
    cudaGetSymbolAddress((void**)&alA,  g_al);
    cudaGetSymbolAddress((void**)&aqhA, g_aqh);
    cudaGetSymbolAddress((void**)&aqlA, g_aql);
    cudaGetSymbolAddress((void**)&wh4A, g_wh4);
    cudaGetSymbolAddress((void**)&wl4A, g_wl4);
    cudaGetSymbolAddress((void**)&qhhA, g_qhh);
    cudaGetSymbolAddress((void**)&qhlA, g_qhl);
    cudaGetSymbolAddress((void**)&khhA, g_khh);
    cudaGetSymbolAddress((void**)&khlA, g_khl);
    cudaGetSymbolAddress((void**)&vhhA, g_vhh);
    cudaGetSymbolAddress((void**)&vhlA, g_vhl);

    float* atted;
    float* pos_out;
    if ((size_t)out_size >= ATTED_ELEMS + POS_ELEMS) {
        atted   = out;
        pos_out = out + ATTED_ELEMS;
    } else if ((size_t)out_size == POS_ELEMS) {
        pos_out = out;
        atted   = posA;            // scratch sink (unused result)
    } else {
        atted   = out;
        pos_out = posA;
    }

    detect_mask_kind<<<1, 256>>>((const unsigned int*)mask);

    cudaFuncSetAttribute(gemm_qkv,
                         cudaFuncAttributeMaxDynamicSharedMemorySize, 65536);
    cudaFuncSetAttribute(gemm_out,
                         cudaFuncAttributeMaxDynamicSharedMemorySize, 65536);
    cudaFuncSetAttribute(attn_tc,
                         cudaFuncAttributeMaxDynamicSharedMemorySize, AT_TOT);

    // Upfront splits: all 4 weights, then q/k/v inputs
    split_w4<<<4096, 256>>>(Wq, Wk, Wv, Wm, wh4A, wl4A);
    split_qkv<<<3 * (BB * NN * DM) / (4 * 256), 256>>>(q, k, v, aqhA, aqlA);

    // Persistent batched Q/K/V projections (296 CTAs = 2/SM x 148)
    gemm_qkv<<<296, 256, 65536>>>(aqhA, aqlA, wh4A, wl4A,
                                  bq, bk, bv,
                                  qhhA, qhlA, khhA, khlA, vhhA, vhlA);

    pos_kernel<<<dim3(NN, BB), 256>>>(box, Wbox, bbox, pos_out);

    // Attention writes bf16 hi/lo A for the output projection directly
    attn_tc<<<BB * NH * 8, 256, AT_TOT>>>(mask, pos_out, ahA, alA);

    // Output projection
    gemm_out<<<dim3(4, 64), 256, 65536>>>(ahA, alA, wh4A, wl4A, bm, atted);
}

// round 13
// speedup vs baseline: 2.4190x; 1.0353x over previous
#include <cuda_runtime.h>
#include <cuda_bf16.h>
#include <cstdint>
#include <cstddef>

// Problem constants
#define BB   32
#define NN   256
#define DM   512
#define NH   8
#define DH   64

typedef unsigned long long ull;
typedef __nv_bfloat16 bf16;

// Scratch (allocation-free rule: __device__ globals)
__device__ float g_pos[BB*NH*NN*NN];  // pos_scores fallback when d_out lacks room
__device__ bf16  g_ah[BB*NN*DM];      // attn output hi split (A of final gemm)
__device__ bf16  g_al[BB*NN*DM];      // attn output lo split
__device__ bf16  g_aqh[3*BB*NN*DM];   // q,k,v input hi splits (3 slabs)
__device__ bf16  g_aql[3*BB*NN*DM];   // q,k,v input lo splits
__device__ bf16  g_wh4[4*DM*DM];      // W^T hi splits: Wq,Wk,Wv,Wm slabs
__device__ bf16  g_wl4[4*DM*DM];
__device__ bf16  g_qhh[BB*NH*NN*DH], g_qhl[BB*NH*NN*DH];  // Q heads hi/lo
__device__ bf16  g_khh[BB*NH*NN*DH], g_khl[BB*NH*NN*DH];  // K heads hi/lo
__device__ bf16  g_vhh[BB*NH*NN*DH], g_vhl[BB*NH*NN*DH];  // V heads hi/lo
__device__ int   g_mask_kind;         // 0=int32, 1=float32, 2=byte

// ---- HMMA helpers (baseline PTX, not 'a'-gated) ----
__device__ __forceinline__ uint32_t smem_u32(const void* p) {
    uint32_t a;
    asm("{ .reg .u64 t; cvta.to.shared.u64 t, %1; cvt.u32.u64 %0, t; }"
        : "=r"(a) : "l"(p));
    return a;
}
__device__ __forceinline__ void mma16816(float* c, const uint32_t* a,
                                         const uint32_t* b) {
    asm volatile(
        "mma.sync.aligned.m16n8k16.row.col.f32.bf16.bf16.f32 "
        "{%0,%1,%2,%3}, {%4,%5,%6,%7}, {%8,%9}, {%0,%1,%2,%3};"
        : "+f"(c[0]), "+f"(c[1]), "+f"(c[2]), "+f"(c[3])
        : "r"(a[0]), "r"(a[1]), "r"(a[2]), "r"(a[3]), "r"(b[0]), "r"(b[1]));
}
__device__ __forceinline__ void ldmA(uint32_t* r, uint32_t addr) {
    asm volatile("ldmatrix.sync.aligned.m8n8.x4.shared.b16 {%0,%1,%2,%3}, [%4];"
        : "=r"(r[0]), "=r"(r[1]), "=r"(r[2]), "=r"(r[3]) : "r"(addr));
}
__device__ __forceinline__ void ldmB(uint32_t* r, uint32_t addr) {
    asm volatile("ldmatrix.sync.aligned.m8n8.x4.shared.b16 {%0,%1,%2,%3}, [%4];"
        : "=r"(r[0]), "=r"(r[1]), "=r"(r[2]), "=r"(r[3]) : "r"(addr));
}
// trans variant: [k][n]-stored data -> b-fragment (V tiles)
__device__ __forceinline__ void ldmVT(uint32_t* r, uint32_t addr) {
    asm volatile("ldmatrix.sync.aligned.m8n8.x4.trans.shared.b16 {%0,%1,%2,%3}, [%4];"
        : "=r"(r[0]), "=r"(r[1]), "=r"(r[2]), "=r"(r[3]) : "r"(addr));
}
// gemm smem: 64B rows, 4x16B chunks
__device__ __forceinline__ int swz(int row, int ch) {
    return row * 64 + ((ch ^ ((row >> 1) & 3)) << 4);
}
// attn smem: 128B rows (64 bf16), 8x16B chunks
__device__ __forceinline__ int swz128(int row, int ch) {
    return row * 128 + ((ch ^ (row & 7)) << 4);
}
// P smem: 512B rows (256 bf16), 32x16B chunks
__device__ __forceinline__ int swzP(int row, int ch) {
    return row * 512 + ((ch ^ (row & 7)) << 4);
}
// ---- cp.async (Ampere-baseline) ----
__device__ __forceinline__ void cpa16(uint32_t dst, const void* src) {
    asm volatile("cp.async.cg.shared.global [%0], [%1], 16;"
                 :: "r"(dst), "l"(src) : "memory");
}
__device__ __forceinline__ void cpa_commit() {
    asm volatile("cp.async.commit_group;" ::: "memory");
}
__device__ __forceinline__ void split2(float x, bf16& h, bf16& l) {
    h = __float2bfloat16(x);
    l = __float2bfloat16(x - __bfloat162float(h));
}

// ---------------------------------------------------------------------------
// Mask dtype sniffing (bool may arrive as u8/i32/f32).
// ---------------------------------------------------------------------------
__global__ void detect_mask_kind(const unsigned int* __restrict__ m) {
    __shared__ int oki, okf;
    if (threadIdx.x == 0) { oki = 1; okf = 1; }
    __syncthreads();
    for (int idx = threadIdx.x; idx < 2048; idx += 256) {
        unsigned int w = m[idx];
        if (w > 1u) oki = 0;
        if (w != 0u && w != 0x3F800000u) okf = 0;
    }
    __syncthreads();
    if (threadIdx.x == 0) g_mask_kind = oki ? 0 : (okf ? 1 : 2);
}

// ---------------------------------------------------------------------------
// Split q,k,v (3 x 4M fp32) -> bf16 hi/lo slabs. float4 per thread.
// ---------------------------------------------------------------------------
__global__ void split_qkv(const float* __restrict__ q,
                          const float* __restrict__ k,
                          const float* __restrict__ v,
                          bf16* __restrict__ hi, bf16* __restrict__ lo) {
    int gi = blockIdx.x * 256 + threadIdx.x;
    const int SLAB4 = BB * NN * DM / 4;
    int slab = gi / SLAB4;
    int r4 = gi - slab * SLAB4;
    const float* src = (slab == 0) ? q : (slab == 1) ? k : v;
    int i = r4 * 4;
    float4 x = *(const float4*)(src + i);
    bf16 h0, l0, h1, l1, h2, l2, h3, l3;
    split2(x.x, h0, l0); split2(x.y, h1, l1);
    split2(x.z, h2, l2); split2(x.w, h3, l3);
    size_t o = (size_t)slab * (BB * NN * DM) + i;
    *(__nv_bfloat162*)(hi + o)     = __nv_bfloat162(h0, h1);
    *(__nv_bfloat162*)(hi + o + 2) = __nv_bfloat162(h2, h3);
    *(__nv_bfloat162*)(lo + o)     = __nv_bfloat162(l0, l1);
    *(__nv_bfloat162*)(lo + o + 2) = __nv_bfloat162(l2, l3);
}

// ---------------------------------------------------------------------------
// Split + transpose all 4 weights [k][n] -> [n][k] hi/lo slabs. grid 4096x256.
// ---------------------------------------------------------------------------
__global__ void split_w4(const float* __restrict__ W0,
                         const float* __restrict__ W1,
                         const float* __restrict__ W2,
                         const float* __restrict__ W3,
                         bf16* __restrict__ hi, bf16* __restrict__ lo) {
    int gi = blockIdx.x * 256 + threadIdx.x;
    int w = gi >> 18, r = gi & 0x3FFFF;
    int k = r >> 9, n = r & 511;
    const float* W = (w == 0) ? W0 : (w == 1) ? W1 : (w == 2) ? W2 : W3;
    float x = W[r];
    bf16 h, l; split2(x, h, l);
    size_t o = (size_t)w * (DM * DM) + n * 512 + k;
    hi[o] = h;  lo[o] = l;
}

// ---------------------------------------------------------------------------
// HMMA GEMM body: cp.async 2-stage pipeline. CTA 128x128, 8 warps, BK=32.
// mode 0: fp32 row-major C.  mode 1: bf16 hi/lo head-split [B,H,N,DH].
// ---------------------------------------------------------------------------
__device__ __forceinline__ void issue_tile(
    uint32_t bs, int kn, int m0, int n0, int lr, int lr1, int lch,
    int so0, int so1,
    const bf16* __restrict__ Ah, const bf16* __restrict__ Al,
    const bf16* __restrict__ Bh, const bf16* __restrict__ Bl) {
    size_t ga0 = (size_t)(m0 + lr)  * 512 + kn + lch * 8;
    size_t ga1 = (size_t)(m0 + lr1) * 512 + kn + lch * 8;
    size_t gb0 = (size_t)(n0 + lr)  * 512 + kn + lch * 8;
    size_t gb1 = (size_t)(n0 + lr1) * 512 + kn + lch * 8;
    cpa16(bs +         so0, Ah + ga0);  cpa16(bs +         so1, Ah + ga1);
    cpa16(bs +  8192 + so0, Al + ga0);  cpa16(bs +  8192 + so1, Al + ga1);
    cpa16(bs + 16384 + so0, Bh + gb0);  cpa16(bs + 16384 + so1, Bh + gb1);
    cpa16(bs + 24576 + so0, Bl + gb0);  cpa16(bs + 24576 + so1, Bl + gb1);
    cpa_commit();
}

__device__ __forceinline__ void gemm_body(
    char* dsm, const bf16* __restrict__ Ah, const bf16* __restrict__ Al,
    const bf16* __restrict__ BhT, const bf16* __restrict__ BlT,
    const float* __restrict__ bias, float* __restrict__ C,
    bf16* __restrict__ Chi, bf16* __restrict__ Clo, int mode,
    int m0, int n0) {
    const uint32_t sb = smem_u32(dsm);
    const int tid = threadIdx.x, wid = tid >> 5, lane = tid & 31;
    const int wm = wid >> 2, wn = wid & 3;
    const int lr = tid >> 2, lch = tid & 3, lr1 = lr + 64;
    const int so0 = swz(lr, lch), so1 = swz(lr1, lch);

    float acc[4][4][4];
    #pragma unroll
    for (int i = 0; i < 4; i++)
        #pragma unroll
        for (int j = 0; j < 4; j++)
            #pragma unroll
            for (int t = 0; t < 4; t++) acc[i][j][t] = 0.f;

    issue_tile(sb, 0, m0, n0, lr, lr1, lch, so0, so1, Ah, Al, BhT, BlT);

    for (int c = 0; c < 16; c++) {
        if (c + 1 < 16) {
            issue_tile(sb + ((c + 1) & 1) * 32768, (c + 1) * 32,
                       m0, n0, lr, lr1, lch, so0, so1, Ah, Al, BhT, BlT);
            asm volatile("cp.async.wait_group %0;" :: "n"(1) : "memory");
        } else {
            asm volatile("cp.async.wait_group %0;" :: "n"(0) : "memory");
        }
        __syncthreads();

        const uint32_t bs = sb + (c & 1) * 32768;
        const uint32_t sbAh = bs, sbAl = bs + 8192;
        const uint32_t sbWh = bs + 16384, sbWl = bs + 24576;

        #pragma unroll
        for (int ks = 0; ks < 2; ks++) {
            const int arow = wm * 64 + (lane & 7) + ((lane >> 3) & 1) * 8;
            const int akch = ks * 2 + ((lane >> 4) & 1);
            const int nrow = wn * 32 + (lane & 7) + ((lane >> 4) & 1) * 8;
            const int nkch = ks * 2 + ((lane >> 3) & 1);

            uint32_t whf[2][4], wlf[2][4], af[4][4];
            #pragma unroll
            for (int g = 0; g < 2; g++) {
                ldmB(whf[g], sbWh + swz(nrow + g * 16, nkch));
                ldmB(wlf[g], sbWl + swz(nrow + g * 16, nkch));
            }
            #pragma unroll
            for (int mt = 0; mt < 4; mt++)
                ldmA(af[mt], sbAh + swz(arow + mt * 16, akch));
            #pragma unroll
            for (int mt = 0; mt < 4; mt++)
                #pragma unroll
                for (int nt = 0; nt < 4; nt++) {
                    mma16816(acc[mt][nt], af[mt], &whf[nt >> 1][(nt & 1) * 2]);
                    mma16816(acc[mt][nt], af[mt], &wlf[nt >> 1][(nt & 1) * 2]);
                }
            #pragma unroll
            for (int mt = 0; mt < 4; mt++)
                ldmA(af[mt], sbAl + swz(arow + mt * 16, akch));
            #pragma unroll
            for (int mt = 0; mt < 4; mt++)
                #pragma unroll
                for (int nt = 0; nt < 4; nt++)
                    mma16816(acc[mt][nt], af[mt], &whf[nt >> 1][(nt & 1) * 2]);
        }
        __syncthreads();
    }

    // ---- epilogue ----
    #pragma unroll
    for (int mt = 0; mt < 4; mt++) {
        int row = m0 + wm * 64 + mt * 16 + (lane >> 2);
        #pragma unroll
        for (int nt = 0; nt < 4; nt++) {
            int col = n0 + wn * 32 + nt * 8 + (lane & 3) * 2;
            float b0 = __ldg(&bias[col]), b1 = __ldg(&bias[col + 1]);
            float2 v0 = make_float2(acc[mt][nt][0] + b0, acc[mt][nt][1] + b1);
            float2 v1 = make_float2(acc[mt][nt][2] + b0, acc[mt][nt][3] + b1);
            if (mode == 1) {
                int h = col >> 6, d = col & 63;
                #pragma unroll
                for (int half = 0; half < 2; half++) {
                    float2 v = half ? v1 : v0;
                    int rr = row + half * 8;
                    int b = rr >> 8, n = rr & 255;
                    size_t base = (((size_t)b * NH + h) * NN + n) * DH + d;
                    bf16 h0, l0, h1, l1;
                    split2(v.x, h0, l0); split2(v.y, h1, l1);
                    *(__nv_bfloat162*)&Chi[base] = __nv_bfloat162(h0, h1);
                    *(__nv_bfloat162*)&Clo[base] = __nv_bfloat162(l0, l1);
                }
            } else {
                *(float2*)(C + (size_t)row * DM + col) = v0;
                *(float2*)(C + (size_t)(row + 8) * DM + col) = v1;
            }
        }
    }
}

// ---------------------------------------------------------------------------
// Fused launch: blocks [0,768) = Q/K/V projection tiles (tensor-bound);
// blocks [768, 768+8192) = geometric positional bias (MUFU-bound).
// Heterogeneous blocks overlap complementary pipes on the same SMs.
// ---------------------------------------------------------------------------
__global__ void __launch_bounds__(256, 2)
gemm_qkv_pos(const bf16* __restrict__ Aqh, const bf16* __restrict__ Aql,
             const bf16* __restrict__ Wh4, const bf16* __restrict__ Wl4,
             const float* __restrict__ bq, const float* __restrict__ bk,
             const float* __restrict__ bv,
             bf16* __restrict__ Qhh, bf16* __restrict__ Qhl,
             bf16* __restrict__ Khh, bf16* __restrict__ Khl,
             bf16* __restrict__ Vhh, bf16* __restrict__ Vhl,
             const float* __restrict__ box, const float* __restrict__ Wbox,
             const float* __restrict__ bbox, float* __restrict__ pos_out) {
    extern __shared__ char dsm[];
    const int bid = blockIdx.x;
    if (bid < 768) {
        // ---- GEMM tile ----
        int z = bid >> 8, rem = bid & 255;
        const size_t aoff = (size_t)z * (BB * NN * DM);
        const size_t woff = (size_t)z * (DM * DM);
        const float* bias = (z == 0) ? bq : (z == 1) ? bk : bv;
        bf16* Chi = (z == 0) ? Qhh : (z == 1) ? Khh : Vhh;
        bf16* Clo = (z == 0) ? Qhl : (z == 1) ? Khl : Vhl;
        gemm_body(dsm, Aqh + aoff, Aql + aoff, Wh4 + woff, Wl4 + woff,
                  bias, nullptr, Chi, Clo, 1, (rem >> 2) * 128, (rem & 3) * 128);
        return;
    }
    // ---- pos block ----
    float* scx = (float*)dsm;
    float* scy = scx + NN;
    float* slw = scy + NN;
    float* slh = slw + NN;
    float* wb  = slh + NN;     // 65 floats
    const int pid = bid - 768;
    const int i = pid & 255, b = pid >> 8;
    const int j = threadIdx.x;

    {
        const float* bj = box + ((size_t)b * NN + j) * 4;
        float x0 = bj[0], y0 = bj[1], x1 = bj[2], y1 = bj[3];
        scx[j] = 0.5f * (x0 + x1);
        scy[j] = 0.5f * (y0 + y1);
        slw[j] = __logf(x1 - x0 + 1.0f);
        slh[j] = __logf(y1 - y0 + 1.0f);
    }
    if (j < 64) wb[j] = Wbox[j];
    if (j == 0) wb[64] = bbox[0];
    __syncthreads();

    const float* bi = box + ((size_t)b * NN + i) * 4;
    float xi0 = bi[0], yi0 = bi[1], xi1 = bi[2], yi1 = bi[3];
    float cxi = 0.5f * (xi0 + xi1), cyi = 0.5f * (yi0 + yi1);
    float wi = xi1 - xi0 + 1.0f, hi = yi1 - yi0 + 1.0f;
    float invw = 1.0f / wi, invh = 1.0f / hi;
    float lwi = __logf(wi), lhi = __logf(hi);

    float p0 = __logf(fmaxf(fabsf((cxi - scx[j]) * invw), 1e-3f));
    float p1 = __logf(fmaxf(fabsf((cyi - scy[j]) * invh), 1e-3f));
    float p2 = lwi - slw[j];
    float p3 = lhi - slh[j];

    const float dmv[8] = {1.0f, 0.42169651f, 0.17782794f, 0.074989423f,
                          0.031622777f, 0.013335214f, 0.0056234132f, 0.0023713737f};
    float pc[4] = {100.f * p0, 100.f * p1, 100.f * p2, 100.f * p3};

    float s = wb[64];
    #pragma unroll
    for (int c = 0; c < 4; c++) {
        #pragma unroll
        for (int f = 0; f < 8; f++) {
            float m = pc[c] * dmv[f];
            float sn, cs;
            __sincosf(m, &sn, &cs);
            s = fmaf(sn, wb[c * 8 + f], s);
            s = fmaf(cs, wb[32 + c * 8 + f], s);
        }
    }
    float ps = fmaxf(s, 0.f);

    size_t base = (size_t)b * NH * NN * NN + (size_t)i * NN + j;
    #pragma unroll
    for (int hh = 0; hh < NH; hh++)
        pos_out[base + (size_t)hh * NN * NN] = ps;
}

// Output projection (mode 0, Wm = slab 3).
__global__ void __launch_bounds__(256, 2)
gemm_out(const bf16* __restrict__ Ah, const bf16* __restrict__ Al,
         const bf16* __restrict__ Wh4, const bf16* __restrict__ Wl4,
         const float* __restrict__ bias, float* __restrict__ C) {
    extern __shared__ char dsm[];
    gemm_body(dsm, Ah, Al, Wh4 + (size_t)3 * DM * DM, Wl4 + (size_t)3 * DM * DM,
              bias, C, nullptr, nullptr, 0, blockIdx.y * 128, blockIdx.x * 128);
}

// ---------------------------------------------------------------------------
// HMMA attention per (b, h, 32-q tile). cp.async double-buffered K/V stages.
// ---------------------------------------------------------------------------
#define AT_SQH 0
#define AT_SQL 4096
#define AT_KH(s) (8192 + (s) * 16384)
#define AT_KL(s) (16384 + (s) * 16384)
#define AT_S   40960
#define AT_PHI 40960
#define AT_PLO 57344
#define AT_MR  74752
#define AT_TOT 75008

__device__ __forceinline__ void issue_kv(char* sm8, int s,
                                         const bf16* __restrict__ Gh,
                                         const bf16* __restrict__ Gl,
                                         int kb, int tid) {
    const uint32_t sbase = smem_u32(sm8);
    #pragma unroll
    for (int t = 0; t < 2; t++) {
        int idx = t * 256 + tid;
        int row = idx >> 3, ch = idx & 7;
        const bf16* sh = Gh + (size_t)(kb * 64 + row) * 64 + ch * 8;
        const bf16* sl = Gl + (size_t)(kb * 64 + row) * 64 + ch * 8;
        cpa16(sbase + AT_KH(s) + swz128(row, ch), sh);
        cpa16(sbase + AT_KL(s) + swz128(row, ch), sl);
    }
    cpa_commit();
}

__global__ void __launch_bounds__(256, 2)
attn_tc(const void* __restrict__ maskp, const float* __restrict__ pos,
        bf16* __restrict__ Oh, bf16* __restrict__ Ol) {
    extern __shared__ char sm8[];
    const uint32_t sb = smem_u32(sm8);
    float* S = (float*)(sm8 + AT_S);
    unsigned char* mrow = (unsigned char*)(sm8 + AT_MR);

    const int blk = blockIdx.x;
    const int qt = blk & 7, h = (blk >> 3) & 7, b = blk >> 6;
    const int tid = threadIdx.x, wid = tid >> 5, lane = tid & 31;
    const int wm = wid >> 2, wn = wid & 3;          // 2 x 4 warp grid
    const int q0 = qt * 32;
    const int kind = g_mask_kind;

    const size_t hb = ((size_t)b * NH + h) * NN;
    const bf16* Qh = g_qhh + (hb + q0) * DH;
    const bf16* Ql = g_qhl + (hb + q0) * DH;
    const bf16* Kh = g_khh + hb * DH;
    const bf16* Kl = g_khl + hb * DH;
    const bf16* Vh = g_vhh + hb * DH;
    const bf16* Vl = g_vhl + hb * DH;

    // Prefetch K0 into stage 0 (group 0)
    issue_kv(sm8, 0, Kh, Kl, 0, tid);

    {
        int idx = b * NN + tid;
        bool mv;
        if (kind == 0)      mv = ((const int*)maskp)[idx] != 0;
        else if (kind == 1) mv = ((const float*)maskp)[idx] != 0.0f;
        else                mv = ((const unsigned char*)maskp)[idx] != 0;
        mrow[tid] = mv ? 1 : 0;
    }
    {
        int row = tid >> 3, ch = tid & 7;
        *(uint4*)(sm8 + AT_SQH + swz128(row, ch)) = *(const uint4*)(Qh + row * 64 + ch * 8);
        *(uint4*)(sm8 + AT_SQL + swz128(row, ch)) = *(const uint4*)(Ql + row * 64 + ch * 8);
    }
    const float* prow = pos + (size_t)b * (NH * NN * NN) + (size_t)q0 * NN;

    // ---- S = scale * Q K^T + pos, masked (HMMA) ----
    for (int kb = 0; kb < 4; kb++) {
        if (kb) __syncthreads();               // all done computing stage (kb+1)&1
        if (kb + 1 < 4) issue_kv(sm8, (kb + 1) & 1, Kh, Kl, kb + 1, tid);
        else            issue_kv(sm8, 0, Vh, Vl, 0, tid);   // V0 prefetch
        asm volatile("cp.async.wait_group %0;" :: "n"(1) : "memory");
        __syncthreads();

        const int st = kb & 1;
        float acc[2][4] = {{0.f,0.f,0.f,0.f},{0.f,0.f,0.f,0.f}};
        #pragma unroll
        for (int ks = 0; ks < 4; ks++) {
            const int arow = wm * 16 + (lane & 7) + ((lane >> 3) & 1) * 8;
            const int akch = ks * 2 + ((lane >> 4) & 1);
            const int nrow = wn * 16 + (lane & 7) + ((lane >> 4) & 1) * 8;
            const int nkch = ks * 2 + ((lane >> 3) & 1);
            uint32_t aH[4], aL[4], bH[4], bL[4];
            ldmA(aH, sb + AT_SQH + swz128(arow, akch));
            ldmA(aL, sb + AT_SQL + swz128(arow, akch));
            ldmB(bH, sb + AT_KH(st) + swz128(nrow, nkch));
            ldmB(bL, sb + AT_KL(st) + swz128(nrow, nkch));
            #pragma unroll
            for (int nt = 0; nt < 2; nt++) {
                mma16816(acc[nt], aH, bH + nt * 2);
                mma16816(acc[nt], aH, bL + nt * 2);
                mma16816(acc[nt], aL, bH + nt * 2);
            }
        }
        #pragma unroll
        for (int nt = 0; nt < 2; nt++) {
            int col = kb * 64 + wn * 16 + nt * 8 + (lane & 3) * 2;
            #pragma unroll
            for (int half = 0; half < 2; half++) {
                int r = wm * 16 + (lane >> 2) + half * 8;
                float a0 = acc[nt][half * 2 + 0], a1 = acc[nt][half * 2 + 1];
                float v0 = mrow[col]     ? -1e9f : fmaf(a0, 0.125f, prow[r * NN + col]);
                float v1 = mrow[col + 1] ? -1e9f : fmaf(a1, 0.125f, prow[r * NN + col + 1]);
                S[r * 264 + col]     = v0;
                S[r * 264 + col + 1] = v1;
            }
        }
    }
    __syncthreads();

    // ---- softmax: 8 lanes per row ----
    {
        int row = tid >> 3, sub = tid & 7;
        float* Sr = S + row * 264;
        float mx = -3.4e38f;
        #pragma unroll
        for (int t = 0; t < 32; t++) mx = fmaxf(mx, Sr[sub + t * 8]);
        #pragma unroll
        for (int o = 4; o > 0; o >>= 1)
            mx = fmaxf(mx, __shfl_xor_sync(0xffffffffu, mx, o));
        float ssum = 0.f;
        #pragma unroll
        for (int t = 0; t < 32; t++) {
            float e = __expf(Sr[sub + t * 8] - mx);
            Sr[sub + t * 8] = e;
            ssum += e;
        }
        #pragma unroll
        for (int o = 4; o > 0; o >>= 1)
            ssum += __shfl_xor_sync(0xffffffffu, ssum, o);
        float inv = 1.0f / ssum;
        #pragma unroll
        for (int t = 0; t < 32; t++) Sr[sub + t * 8] *= inv;
    }
    __syncthreads();

    // ---- convert P (fp32 S) -> bf16 hi/lo, overlaid on S region ----
    {
        int row = tid >> 3, cb = (tid & 7) * 4;
        float tmp[32];
        #pragma unroll
        for (int c4 = 0; c4 < 4; c4++)
            #pragma unroll
            for (int e = 0; e < 8; e++)
                tmp[c4 * 8 + e] = S[row * 264 + (cb + c4) * 8 + e];
        __syncthreads();
        #pragma unroll
        for (int c4 = 0; c4 < 4; c4++) {
            uint32_t hi4[4], lo4[4];
            #pragma unroll
            for (int p = 0; p < 4; p++) {
                float x0 = tmp[c4 * 8 + p * 2], x1 = tmp[c4 * 8 + p * 2 + 1];
                bf16 h0, l0, h1, l1;
                split2(x0, h0, l0); split2(x1, h1, l1);
                __nv_bfloat162 hp(h0, h1), lp(l0, l1);
                hi4[p] = *(uint32_t*)&hp;
                lo4[p] = *(uint32_t*)&lp;
            }
            *(uint4*)(sm8 + AT_PHI + swzP(row, cb + c4)) = make_uint4(hi4[0], hi4[1], hi4[2], hi4[3]);
            *(uint4*)(sm8 + AT_PLO + swzP(row, cb + c4)) = make_uint4(lo4[0], lo4[1], lo4[2], lo4[3]);
        }
    }

    // ---- O = P V (HMMA, V via ldmatrix.trans, double-buffered stages) ----
    float oacc[2][4] = {{0.f,0.f,0.f,0.f},{0.f,0.f,0.f,0.f}};
    for (int kb = 0; kb < 4; kb++) {
        __syncthreads();                        // P writes / prior stage reads done
        if (kb + 1 < 4) {
            issue_kv(sm8, (kb + 1) & 1, Vh, Vl, kb + 1, tid);
            asm volatile("cp.async.wait_group %0;" :: "n"(1) : "memory");
        } else {
            asm volatile("cp.async.wait_group %0;" :: "n"(0) : "memory");
        }
        __syncthreads();
        const int st = kb & 1;
        #pragma unroll
        for (int ks = 0; ks < 4; ks++) {
            const int arow = wm * 16 + (lane & 7) + ((lane >> 3) & 1) * 8;
            const int akch = kb * 8 + ks * 2 + ((lane >> 4) & 1);
            const int vrow = ks * 16 + (lane & 7) + ((lane >> 3) & 1) * 8;
            const int vch  = wn * 2 + ((lane >> 4) & 1);
            uint32_t pH[4], pL[4], vH[4], vL[4];
            ldmA(pH, sb + AT_PHI + swzP(arow, akch));
            ldmA(pL, sb + AT_PLO + swzP(arow, akch));
            ldmVT(vH, sb + AT_KH(st) + swz128(vrow, vch));
            ldmVT(vL, sb + AT_KL(st) + swz128(vrow, vch));
            #pragma unroll
            for (int nt = 0; nt < 2; nt++) {
                mma16816(oacc[nt], pH, vH + nt * 2);
                mma16816(oacc[nt], pH, vL + nt * 2);
                mma16816(oacc[nt], pL, vH + nt * 2);
            }
        }
    }

    // ---- store O directly as bf16 hi/lo (A of output projection) ----
    #pragma unroll
    for (int nt = 0; nt < 2; nt++) {
        int dcol = h * 64 + wn * 16 + nt * 8 + (lane & 3) * 2;
        #pragma unroll
        for (int half = 0; half < 2; half++) {
            int drow = q0 + wm * 16 + (lane >> 2) + half * 8;
            float x0 = oacc[nt][half * 2], x1 = oacc[nt][half * 2 + 1];
            bf16 h0, l0, h1, l1;
            split2(x0, h0, l0); split2(x1, h1, l1);
            size_t base = ((size_t)b * NN + drow) * DM + dcol;
            *(__nv_bfloat162*)&Oh[base] = __nv_bfloat162(h0, h1);
            *(__nv_bfloat162*)&Ol[base] = __nv_bfloat162(l0, l1);
        }
    }
}

// ---------------------------------------------------------------------------
extern "C" void kernel_launch(void* const* d_in, const int* in_sizes, int n_in,
                              void* d_out, int out_size) {
    const float *v, *k, *q, *box, *Wq, *bq, *Wk, *bk, *Wv, *bv, *Wm, *bm, *Wbox, *bbox;
    const void* mask;

    if (in_sizes[0] == BB * NN * DM) {
        v    = (const float*)d_in[0];
        k    = (const float*)d_in[1];
        q    = (const float*)d_in[2];
        box  = (const float*)d_in[3];
        mask = d_in[4];
        int wb = 5;
        for (int i = 5; i < n_in; i++) {
            if (in_sizes[i] == DM * DM) { wb = i; break; }
        }
        Wq   = (const float*)d_in[wb + 0];
        bq   = (const float*)d_in[wb + 1];
        Wk   = (const float*)d_in[wb + 2];
        bk   = (const float*)d_in[wb + 3];
        Wv   = (const float*)d_in[wb + 4];
        bv   = (const float*)d_in[wb + 5];
        Wm   = (const float*)d_in[wb + 6];
        bm   = (const float*)d_in[wb + 7];
        Wbox = (const float*)d_in[wb + 8];
        bbox = (const float*)d_in[wb + 9];
    } else {
        Wbox = (const float*)d_in[0];
        Wk   = (const float*)d_in[1];
        Wm   = (const float*)d_in[2];
        Wq   = (const float*)d_in[3];
        Wv   = (const float*)d_in[4];
        bbox = (const float*)d_in[5];
        bk   = (const float*)d_in[6];
        bm   = (const float*)d_in[7];
        bq   = (const float*)d_in[8];
        bv   = (const float*)d_in[9];
        box  = (const float*)d_in[10];
        int idx = 11;
        if (idx < n_in && in_sizes[idx] == 1) idx++;
        k    = (const float*)d_in[idx + 0];
        mask = d_in[idx + 1];
        q    = (const float*)d_in[idx + 2];
        v    = (const float*)d_in[idx + 3];
    }

    const size_t ATTED_ELEMS = (size_t)BB * NN * DM;
    const size_t POS_ELEMS   = (size_t)BB * NH * NN * NN;
    float* out = (float*)d_out;

    float *posA;
    bf16 *ahA, *alA, *aqhA, *aqlA, *wh4A, *wl4A;
    bf16 *qhhA, *qhlA, *khhA, *khlA, *vhhA, *vhlA;
    cudaGetSymbolAddress((void**)&posA, g_pos);
    cudaGetSymbolAddress((void**)&ahA,  g_ah);
    cudaGetSymbolAddress((void**)&alA,  g_al);
    cudaGetSymbolAddress((void**)&aqhA, g_aqh);
    cudaGetSymbolAddress((void**)&aqlA, g_aql);
    cudaGetSymbolAddress((void**)&wh4A, g_wh4);
    cudaGetSymbolAddress((void**)&wl4A, g_wl4);
    cudaGetSymbolAddress((void**)&qhhA, g_qhh);
    cudaGetSymbolAddress((void**)&qhlA, g_qhl);
    cudaGetSymbolAddress((void**)&khhA, g_khh);
    cudaGetSymbolAddress((void**)&khlA, g_khl);
    cudaGetSymbolAddress((void**)&vhhA, g_vhh);
    cudaGetSymbolAddress((void**)&vhlA, g_vhl);

    float* atted;
    float* pos_out;
    if ((size_t)out_size >= ATTED_ELEMS + POS_ELEMS) {
        atted   = out;
        pos_out = out + ATTED_ELEMS;
    } else if ((size_t)out_size == POS_ELEMS) {
        pos_out = out;
        atted   = posA;            // scratch sink (unused result)
    } else {
        atted   = out;
        pos_out = posA;
    }

    detect_mask_kind<<<1, 256>>>((const unsigned int*)mask);

    cudaFuncSetAttribute(gemm_qkv_pos,
                         cudaFuncAttributeMaxDynamicSharedMemorySize, 65536);
    cudaFuncSetAttribute(gemm_out,
                         cudaFuncAttributeMaxDynamicSharedMemorySize, 65536);
    cudaFuncSetAttribute(attn_tc,
                         cudaFuncAttributeMaxDynamicSharedMemorySize, AT_TOT);

    // Upfront splits: all 4 weights, then q/k/v inputs
    split_w4<<<4096, 256>>>(Wq, Wk, Wv, Wm, wh4A, wl4A);
    split_qkv<<<3 * (BB * NN * DM) / (4 * 256), 256>>>(q, k, v, aqhA, aqlA);

    // Fused: 768 GEMM tile blocks + 8192 pos blocks in one launch
    gemm_qkv_pos<<<768 + BB * NN, 256, 65536>>>(
        aqhA, aqlA, wh4A, wl4A, bq, bk, bv,
        qhhA, qhlA, khhA, khlA, vhhA, vhlA,
        box, Wbox, bbox, pos_out);

    // Attention writes bf16 hi/lo A for the output projection directly
    attn_tc<<<BB * NH * 8, 256, AT_TOT>>>(mask, pos_out, ahA, alA);

    // Output projection
    gemm_out<<<dim3(4, 64), 256, 65536>>>(ahA, alA, wh4A, wl4A, bm, atted);
}